// round 2
// baseline (speedup 1.0000x reference)
#include <cuda_runtime.h>
#include <math.h>
#include <stdint.h>

// Problem dims
#define BB   32
#define LL   1024
#define VV   64
#define PLn  16
#define PHn  64
#define PFn  32
#define DD   128
#define HH   256
#define KK   1024
#define NVQ  (BB*VV*PFn)   // 65536 vq rows
#define NROW (BB*VV*DD)    // 262144 mlp rows

// ---------------- scratch (device globals; no allocation allowed) ----------
__device__ float g_mean[BB*VV];
__device__ float g_std[BB*VV];
__device__ float g_A[(size_t)NROW*PHn];     // MLP input, [row=(b,v,d)][p]   64MB
__device__ float g_Zp[(size_t)NVQ*DD];      // z_p  [n=(b,v,f)][d]           32MB
__device__ float g_Zcode[(size_t)NVQ*DD];   // z_code                        32MB
__device__ float g_c2[KK];

// packed fp32x2 FMA (FFMA2) — 2x fp32 throughput on sm_103a
__device__ __forceinline__ float2 ffma2(float2 a, float2 b, float2 c) {
    float2 r;
    asm("fma.rn.f32x2 %0, %1, %2, %3;"
        : "=l"(*reinterpret_cast<unsigned long long*>(&r))
        : "l"(*reinterpret_cast<unsigned long long*>(&a)),
          "l"(*reinterpret_cast<unsigned long long*>(&b)),
          "l"(*reinterpret_cast<unsigned long long*>(&c)));
    return r;
}

// ---------------- K1: RevIN stats per (b,v) --------------------------------
__global__ void k_revin(const float* __restrict__ x) {
    int b = blockIdx.x;
    int v = threadIdx.x;      // 64
    int ty = threadIdx.y;     // 8
    __shared__ float ssum[8][64];
    __shared__ float ssq[8][64];
    float s = 0.f, q = 0.f;
    const float* xp = x + (size_t)b*LL*VV + v;
    for (int l = ty; l < LL; l += 8) {
        float val = xp[(size_t)l*VV];
        s += val; q += val*val;
    }
    ssum[ty][v] = s; ssq[ty][v] = q;
    __syncthreads();
    if (ty == 0) {
        for (int j = 1; j < 8; j++) { s += ssum[j][v]; q += ssq[j][v]; }
        float mean = s * (1.0f/LL);
        float var  = q * (1.0f/LL) - mean*mean;
        g_mean[b*VV + v] = mean;
        g_std[b*VV + v]  = sqrtf(var + 1e-5f);
    }
}

// ---------------- K1b: centroid squared norms ------------------------------
__global__ void k_c2(const float* __restrict__ cent) {
    int w = threadIdx.x >> 5, l = threadIdx.x & 31;
    int k = blockIdx.x * 8 + w;
    const float* cp = cent + (size_t)k*DD;
    float s = 0.f;
    #pragma unroll
    for (int q = 0; q < 4; q++) { float c = cp[l + 32*q]; s += c*c; }
    #pragma unroll
    for (int o = 16; o; o >>= 1) s += __shfl_xor_sync(0xffffffffu, s, o);
    if (l == 0) g_c2[k] = s;
}

// ---------------- K2: encode (16->128) + LN + transpose to [bv,d,p] --------
__global__ void __launch_bounds__(256) k_encode(
    const float* __restrict__ x, const float* __restrict__ ew,
    const float* __restrict__ eb, const float* __restrict__ lnw,
    const float* __restrict__ lnb) {
    __shared__ float xv[1024];
    __shared__ float ws[16*128];
    __shared__ float zt[64*128];
    int bv = blockIdx.x; int t = threadIdx.x;
    int b = bv >> 6, v = bv & 63;
    float mean = g_mean[bv], rstd = 1.0f / g_std[bv];
    const float* xp = x + (size_t)b*LL*VV + v;
    for (int i = t; i < 1024; i += 256) xv[i] = (xp[(size_t)i*VV] - mean) * rstd;
    for (int i = t; i < 2048; i += 256) ws[i] = ew[i];
    __syncthreads();
    for (int idx = t; idx < 8192; idx += 256) {
        int p = idx >> 7, d = idx & 127;
        float s = eb[d];
        const float* xq = &xv[p*16];
        #pragma unroll
        for (int i = 0; i < 16; i++) s += xq[i] * ws[i*128 + d];
        zt[idx] = s;
    }
    __syncthreads();
    int w = t >> 5, l = t & 31;
    #pragma unroll
    for (int j = 0; j < 8; j++) {
        int p = w*8 + j;
        float z[4]; float s = 0.f, q = 0.f;
        #pragma unroll
        for (int qq = 0; qq < 4; qq++) {
            z[qq] = zt[p*128 + l + 32*qq];
            s += z[qq]; q += z[qq]*z[qq];
        }
        #pragma unroll
        for (int o = 16; o; o >>= 1) {
            s += __shfl_xor_sync(0xffffffffu, s, o);
            q += __shfl_xor_sync(0xffffffffu, q, o);
        }
        float mu = s * (1.0f/128.0f);
        float rs = rsqrtf(q*(1.0f/128.0f) - mu*mu + 1e-5f);
        #pragma unroll
        for (int qq = 0; qq < 4; qq++) {
            int d = l + 32*qq;
            g_A[((size_t)bv*128 + d)*64 + p] = (z[qq]-mu)*rs*lnw[d] + lnb[d];
        }
    }
}

// ---------------- K3: fused 3-layer MLP (the FLOP king) --------------------
// rows: 64 per block; fc1 64->256 relu; fcm 256->512 relu (chunked by 128);
// fc2 512->32 accumulated across chunks. f32x2 packed FMA throughout.
__global__ void __launch_bounds__(256) k_mlp(
    const float* __restrict__ w1, const float* __restrict__ b1,
    const float* __restrict__ w2, const float* __restrict__ b2,
    const float* __restrict__ w3, const float* __restrict__ b3) {
    extern __shared__ float sm[];
    float* As = sm;               // [64 k][72]        4608
    float* Ws = As + 64*72;       // tile buffer       4096
    float* H1 = Ws + 4096;        // [256 n][68 m]     17408
    float* H2 = H1 + 256*68;      // [128 n][68 m]     8704
    int t = threadIdx.x;
    int row0 = blockIdx.x * 64;

    for (int i = t; i < 64*64; i += 256) {
        int m = i >> 6, k = i & 63;
        As[k*72 + m] = g_A[(size_t)(row0+m)*64 + k];
    }
    __syncthreads();

    // ---- stage 1: H1 = relu(A @ W1 + b1), store transposed [n][m] ----
    {
        int tx = t & 31, ty = t >> 5;
        int cn = tx*8, rm = ty*8;
        float2 acc[8][4];
        #pragma unroll
        for (int i = 0; i < 8; i++)
            #pragma unroll
            for (int j = 0; j < 4; j++) acc[i][j] = make_float2(0.f,0.f);
        for (int kt = 0; kt < 4; kt++) {
            for (int i = t; i < 4096; i += 256) Ws[i] = w1[kt*4096 + i];
            __syncthreads();
            #pragma unroll 4
            for (int k = 0; k < 16; k++) {
                float4 a0 = *(const float4*)&As[(kt*16+k)*72 + rm];
                float4 a1 = *(const float4*)&As[(kt*16+k)*72 + rm + 4];
                float4 wv0 = *(const float4*)&Ws[k*256 + cn];
                float4 wv1 = *(const float4*)&Ws[k*256 + cn + 4];
                float a[8] = {a0.x,a0.y,a0.z,a0.w,a1.x,a1.y,a1.z,a1.w};
                float2 wf[4] = {make_float2(wv0.x,wv0.y), make_float2(wv0.z,wv0.w),
                                make_float2(wv1.x,wv1.y), make_float2(wv1.z,wv1.w)};
                #pragma unroll
                for (int i = 0; i < 8; i++) {
                    float2 ab = make_float2(a[i], a[i]);
                    #pragma unroll
                    for (int j = 0; j < 4; j++) acc[i][j] = ffma2(ab, wf[j], acc[i][j]);
                }
            }
            __syncthreads();
        }
        #pragma unroll
        for (int jj = 0; jj < 8; jj++) {
            int n = cn + jj;
            float bia = b1[n];
            int j = jj >> 1, comp = jj & 1;
            float vals[8];
            #pragma unroll
            for (int i = 0; i < 8; i++) {
                float vv = (comp ? acc[i][j].y : acc[i][j].x) + bia;
                vals[i] = fmaxf(vv, 0.f);
            }
            *(float4*)&H1[n*68 + rm]     = make_float4(vals[0],vals[1],vals[2],vals[3]);
            *(float4*)&H1[n*68 + rm + 4] = make_float4(vals[4],vals[5],vals[6],vals[7]);
        }
        __syncthreads();
    }

    // ---- stage 2+3: chunked fcm + fc2 accumulation ----
    int tx2 = t & 15, ty2 = t >> 4;       // stage2: n=tx2*8, m=ty2*4
    int m3 = t >> 2, tn3 = (t & 3) * 8;   // stage3: m=m3, n=tn3..tn3+7
    float2 oacc[4];
    #pragma unroll
    for (int j = 0; j < 4; j++) oacc[j] = make_float2(0.f,0.f);

    for (int c = 0; c < 4; c++) {
        float2 a2[4][4];
        #pragma unroll
        for (int i = 0; i < 4; i++)
            #pragma unroll
            for (int j = 0; j < 4; j++) a2[i][j] = make_float2(0.f,0.f);
        for (int kt = 0; kt < 16; kt++) {
            for (int i = t; i < 2048; i += 256) {
                int kk = i >> 7, n = i & 127;
                Ws[i] = w2[(size_t)(kt*16+kk)*512 + c*128 + n];
            }
            __syncthreads();
            #pragma unroll 4
            for (int k = 0; k < 16; k++) {
                float4 av  = *(const float4*)&H1[(kt*16+k)*68 + ty2*4];
                float4 wv0 = *(const float4*)&Ws[k*128 + tx2*8];
                float4 wv1 = *(const float4*)&Ws[k*128 + tx2*8 + 4];
                float a[4] = {av.x,av.y,av.z,av.w};
                float2 wf[4] = {make_float2(wv0.x,wv0.y), make_float2(wv0.z,wv0.w),
                                make_float2(wv1.x,wv1.y), make_float2(wv1.z,wv1.w)};
                #pragma unroll
                for (int i = 0; i < 4; i++) {
                    float2 ab = make_float2(a[i], a[i]);
                    #pragma unroll
                    for (int j = 0; j < 4; j++) a2[i][j] = ffma2(ab, wf[j], a2[i][j]);
                }
            }
            __syncthreads();
        }
        // bias+relu, store H2 transposed [n][m]
        #pragma unroll
        for (int jj = 0; jj < 8; jj++) {
            int n = tx2*8 + jj;
            float bia = b2[c*128 + n];
            int j = jj >> 1, comp = jj & 1;
            float vals[4];
            #pragma unroll
            for (int i = 0; i < 4; i++) {
                float vv = (comp ? a2[i][j].y : a2[i][j].x) + bia;
                vals[i] = fmaxf(vv, 0.f);
            }
            *(float4*)&H2[n*68 + ty2*4] = make_float4(vals[0],vals[1],vals[2],vals[3]);
        }
        __syncthreads();
        // load W3 chunk [128][32]
        for (int i = t; i < 4096; i += 256) Ws[i] = w3[c*4096 + i];
        __syncthreads();
        // stage 3 accumulate OUT += H2c @ W3c
        #pragma unroll 4
        for (int k = 0; k < 128; k++) {
            float a = H2[k*68 + m3];
            float4 wv0 = *(const float4*)&Ws[k*32 + tn3];
            float4 wv1 = *(const float4*)&Ws[k*32 + tn3 + 4];
            float2 ab = make_float2(a, a);
            oacc[0] = ffma2(ab, make_float2(wv0.x, wv0.y), oacc[0]);
            oacc[1] = ffma2(ab, make_float2(wv0.z, wv0.w), oacc[1]);
            oacc[2] = ffma2(ab, make_float2(wv1.x, wv1.y), oacc[2]);
            oacc[3] = ffma2(ab, make_float2(wv1.z, wv1.w), oacc[3]);
        }
        __syncthreads();
    }

    // epilogue: + b3, scatter to z_p layout [n=(bv,f)][d]
    int row = row0 + m3;
    int bv32 = (row0 >> 7) * 32;
    int d = row & 127;
    #pragma unroll
    for (int jj = 0; jj < 8; jj++) {
        int f = tn3 + jj;
        int j = jj >> 1, comp = jj & 1;
        float vv = (comp ? oacc[j].y : oacc[j].x) + b3[f];
        g_Zp[(size_t)(bv32 + f)*128 + d] = vv;
    }
}

// ---------------- K4: VQ distances + logits + top5 + softmax gather --------
__global__ void __launch_bounds__(256) k_vq(const float* __restrict__ cent,
                                            float* __restrict__ logits) {
    extern __shared__ float sm[];
    float* Zt  = sm;               // [128 d][68 m]   8704
    float* Cs  = Zt + 8704;        // [128 d][136 k]  17408
    float* z2s = Cs + 17408;       // 64
    float* sval = z2s + 64;        // 64*16*5 = 5120
    int*   sidx = (int*)(sval + 5120);
    float* wsm  = (float*)(sidx + 5120);  // 64*5
    int*   ism  = (int*)(wsm + 320);      // 64*5
    int t = threadIdx.x;
    int n0 = blockIdx.x * 64;

    for (int i = t; i < 64*128; i += 256) {
        int m = i >> 7, d = i & 127;
        Zt[d*68 + m] = g_Zp[(size_t)(n0+m)*128 + d];
    }
    __syncthreads();
    if (t < 64) {
        float s = 0.f;
        for (int d = 0; d < 128; d++) { float vv = Zt[d*68 + t]; s += vv*vv; }
        z2s[t] = s;
    }
    __syncthreads();

    int tx = t & 15, ty = t >> 4;
    int kk = tx*8, mb = ty*4;
    float tv[4][5]; int ti[4][5];
    #pragma unroll
    for (int i = 0; i < 4; i++)
        #pragma unroll
        for (int s5 = 0; s5 < 5; s5++) { tv[i][s5] = 3.0e38f; ti[i][s5] = 0; }

    for (int kt = 0; kt < 8; kt++) {
        for (int i = t; i < 128*128; i += 256) {
            int k = i >> 7, d = i & 127;
            Cs[d*136 + k] = cent[(size_t)(kt*128+k)*128 + d];
        }
        __syncthreads();
        float2 acc[4][4];
        #pragma unroll
        for (int i = 0; i < 4; i++)
            #pragma unroll
            for (int j = 0; j < 4; j++) acc[i][j] = make_float2(0.f,0.f);
        #pragma unroll 4
        for (int d = 0; d < 128; d++) {
            float4 av  = *(const float4*)&Zt[d*68 + mb];
            float4 w0  = *(const float4*)&Cs[d*136 + kk];
            float4 w1  = *(const float4*)&Cs[d*136 + kk + 4];
            float a[4] = {av.x,av.y,av.z,av.w};
            float2 wf[4] = {make_float2(w0.x,w0.y), make_float2(w0.z,w0.w),
                            make_float2(w1.x,w1.y), make_float2(w1.z,w1.w)};
            #pragma unroll
            for (int i = 0; i < 4; i++) {
                float2 ab = make_float2(a[i], a[i]);
                #pragma unroll
                for (int j = 0; j < 4; j++) acc[i][j] = ffma2(ab, wf[j], acc[i][j]);
            }
        }
        // epilogue: dist -> logits + local top5
        #pragma unroll
        for (int i = 0; i < 4; i++) {
            int n = n0 + mb + i;
            float z2v = z2s[mb + i];
            float vout[8];
            #pragma unroll
            for (int jj = 0; jj < 8; jj++) {
                int k = kt*128 + kk + jj;
                int j = jj >> 1, comp = jj & 1;
                float zc = comp ? acc[i][j].y : acc[i][j].x;
                float dist = z2v + g_c2[k] - 2.0f*zc;
                vout[jj] = -dist;
                if (dist < tv[i][4]) {
                    tv[i][4] = dist; ti[i][4] = k;
                    #pragma unroll
                    for (int s5 = 4; s5 > 0; s5--) {
                        if (tv[i][s5] < tv[i][s5-1]) {
                            float tf = tv[i][s5]; tv[i][s5] = tv[i][s5-1]; tv[i][s5-1] = tf;
                            int tk = ti[i][s5]; ti[i][s5] = ti[i][s5-1]; ti[i][s5-1] = tk;
                        }
                    }
                }
            }
            float* lp = logits + (size_t)n*1024 + kt*128 + kk;
            *(float4*)lp     = make_float4(vout[0],vout[1],vout[2],vout[3]);
            *(float4*)(lp+4) = make_float4(vout[4],vout[5],vout[6],vout[7]);
        }
        __syncthreads();
    }

    // dump local top5 and merge per row
    #pragma unroll
    for (int i = 0; i < 4; i++) {
        int r = mb + i;
        #pragma unroll
        for (int s5 = 0; s5 < 5; s5++) {
            sval[r*80 + tx*5 + s5] = tv[i][s5];
            sidx[r*80 + tx*5 + s5] = ti[i][s5];
        }
    }
    __syncthreads();
    if (t < 64) {
        float mv[5]; int mi[5];
        #pragma unroll
        for (int s5 = 0; s5 < 5; s5++) { mv[s5] = 3.0e38f; mi[s5] = 0; }
        for (int c = 0; c < 80; c++) {
            float dv = sval[t*80 + c]; int ki = sidx[t*80 + c];
            if (dv < mv[4]) {
                mv[4] = dv; mi[4] = ki;
                #pragma unroll
                for (int s5 = 4; s5 > 0; s5--) {
                    if (mv[s5] < mv[s5-1]) {
                        float tf = mv[s5]; mv[s5] = mv[s5-1]; mv[s5-1] = tf;
                        int tk = mi[s5]; mi[s5] = mi[s5-1]; mi[s5-1] = tk;
                    }
                }
            }
        }
        float m0 = mv[0];
        float wv[5]; float wsum = 0.f;
        #pragma unroll
        for (int j = 0; j < 5; j++) { wv[j] = expf(m0 - mv[j]); wsum += wv[j]; }
        float inv = 1.0f / wsum;
        #pragma unroll
        for (int j = 0; j < 5; j++) { wsm[t*5 + j] = wv[j]*inv; ism[t*5 + j] = mi[j]; }
    }
    __syncthreads();

    // weighted codebook gather -> z_code
    int w = t >> 5, l = t & 31;
    for (int r = w; r < 64; r += 8) {
        float wg[5]; int id[5];
        #pragma unroll
        for (int j = 0; j < 5; j++) { wg[j] = wsm[r*5 + j]; id[j] = ism[r*5 + j]; }
        int dbase = l*4;
        float4 o = make_float4(0.f,0.f,0.f,0.f);
        #pragma unroll
        for (int j = 0; j < 5; j++) {
            float4 cv = *(const float4*)&cent[(size_t)id[j]*128 + dbase];
            o.x += wg[j]*cv.x; o.y += wg[j]*cv.y;
            o.z += wg[j]*cv.z; o.w += wg[j]*cv.w;
        }
        *(float4*)&g_Zcode[(size_t)(n0+r)*128 + dbase] = o;
    }
}

// ---------------- K5: residual fusion + LN + decode + denorm ---------------
__global__ void __launch_bounds__(256) k_fuse(
    const float* __restrict__ fw, const float* __restrict__ fb,
    const float* __restrict__ flnw, const float* __restrict__ flnb,
    const float* __restrict__ dw, const float* __restrict__ db,
    float* __restrict__ out) {
    extern __shared__ float sm[];
    float* Ws  = sm;            // 128*128 = 16384
    float* Zps = Ws + 16384;    // 32*128 = 4096
    float* dws = Zps + 4096;    // 128*16 = 2048
    float* Fs  = dws + 2048;    // 8*128 = 1024
    int t = threadIdx.x;
    int bv = blockIdx.x;
    int b = bv >> 6, v = bv & 63;
    for (int i = t; i < 16384; i += 256) Ws[i] = fw[i];
    for (int i = t; i < 4096; i += 256) Zps[i] = g_Zp[(size_t)bv*4096 + i];
    for (int i = t; i < 2048; i += 256) dws[i] = dw[i];
    __syncthreads();
    int w = t >> 5, l = t & 31;
    float stdv = g_std[bv], meanv = g_mean[bv];
    for (int f = w; f < 32; f += 8) {
        float acc4[4];
        #pragma unroll
        for (int q = 0; q < 4; q++) acc4[q] = fb[l + 32*q];
        const float* zrow = &Zps[f*128];
        for (int e = 0; e < 128; e++) {
            float z = zrow[e];
            const float* wr = &Ws[e*128];
            #pragma unroll
            for (int q = 0; q < 4; q++) acc4[q] += z * wr[l + 32*q];
        }
        size_t nrow = (size_t)(bv*32 + f)*128;
        float s = 0.f, qq = 0.f;
        #pragma unroll
        for (int q = 0; q < 4; q++) {
            float val = fmaxf(acc4[q], 0.f) + g_Zcode[nrow + l + 32*q];
            acc4[q] = val;
            s += val; qq += val*val;
        }
        #pragma unroll
        for (int o = 16; o; o >>= 1) {
            s  += __shfl_xor_sync(0xffffffffu, s,  o);
            qq += __shfl_xor_sync(0xffffffffu, qq, o);
        }
        float mu = s * (1.0f/128.0f);
        float rs = rsqrtf(qq*(1.0f/128.0f) - mu*mu + 1e-5f);
        #pragma unroll
        for (int q = 0; q < 4; q++) {
            int d = l + 32*q;
            Fs[w*128 + d] = (acc4[q]-mu)*rs*flnw[d] + flnb[d];
        }
        __syncwarp();
        if (l < 16) {
            float r = db[l];
            #pragma unroll 8
            for (int d = 0; d < 128; d++) r += Fs[w*128 + d] * dws[d*16 + l];
            out[(size_t)b*512*64 + (size_t)(f*16 + l)*64 + v] = r*stdv + meanv;
        }
        __syncwarp();
    }
}

// ---------------- launch ---------------------------------------------------
extern "C" void kernel_launch(void* const* d_in, const int* in_sizes, int n_in,
                              void* d_out, int out_size) {
    const float* x      = (const float*)d_in[0];
    const float* cent   = (const float*)d_in[1];
    const float* enc_w  = (const float*)d_in[2];
    const float* enc_b  = (const float*)d_in[3];
    const float* ln_w   = (const float*)d_in[4];
    const float* ln_b   = (const float*)d_in[5];
    const float* fc1_w  = (const float*)d_in[6];
    const float* fc1_b  = (const float*)d_in[7];
    const float* fcm_w  = (const float*)d_in[8];
    const float* fcm_b  = (const float*)d_in[9];
    const float* fc2_w  = (const float*)d_in[10];
    const float* fc2_b  = (const float*)d_in[11];
    const float* fuse_w = (const float*)d_in[12];
    const float* fuse_b = (const float*)d_in[13];
    const float* fln_w  = (const float*)d_in[14];
    const float* fln_b  = (const float*)d_in[15];
    const float* dec_w  = (const float*)d_in[16];
    const float* dec_b  = (const float*)d_in[17];

    float* out    = (float*)d_out;
    float* logits = out + (size_t)BB*512*VV;   // outputs first, then logits

    int sm3 = (64*72 + 4096 + 256*68 + 128*68) * 4;            // 139264
    int sm4 = (8704 + 17408 + 64 + 5120 + 5120 + 320 + 320)*4; // 148224
    int sm5 = (16384 + 4096 + 2048 + 1024) * 4;                // 94208
    cudaFuncSetAttribute(k_mlp,  cudaFuncAttributeMaxDynamicSharedMemorySize, sm3);
    cudaFuncSetAttribute(k_vq,   cudaFuncAttributeMaxDynamicSharedMemorySize, sm4);
    cudaFuncSetAttribute(k_fuse, cudaFuncAttributeMaxDynamicSharedMemorySize, sm5);

    k_revin<<<BB, dim3(64,8)>>>(x);
    k_c2<<<KK/8, 256>>>(cent);
    k_encode<<<BB*VV, 256>>>(x, enc_w, enc_b, ln_w, ln_b);
    k_mlp<<<NROW/64, 256, sm3>>>(fc1_w, fc1_b, fcm_w, fcm_b, fc2_w, fc2_b);
    k_vq<<<NVQ/64, 256, sm4>>>(cent, logits);
    k_fuse<<<BB*VV, 256, sm5>>>(fuse_w, fuse_b, fln_w, fln_b, dec_w, dec_b, out);
}

// round 4
// speedup vs baseline: 3.0394x; 3.0394x over previous
#include <cuda_runtime.h>
#include <cuda_bf16.h>
#include <math.h>
#include <stdint.h>

#define BB   32
#define LL   1024
#define VV   64
#define PHn  64
#define PFn  32
#define DD   128
#define KK   1024
#define NVQ  (BB*VV*PFn)
#define NROW (BB*VV*DD)

__device__ float g_mean[BB*VV];
__device__ float g_std[BB*VV];
__device__ float g_Zp[(size_t)NVQ*DD];
__device__ float g_Zcode[(size_t)NVQ*DD];
__device__ float g_c2[KK];
__device__ __nv_bfloat16 g_Ab[(size_t)NROW*64];   // [bv][d(row)][p(k)] 16KB each
__device__ __nv_bfloat16 g_W1b[64*256];           // [k][n] row-major
__device__ __nv_bfloat16 g_W2b[256*512];
__device__ __nv_bfloat16 g_W3b[512*32];

// ===== helpers =====
__device__ __forceinline__ uint32_t smem_u32(const void* p) {
    uint32_t a;
    asm("{ .reg .u64 t; cvta.to.shared.u64 t, %1; cvt.u32.u64 %0, t; }" : "=r"(a) : "l"(p));
    return a;
}
__device__ __forceinline__ void ldsm4(uint32_t* r, uint32_t a) {
    asm volatile("ldmatrix.sync.aligned.m8n8.x4.shared.b16 {%0,%1,%2,%3}, [%4];"
        : "=r"(r[0]), "=r"(r[1]), "=r"(r[2]), "=r"(r[3]) : "r"(a));
}
__device__ __forceinline__ void ldsm4t(uint32_t* r, uint32_t a) {
    asm volatile("ldmatrix.sync.aligned.m8n8.x4.trans.shared.b16 {%0,%1,%2,%3}, [%4];"
        : "=r"(r[0]), "=r"(r[1]), "=r"(r[2]), "=r"(r[3]) : "r"(a));
}
__device__ __forceinline__ void mma_bf16(float* c, const uint32_t* a, uint32_t b0, uint32_t b1) {
    asm volatile("mma.sync.aligned.m16n8k16.row.col.f32.bf16.bf16.f32 "
        "{%0,%1,%2,%3}, {%4,%5,%6,%7}, {%8,%9}, {%0,%1,%2,%3};"
        : "+f"(c[0]), "+f"(c[1]), "+f"(c[2]), "+f"(c[3])
        : "r"(a[0]), "r"(a[1]), "r"(a[2]), "r"(a[3]), "r"(b0), "r"(b1));
}
__device__ __forceinline__ uint32_t packrelu(float x, float y, float bx, float by) {
    __nv_bfloat162 h = __float22bfloat162_rn(make_float2(fmaxf(x+bx,0.f), fmaxf(y+by,0.f)));
    return *reinterpret_cast<uint32_t*>(&h);
}
__device__ __forceinline__ float2 ffma2(float2 a, float2 b, float2 c) {
    float2 r;
    asm("fma.rn.f32x2 %0, %1, %2, %3;"
        : "=l"(*reinterpret_cast<unsigned long long*>(&r))
        : "l"(*reinterpret_cast<unsigned long long*>(&a)),
          "l"(*reinterpret_cast<unsigned long long*>(&b)),
          "l"(*reinterpret_cast<unsigned long long*>(&c)));
    return r;
}

// ===== K1: RevIN stats =====
__global__ void k_revin(const float* __restrict__ x) {
    int b = blockIdx.x, v = threadIdx.x, ty = threadIdx.y;
    __shared__ float ssum[8][64], ssq[8][64];
    float s = 0.f, q = 0.f;
    const float* xp = x + (size_t)b*LL*VV + v;
    for (int l = ty; l < LL; l += 8) { float val = xp[(size_t)l*VV]; s += val; q += val*val; }
    ssum[ty][v] = s; ssq[ty][v] = q;
    __syncthreads();
    if (ty == 0) {
        for (int j = 1; j < 8; j++) { s += ssum[j][v]; q += ssq[j][v]; }
        float mean = s * (1.0f/LL);
        g_mean[b*VV + v] = mean;
        g_std[b*VV + v]  = sqrtf(q*(1.0f/LL) - mean*mean + 1e-5f);
    }
}

// ===== K1b: centroid norms =====
__global__ void k_c2(const float* __restrict__ cent) {
    int w = threadIdx.x >> 5, l = threadIdx.x & 31;
    int k = blockIdx.x * 8 + w;
    const float* cp = cent + (size_t)k*DD;
    float s = 0.f;
    #pragma unroll
    for (int q = 0; q < 4; q++) { float c = cp[l + 32*q]; s += c*c; }
    #pragma unroll
    for (int o = 16; o; o >>= 1) s += __shfl_xor_sync(0xffffffffu, s, o);
    if (l == 0) g_c2[k] = s;
}

// ===== K1c: weight convert to bf16 (row-major preserved) =====
__global__ void k_wprep(const float* __restrict__ w1, const float* __restrict__ w2,
                        const float* __restrict__ w3) {
    int i = blockIdx.x*256 + threadIdx.x;
    if (i < 16384)        g_W1b[i] = __float2bfloat16(w1[i]);
    else if (i < 147456)  g_W2b[i - 16384] = __float2bfloat16(w2[i - 16384]);
    else if (i < 163840)  g_W3b[i - 147456] = __float2bfloat16(w3[i - 147456]);
}

// ===== K2: encode + LN -> bf16 A [d][p] =====
__global__ void __launch_bounds__(256) k_encode(
    const float* __restrict__ x, const float* __restrict__ ew,
    const float* __restrict__ eb, const float* __restrict__ lnw,
    const float* __restrict__ lnb) {
    __shared__ float xv[1024], ws[2048], zt[8192];
    int bv = blockIdx.x, t = threadIdx.x;
    int b = bv >> 6, v = bv & 63;
    float mean = g_mean[bv], rstd = 1.0f / g_std[bv];
    const float* xp = x + (size_t)b*LL*VV + v;
    for (int i = t; i < 1024; i += 256) xv[i] = (xp[(size_t)i*VV] - mean) * rstd;
    for (int i = t; i < 2048; i += 256) ws[i] = ew[i];
    __syncthreads();
    for (int idx = t; idx < 8192; idx += 256) {
        int p = idx >> 7, d = idx & 127;
        float s = eb[d];
        const float* xq = &xv[p*16];
        #pragma unroll
        for (int i = 0; i < 16; i++) s += xq[i] * ws[i*128 + d];
        zt[idx] = s;
    }
    __syncthreads();
    int w = t >> 5, l = t & 31;
    __nv_bfloat16* Adst = g_Ab + (size_t)bv*8192;
    #pragma unroll
    for (int j = 0; j < 8; j++) {
        int p = w*8 + j;
        float z[4], s = 0.f, q = 0.f;
        #pragma unroll
        for (int qq = 0; qq < 4; qq++) {
            z[qq] = zt[p*128 + l + 32*qq];
            s += z[qq]; q += z[qq]*z[qq];
        }
        #pragma unroll
        for (int o = 16; o; o >>= 1) {
            s += __shfl_xor_sync(0xffffffffu, s, o);
            q += __shfl_xor_sync(0xffffffffu, q, o);
        }
        float mu = s * (1.0f/128.0f);
        float rs = rsqrtf(q*(1.0f/128.0f) - mu*mu + 1e-5f);
        #pragma unroll
        for (int qq = 0; qq < 4; qq++) {
            int d = l + 32*qq;
            Adst[d*64 + p] = __float2bfloat16((z[qq]-mu)*rs*lnw[d] + lnb[d]);
        }
    }
}

// ===== K3: HMMA bf16 fused MLP =====
// smem layout (bytes), strides in bf16 elements (+8 pad, 16B-multiple):
//   A   [128][72]  @ 0       (18432)  -> reused as f32 OUT[32][132] at end
//   W   [64][264] / [256][136] @ 18432 (W1 33792 / W2 chunk 69632)
//   H1  [128][264] @ 88064   (67584)
//   H2c [128][136] @ 155648  (34816)
//   W3  [512][40]  @ 190464  (40960)   total 231424
#define MO_A   0
#define MO_W   18432
#define MO_H1  88064
#define MO_H2  155648
#define MO_W3  190464
#define SMEM_MLP 231424

__device__ __forceinline__ void gemm_tile64(uint32_t Abase, int sA, int m0,
                                            uint32_t Bbase, int sB, int n0,
                                            int ksteps, int l, float acc[8][4]) {
    for (int ks = 0; ks < ksteps; ks++) {
        int kk = ks*16;
        uint32_t av[4];
        ldsm4(av, Abase + (uint32_t)(((m0 + (l&15))*sA + kk + ((l>>4)<<3))*2));
        #pragma unroll
        for (int t = 0; t < 4; t++) {
            uint32_t bvv[4];
            ldsm4t(bvv, Bbase + (uint32_t)(((kk + (l&15))*sB + n0 + t*16 + ((l>>4)<<3))*2));
            mma_bf16(acc[2*t],   av, bvv[0], bvv[1]);
            mma_bf16(acc[2*t+1], av, bvv[2], bvv[3]);
        }
    }
}

__device__ __forceinline__ void epi64(float acc[8][4], char* hdst, int sH, int m0, int n0,
                                      const float* __restrict__ bias, int boff, int l) {
    int row = l >> 2, qc = (l & 3)*2;
    #pragma unroll
    for (int t8 = 0; t8 < 8; t8++) {
        int col = n0 + t8*8 + qc;
        float b0 = __ldg(&bias[boff + col]), b1 = __ldg(&bias[boff + col + 1]);
        *(uint32_t*)(hdst + ((m0+row)*sH + col)*2)   = packrelu(acc[t8][0], acc[t8][1], b0, b1);
        *(uint32_t*)(hdst + ((m0+row+8)*sH + col)*2) = packrelu(acc[t8][2], acc[t8][3], b0, b1);
    }
}

__global__ void __launch_bounds__(256, 1) k_mlp_mma(
    const float* __restrict__ b1g, const float* __restrict__ b2g,
    const float* __restrict__ b3g) {
    extern __shared__ char smem[];
    uint32_t base = smem_u32(smem);
    int t = threadIdx.x, w = t >> 5, l = t & 31;
    int bv = blockIdx.x;

    {   // load A, W1, W3 into padded smem
        const uint4* Ag = reinterpret_cast<const uint4*>(g_Ab) + (size_t)bv*1024;
        for (int i = t; i < 1024; i += 256) {
            int row = i >> 3, q = i & 7;
            *(uint4*)(smem + MO_A + row*144 + q*16) = Ag[i];
        }
        const uint4* W1g = reinterpret_cast<const uint4*>(g_W1b);
        for (int i = t; i < 2048; i += 256) {
            int row = i >> 5, q = i & 31;
            *(uint4*)(smem + MO_W + row*528 + q*16) = W1g[i];
        }
        const uint4* W3g = reinterpret_cast<const uint4*>(g_W3b);
        for (int i = t; i < 2048; i += 256) {
            int row = i >> 2, q = i & 3;
            *(uint4*)(smem + MO_W3 + row*80 + q*16) = W3g[i];
        }
    }
    __syncthreads();

    // stage 1: H1[128,256] = relu(A @ W1 + b1)
    {
        int m0 = w*16;
        for (int j = 0; j < 4; j++) {
            float acc[8][4];
            #pragma unroll
            for (int i = 0; i < 8; i++)
                #pragma unroll
                for (int jj = 0; jj < 4; jj++) acc[i][jj] = 0.f;
            gemm_tile64(base + MO_A, 72, m0, base + MO_W, 264, j*64, 4, l, acc);
            epi64(acc, smem + MO_H1, 264, m0, j*64, b1g, 0, l);
        }
    }
    __syncthreads();

    // stages 2+3: N-chunked fcm (relu) + fc2 accumulation
    float acc3[4][4];
    #pragma unroll
    for (int i = 0; i < 4; i++)
        #pragma unroll
        for (int j = 0; j < 4; j++) acc3[i][j] = 0.f;
    const uint4* W2g = reinterpret_cast<const uint4*>(g_W2b);
    int m0 = w*16;
    for (int c = 0; c < 4; c++) {
        for (int i = t; i < 4096; i += 256) {       // W2 chunk [256][128]
            int row = i >> 4, q = i & 15;
            *(uint4*)(smem + MO_W + row*272 + q*16) = W2g[row*64 + c*16 + q];
        }
        __syncthreads();
        for (int j = 0; j < 2; j++) {
            float acc[8][4];
            #pragma unroll
            for (int i = 0; i < 8; i++)
                #pragma unroll
                for (int jj = 0; jj < 4; jj++) acc[i][jj] = 0.f;
            gemm_tile64(base + MO_H1, 264, m0, base + MO_W, 136, j*64, 16, l, acc);
            epi64(acc, smem + MO_H2, 136, m0, j*64, b2g, c*128, l);
        }
        // stage 3: each warp reads only its own H2 rows — no sync needed
        for (int ks = 0; ks < 8; ks++) {
            int kk = ks*16;
            uint32_t av[4];
            ldsm4(av, base + MO_H2 + (uint32_t)(((m0 + (l&15))*136 + kk + ((l>>4)<<3))*2));
            #pragma unroll
            for (int tt = 0; tt < 2; tt++) {
                uint32_t bvv[4];
                ldsm4t(bvv, base + MO_W3 + (uint32_t)(((c*128 + kk + (l&15))*40 + tt*16 + ((l>>4)<<3))*2));
                mma_bf16(acc3[2*tt],   av, bvv[0], bvv[1]);
                mma_bf16(acc3[2*tt+1], av, bvv[2], bvv[3]);
            }
        }
        __syncthreads();   // guard W2/H2 reuse next chunk
    }

    // final epilogue: +b3, transpose via smem, write z_p [f][d]
    float* OUT = (float*)(smem + MO_A);
    {
        int row = l >> 2, qc = (l & 3)*2;
        #pragma unroll
        for (int t8 = 0; t8 < 4; t8++) {
            int col = t8*8 + qc;
            float b0 = __ldg(&b3g[col]), b1 = __ldg(&b3g[col+1]);
            OUT[col*132     + m0 + row]     = acc3[t8][0] + b0;
            OUT[(col+1)*132 + m0 + row]     = acc3[t8][1] + b1;
            OUT[col*132     + m0 + row + 8] = acc3[t8][2] + b0;
            OUT[(col+1)*132 + m0 + row + 8] = acc3[t8][3] + b1;
        }
    }
    __syncthreads();
    float* zp = g_Zp + (size_t)bv*4096;
    for (int i = t; i < 4096; i += 256) {
        int f = i >> 7, r = i & 127;
        zp[i] = OUT[f*132 + r];
    }
}

// ===== K4: VQ distances + logits + top5 + softmax gather =====
__global__ void __launch_bounds__(256) k_vq(const float* __restrict__ cent,
                                            float* __restrict__ logits) {
    extern __shared__ float sm[];
    float* Zt  = sm;               // [128 d][68 m]
    float* Cs  = Zt + 8704;        // [128 d][136 k]
    float* z2s = Cs + 17408;
    float* sval = z2s + 64;
    int*   sidx = (int*)(sval + 5120);
    float* wsm  = (float*)(sidx + 5120);
    int*   ism  = (int*)(wsm + 320);
    int t = threadIdx.x;
    int n0 = blockIdx.x * 64;

    for (int i = t; i < 64*128; i += 256) {
        int m = i >> 7, d = i & 127;
        Zt[d*68 + m] = g_Zp[(size_t)(n0+m)*128 + d];
    }
    __syncthreads();
    if (t < 64) {
        float s = 0.f;
        for (int d = 0; d < 128; d++) { float vv = Zt[d*68 + t]; s += vv*vv; }
        z2s[t] = s;
    }
    __syncthreads();

    int tx = t & 15, ty = t >> 4;
    int kk = tx*8, mb = ty*4;
    float tv[4][5]; int ti[4][5];
    #pragma unroll
    for (int i = 0; i < 4; i++)
        #pragma unroll
        for (int s5 = 0; s5 < 5; s5++) { tv[i][s5] = 3.0e38f; ti[i][s5] = 0; }

    for (int kt = 0; kt < 8; kt++) {
        for (int i = t; i < 128*128; i += 256) {
            int k = i >> 7, d = i & 127;
            Cs[d*136 + k] = cent[(size_t)(kt*128+k)*128 + d];
        }
        __syncthreads();
        float2 acc[4][4];
        #pragma unroll
        for (int i = 0; i < 4; i++)
            #pragma unroll
            for (int j = 0; j < 4; j++) acc[i][j] = make_float2(0.f,0.f);
        #pragma unroll 4
        for (int d = 0; d < 128; d++) {
            float4 av = *(const float4*)&Zt[d*68 + mb];
            float4 w0 = *(const float4*)&Cs[d*136 + kk];
            float4 w1 = *(const float4*)&Cs[d*136 + kk + 4];
            float a[4] = {av.x,av.y,av.z,av.w};
            float2 wf[4] = {make_float2(w0.x,w0.y), make_float2(w0.z,w0.w),
                            make_float2(w1.x,w1.y), make_float2(w1.z,w1.w)};
            #pragma unroll
            for (int i = 0; i < 4; i++) {
                float2 ab = make_float2(a[i], a[i]);
                #pragma unroll
                for (int j = 0; j < 4; j++) acc[i][j] = ffma2(ab, wf[j], acc[i][j]);
            }
        }
        #pragma unroll
        for (int i = 0; i < 4; i++) {
            int n = n0 + mb + i;
            float z2v = z2s[mb + i];
            float vout[8];
            #pragma unroll
            for (int jj = 0; jj < 8; jj++) {
                int k = kt*128 + kk + jj;
                int j = jj >> 1, comp = jj & 1;
                float zc = comp ? acc[i][j].y : acc[i][j].x;
                float dist = z2v + g_c2[k] - 2.0f*zc;
                vout[jj] = -dist;
                if (dist < tv[i][4]) {
                    tv[i][4] = dist; ti[i][4] = k;
                    #pragma unroll
                    for (int s5 = 4; s5 > 0; s5--) {
                        if (tv[i][s5] < tv[i][s5-1]) {
                            float tf = tv[i][s5]; tv[i][s5] = tv[i][s5-1]; tv[i][s5-1] = tf;
                            int tk = ti[i][s5]; ti[i][s5] = ti[i][s5-1]; ti[i][s5-1] = tk;
                        }
                    }
                }
            }
            float* lp = logits + (size_t)n*1024 + kt*128 + kk;
            *(float4*)lp     = make_float4(vout[0],vout[1],vout[2],vout[3]);
            *(float4*)(lp+4) = make_float4(vout[4],vout[5],vout[6],vout[7]);
        }
        __syncthreads();
    }

    #pragma unroll
    for (int i = 0; i < 4; i++) {
        int r = mb + i;
        #pragma unroll
        for (int s5 = 0; s5 < 5; s5++) {
            sval[r*80 + tx*5 + s5] = tv[i][s5];
            sidx[r*80 + tx*5 + s5] = ti[i][s5];
        }
    }
    __syncthreads();
    if (t < 64) {
        float mv[5]; int mi[5];
        #pragma unroll
        for (int s5 = 0; s5 < 5; s5++) { mv[s5] = 3.0e38f; mi[s5] = 0; }
        for (int c = 0; c < 80; c++) {
            float dv = sval[t*80 + c]; int ki = sidx[t*80 + c];
            if (dv < mv[4]) {
                mv[4] = dv; mi[4] = ki;
                #pragma unroll
                for (int s5 = 4; s5 > 0; s5--) {
                    if (mv[s5] < mv[s5-1]) {
                        float tf = mv[s5]; mv[s5] = mv[s5-1]; mv[s5-1] = tf;
                        int tk = mi[s5]; mi[s5] = mi[s5-1]; mi[s5-1] = tk;
                    }
                }
            }
        }
        float m0 = mv[0];
        float wv[5]; float wsum = 0.f;
        #pragma unroll
        for (int j = 0; j < 5; j++) { wv[j] = expf(m0 - mv[j]); wsum += wv[j]; }
        float inv = 1.0f / wsum;
        #pragma unroll
        for (int j = 0; j < 5; j++) { wsm[t*5 + j] = wv[j]*inv; ism[t*5 + j] = mi[j]; }
    }
    __syncthreads();

    int w = t >> 5, l = t & 31;
    for (int r = w; r < 64; r += 8) {
        float wg[5]; int id[5];
        #pragma unroll
        for (int j = 0; j < 5; j++) { wg[j] = wsm[r*5 + j]; id[j] = ism[r*5 + j]; }
        int dbase = l*4;
        float4 o = make_float4(0.f,0.f,0.f,0.f);
        #pragma unroll
        for (int j = 0; j < 5; j++) {
            float4 cv = *(const float4*)&cent[(size_t)id[j]*128 + dbase];
            o.x += wg[j]*cv.x; o.y += wg[j]*cv.y;
            o.z += wg[j]*cv.z; o.w += wg[j]*cv.w;
        }
        *(float4*)&g_Zcode[(size_t)(n0+r)*128 + dbase] = o;
    }
}

// ===== K5: residual fusion + LN + decode + denorm =====
__global__ void __launch_bounds__(256) k_fuse(
    const float* __restrict__ fw, const float* __restrict__ fb,
    const float* __restrict__ flnw, const float* __restrict__ flnb,
    const float* __restrict__ dw, const float* __restrict__ db,
    float* __restrict__ out) {
    extern __shared__ float sm[];
    float* Ws  = sm;            // 16384
    float* Zps = Ws + 16384;    // 4096
    float* dws = Zps + 4096;    // 2048
    float* Fs  = dws + 2048;    // 1024
    int t = threadIdx.x;
    int bv = blockIdx.x;
    int b = bv >> 6, v = bv & 63;
    for (int i = t; i < 16384; i += 256) Ws[i] = fw[i];
    for (int i = t; i < 4096; i += 256) Zps[i] = g_Zp[(size_t)bv*4096 + i];
    for (int i = t; i < 2048; i += 256) dws[i] = dw[i];
    __syncthreads();
    int w = t >> 5, l = t & 31;
    float stdv = g_std[bv], meanv = g_mean[bv];
    for (int f = w; f < 32; f += 8) {
        float acc4[4];
        #pragma unroll
        for (int q = 0; q < 4; q++) acc4[q] = fb[l + 32*q];
        const float* zrow = &Zps[f*128];
        for (int e = 0; e < 128; e++) {
            float z = zrow[e];
            const float* wr = &Ws[e*128];
            #pragma unroll
            for (int q = 0; q < 4; q++) acc4[q] += z * wr[l + 32*q];
        }
        size_t nrow = (size_t)(bv*32 + f)*128;
        float s = 0.f, qq = 0.f;
        #pragma unroll
        for (int q = 0; q < 4; q++) {
            float val = fmaxf(acc4[q], 0.f) + g_Zcode[nrow + l + 32*q];
            acc4[q] = val;
            s += val; qq += val*val;
        }
        #pragma unroll
        for (int o = 16; o; o >>= 1) {
            s  += __shfl_xor_sync(0xffffffffu, s,  o);
            qq += __shfl_xor_sync(0xffffffffu, qq, o);
        }
        float mu = s * (1.0f/128.0f);
        float rs = rsqrtf(qq*(1.0f/128.0f) - mu*mu + 1e-5f);
        #pragma unroll
        for (int q = 0; q < 4; q++) {
            int d = l + 32*q;
            Fs[w*128 + d] = (acc4[q]-mu)*rs*flnw[d] + flnb[d];
        }
        __syncwarp();
        if (l < 16) {
            float r = db[l];
            #pragma unroll 8
            for (int d = 0; d < 128; d++) r += Fs[w*128 + d] * dws[d*16 + l];
            out[(size_t)b*512*64 + (size_t)(f*16 + l)*64 + v] = r*stdv + meanv;
        }
        __syncwarp();
    }
}

// ===== launch =====
extern "C" void kernel_launch(void* const* d_in, const int* in_sizes, int n_in,
                              void* d_out, int out_size) {
    const float* x      = (const float*)d_in[0];
    const float* cent   = (const float*)d_in[1];
    const float* enc_w  = (const float*)d_in[2];
    const float* enc_b  = (const float*)d_in[3];
    const float* ln_w   = (const float*)d_in[4];
    const float* ln_b   = (const float*)d_in[5];
    const float* fc1_w  = (const float*)d_in[6];
    const float* fc1_b  = (const float*)d_in[7];
    const float* fcm_w  = (const float*)d_in[8];
    const float* fcm_b  = (const float*)d_in[9];
    const float* fc2_w  = (const float*)d_in[10];
    const float* fc2_b  = (const float*)d_in[11];
    const float* fuse_w = (const float*)d_in[12];
    const float* fuse_b = (const float*)d_in[13];
    const float* fln_w  = (const float*)d_in[14];
    const float* fln_b  = (const float*)d_in[15];
    const float* dec_w  = (const float*)d_in[16];
    const float* dec_b  = (const float*)d_in[17];

    float* out    = (float*)d_out;
    float* logits = out + (size_t)BB*512*VV;

    int sm4 = (8704 + 17408 + 64 + 5120 + 5120 + 320 + 320)*4;
    int sm5 = (16384 + 4096 + 2048 + 1024) * 4;
    cudaFuncSetAttribute(k_mlp_mma, cudaFuncAttributeMaxDynamicSharedMemorySize, SMEM_MLP);
    cudaFuncSetAttribute(k_vq,      cudaFuncAttributeMaxDynamicSharedMemorySize, sm4);
    cudaFuncSetAttribute(k_fuse,    cudaFuncAttributeMaxDynamicSharedMemorySize, sm5);

    k_revin<<<BB, dim3(64,8)>>>(x);
    k_c2<<<KK/8, 256>>>(cent);
    k_wprep<<<640, 256>>>(fc1_w, fcm_w, fc2_w);
    k_encode<<<BB*VV, 256>>>(x, enc_w, enc_b, ln_w, ln_b);
    k_mlp_mma<<<BB*VV, 256, SMEM_MLP>>>(fc1_b, fcm_b, fc2_b);
    k_vq<<<NVQ/64, 256, sm4>>>(cent, logits);
    k_fuse<<<BB*VV, 256, sm5>>>(fuse_w, fuse_b, fln_w, fln_b, dec_w, dec_b, out);
}

// round 6
// speedup vs baseline: 5.3924x; 1.7741x over previous
#include <cuda_runtime.h>
#include <cuda_bf16.h>
#include <math.h>
#include <stdint.h>

#define BB   32
#define LL   1024
#define VV   64
#define PHn  64
#define PFn  32
#define DD   128
#define KK   1024
#define NVQ  (BB*VV*PFn)
#define NROW (BB*VV*DD)

__device__ float g_mean[BB*VV];
__device__ float g_std[BB*VV];
__device__ float g_xt[(size_t)BB*VV*LL];          // x transposed [b][v][l]
__device__ float g_Zp[(size_t)NVQ*DD];
__device__ float g_Zcode[(size_t)NVQ*DD];
__device__ float g_c2[KK];
__device__ __nv_bfloat16 g_Zpb[(size_t)NVQ*DD];   // bf16 z_p [n][d]
__device__ __nv_bfloat16 g_Cb[(size_t)KK*DD];     // bf16 centroids [k][d]
__device__ __nv_bfloat16 g_Ab[(size_t)NROW*64];   // [bv][d(row)][p(k)]
__device__ __nv_bfloat16 g_W1b[64*256];
__device__ __nv_bfloat16 g_W2b[256*512];
__device__ __nv_bfloat16 g_W3b[512*32];

extern __shared__ char dynsm[];

// ===== helpers =====
__device__ __forceinline__ uint32_t smem_u32(const void* p) {
    uint32_t a;
    asm("{ .reg .u64 t; cvta.to.shared.u64 t, %1; cvt.u32.u64 %0, t; }" : "=r"(a) : "l"(p));
    return a;
}
__device__ __forceinline__ void ldsm4(uint32_t* r, uint32_t a) {
    asm volatile("ldmatrix.sync.aligned.m8n8.x4.shared.b16 {%0,%1,%2,%3}, [%4];"
        : "=r"(r[0]), "=r"(r[1]), "=r"(r[2]), "=r"(r[3]) : "r"(a));
}
__device__ __forceinline__ void ldsm4t(uint32_t* r, uint32_t a) {
    asm volatile("ldmatrix.sync.aligned.m8n8.x4.trans.shared.b16 {%0,%1,%2,%3}, [%4];"
        : "=r"(r[0]), "=r"(r[1]), "=r"(r[2]), "=r"(r[3]) : "r"(a));
}
__device__ __forceinline__ void mma_bf16(float* c, const uint32_t* a, uint32_t b0, uint32_t b1) {
    asm volatile("mma.sync.aligned.m16n8k16.row.col.f32.bf16.bf16.f32 "
        "{%0,%1,%2,%3}, {%4,%5,%6,%7}, {%8,%9}, {%0,%1,%2,%3};"
        : "+f"(c[0]), "+f"(c[1]), "+f"(c[2]), "+f"(c[3])
        : "r"(a[0]), "r"(a[1]), "r"(a[2]), "r"(a[3]), "r"(b0), "r"(b1));
}
__device__ __forceinline__ uint32_t packrelu(float x, float y, float bx, float by) {
    __nv_bfloat162 h = __float22bfloat162_rn(make_float2(fmaxf(x+bx,0.f), fmaxf(y+by,0.f)));
    return *reinterpret_cast<uint32_t*>(&h);
}
__device__ __forceinline__ void top5_ins(float* tv, int* ti, float d, int k) {
    if (d < tv[4]) {
        tv[4] = d; ti[4] = k;
        #pragma unroll
        for (int s = 4; s > 0; s--) {
            if (tv[s] < tv[s-1]) {
                float tf = tv[s]; tv[s] = tv[s-1]; tv[s-1] = tf;
                int tk = ti[s]; ti[s] = ti[s-1]; ti[s-1] = tk;
            }
        }
    }
}

// ===== K0: transpose x -> [b][v][l] =====
__global__ void __launch_bounds__(256) k_xT(const float* __restrict__ x) {
    __shared__ float tile[64][65];
    int b = blockIdx.y, l0 = blockIdx.x*64;
    int t = threadIdx.x;
    for (int i = t; i < 4096; i += 256) {
        int li = i >> 6, v = i & 63;
        tile[li][v] = x[((size_t)b*1024 + l0 + li)*64 + v];
    }
    __syncthreads();
    for (int i = t; i < 4096; i += 256) {
        int v = i >> 6, li = i & 63;
        g_xt[((size_t)b*64 + v)*1024 + l0 + li] = tile[li][v];
    }
}

// ===== K1: RevIN stats (coalesced over xt) =====
__global__ void __launch_bounds__(256) k_revin() {
    int b = blockIdx.x, t = threadIdx.x, w = t >> 5, l = t & 31;
    #pragma unroll
    for (int vi = 0; vi < 8; vi++) {
        int v = vi*8 + w;
        const float* row = g_xt + ((size_t)b*64 + v)*1024;
        float s = 0.f, q = 0.f;
        #pragma unroll 8
        for (int j = 0; j < 32; j++) { float val = row[l + 32*j]; s += val; q += val*val; }
        #pragma unroll
        for (int o = 16; o; o >>= 1) {
            s += __shfl_xor_sync(0xffffffffu, s, o);
            q += __shfl_xor_sync(0xffffffffu, q, o);
        }
        if (l == 0) {
            float mean = s * (1.0f/LL);
            g_mean[b*VV + v] = mean;
            g_std[b*VV + v]  = sqrtf(q*(1.0f/LL) - mean*mean + 1e-5f);
        }
    }
}

// ===== K1b: centroid norms (fp32) + bf16 centroid copy =====
__global__ void k_c2(const float* __restrict__ cent) {
    int w = threadIdx.x >> 5, l = threadIdx.x & 31;
    int k = blockIdx.x * 8 + w;
    const float* cp = cent + (size_t)k*DD;
    float s = 0.f;
    #pragma unroll
    for (int q = 0; q < 4; q++) {
        float c = cp[l + 32*q];
        s += c*c;
        g_Cb[(size_t)k*DD + l + 32*q] = __float2bfloat16(c);
    }
    #pragma unroll
    for (int o = 16; o; o >>= 1) s += __shfl_xor_sync(0xffffffffu, s, o);
    if (l == 0) g_c2[k] = s;
}

// ===== K1c: weight convert to bf16 =====
__global__ void k_wprep(const float* __restrict__ w1, const float* __restrict__ w2,
                        const float* __restrict__ w3) {
    int i = blockIdx.x*256 + threadIdx.x;
    if (i < 16384)        g_W1b[i] = __float2bfloat16(w1[i]);
    else if (i < 147456)  g_W2b[i - 16384] = __float2bfloat16(w2[i - 16384]);
    else if (i < 163840)  g_W3b[i - 147456] = __float2bfloat16(w3[i - 147456]);
}

// ===== K2: encode + LN -> bf16 A [d][p] =====
__global__ void __launch_bounds__(256) k_encode(
    const float* __restrict__ ew, const float* __restrict__ eb,
    const float* __restrict__ lnw, const float* __restrict__ lnb) {
    __shared__ float xv[1024], ws[2048], zt[8192];
    int bv = blockIdx.x, t = threadIdx.x;
    float mean = g_mean[bv], rstd = 1.0f / g_std[bv];
    const float* xp = g_xt + (size_t)bv*1024;
    for (int i = t; i < 1024; i += 256) xv[i] = (xp[i] - mean) * rstd;
    for (int i = t; i < 2048; i += 256) ws[i] = ew[i];
    __syncthreads();
    for (int idx = t; idx < 8192; idx += 256) {
        int p = idx >> 7, d = idx & 127;
        float s = eb[d];
        const float* xq = &xv[p*16];
        #pragma unroll
        for (int i = 0; i < 16; i++) s += xq[i] * ws[i*128 + d];
        zt[idx] = s;
    }
    __syncthreads();
    int w = t >> 5, l = t & 31;
    __nv_bfloat16* Adst = g_Ab + (size_t)bv*8192;
    #pragma unroll
    for (int j = 0; j < 8; j++) {
        int p = w*8 + j;
        float z[4], s = 0.f, q = 0.f;
        #pragma unroll
        for (int qq = 0; qq < 4; qq++) {
            z[qq] = zt[p*128 + l + 32*qq];
            s += z[qq]; q += z[qq]*z[qq];
        }
        #pragma unroll
        for (int o = 16; o; o >>= 1) {
            s += __shfl_xor_sync(0xffffffffu, s, o);
            q += __shfl_xor_sync(0xffffffffu, q, o);
        }
        float mu = s * (1.0f/128.0f);
        float rs = rsqrtf(q*(1.0f/128.0f) - mu*mu + 1e-5f);
        #pragma unroll
        for (int qq = 0; qq < 4; qq++) {
            int d = l + 32*qq;
            Adst[d*64 + p] = __float2bfloat16((z[qq]-mu)*rs*lnw[d] + lnb[d]);
        }
    }
}

// ===== K3: HMMA bf16 fused MLP =====
#define MO_A   0
#define MO_W   18432
#define MO_H1  88064
#define MO_H2  155648
#define MO_W3  190464
#define SMEM_MLP 231424

__device__ __forceinline__ void gemm_tile64(uint32_t Abase, int sA, int m0,
                                            uint32_t Bbase, int sB, int n0,
                                            int ksteps, int l, float acc[8][4]) {
    for (int ks = 0; ks < ksteps; ks++) {
        int kk = ks*16;
        uint32_t av[4];
        ldsm4(av, Abase + (uint32_t)(((m0 + (l&15))*sA + kk + ((l>>4)<<3))*2));
        #pragma unroll
        for (int t = 0; t < 4; t++) {
            uint32_t bvv[4];
            ldsm4t(bvv, Bbase + (uint32_t)(((kk + (l&15))*sB + n0 + t*16 + ((l>>4)<<3))*2));
            mma_bf16(acc[2*t],   av, bvv[0], bvv[1]);
            mma_bf16(acc[2*t+1], av, bvv[2], bvv[3]);
        }
    }
}

__device__ __forceinline__ void epi64(float acc[8][4], char* hdst, int sH, int m0, int n0,
                                      const float* __restrict__ bias, int boff, int l) {
    int row = l >> 2, qc = (l & 3)*2;
    #pragma unroll
    for (int t8 = 0; t8 < 8; t8++) {
        int col = n0 + t8*8 + qc;
        float b0 = __ldg(&bias[boff + col]), b1 = __ldg(&bias[boff + col + 1]);
        *(uint32_t*)(hdst + ((m0+row)*sH + col)*2)   = packrelu(acc[t8][0], acc[t8][1], b0, b1);
        *(uint32_t*)(hdst + ((m0+row+8)*sH + col)*2) = packrelu(acc[t8][2], acc[t8][3], b0, b1);
    }
}

__global__ void __launch_bounds__(256, 1) k_mlp_mma(
    const float* __restrict__ b1g, const float* __restrict__ b2g,
    const float* __restrict__ b3g) {
    char* smem = dynsm;
    uint32_t base = smem_u32(smem);
    int t = threadIdx.x, w = t >> 5, l = t & 31;
    int bv = blockIdx.x;

    {
        const uint4* Ag = reinterpret_cast<const uint4*>(g_Ab) + (size_t)bv*1024;
        for (int i = t; i < 1024; i += 256) {
            int row = i >> 3, q = i & 7;
            *(uint4*)(smem + MO_A + row*144 + q*16) = Ag[i];
        }
        const uint4* W1g = reinterpret_cast<const uint4*>(g_W1b);
        for (int i = t; i < 2048; i += 256) {
            int row = i >> 5, q = i & 31;
            *(uint4*)(smem + MO_W + row*528 + q*16) = W1g[i];
        }
        const uint4* W3g = reinterpret_cast<const uint4*>(g_W3b);
        for (int i = t; i < 2048; i += 256) {
            int row = i >> 2, q = i & 3;
            *(uint4*)(smem + MO_W3 + row*80 + q*16) = W3g[i];
        }
    }
    __syncthreads();

    {
        int m0 = w*16;
        for (int j = 0; j < 4; j++) {
            float acc[8][4];
            #pragma unroll
            for (int i = 0; i < 8; i++)
                #pragma unroll
                for (int jj = 0; jj < 4; jj++) acc[i][jj] = 0.f;
            gemm_tile64(base + MO_A, 72, m0, base + MO_W, 264, j*64, 4, l, acc);
            epi64(acc, smem + MO_H1, 264, m0, j*64, b1g, 0, l);
        }
    }
    __syncthreads();

    float acc3[4][4];
    #pragma unroll
    for (int i = 0; i < 4; i++)
        #pragma unroll
        for (int j = 0; j < 4; j++) acc3[i][j] = 0.f;
    const uint4* W2g = reinterpret_cast<const uint4*>(g_W2b);
    int m0 = w*16;
    for (int c = 0; c < 4; c++) {
        for (int i = t; i < 4096; i += 256) {
            int row = i >> 4, q = i & 15;
            *(uint4*)(smem + MO_W + row*272 + q*16) = W2g[row*64 + c*16 + q];
        }
        __syncthreads();
        for (int j = 0; j < 2; j++) {
            float acc[8][4];
            #pragma unroll
            for (int i = 0; i < 8; i++)
                #pragma unroll
                for (int jj = 0; jj < 4; jj++) acc[i][jj] = 0.f;
            gemm_tile64(base + MO_H1, 264, m0, base + MO_W, 136, j*64, 16, l, acc);
            epi64(acc, smem + MO_H2, 136, m0, j*64, b2g, c*128, l);
        }
        for (int ks = 0; ks < 8; ks++) {
            int kk = ks*16;
            uint32_t av[4];
            ldsm4(av, base + MO_H2 + (uint32_t)(((m0 + (l&15))*136 + kk + ((l>>4)<<3))*2));
            #pragma unroll
            for (int tt = 0; tt < 2; tt++) {
                uint32_t bvv[4];
                ldsm4t(bvv, base + MO_W3 + (uint32_t)(((c*128 + kk + (l&15))*40 + tt*16 + ((l>>4)<<3))*2));
                mma_bf16(acc3[2*tt],   av, bvv[0], bvv[1]);
                mma_bf16(acc3[2*tt+1], av, bvv[2], bvv[3]);
            }
        }
        __syncthreads();
    }

    float* OUT = (float*)(smem + MO_A);
    {
        int row = l >> 2, qc = (l & 3)*2;
        #pragma unroll
        for (int t8 = 0; t8 < 4; t8++) {
            int col = t8*8 + qc;
            float b0 = __ldg(&b3g[col]), b1 = __ldg(&b3g[col+1]);
            OUT[col*132     + m0 + row]     = acc3[t8][0] + b0;
            OUT[(col+1)*132 + m0 + row]     = acc3[t8][1] + b1;
            OUT[col*132     + m0 + row + 8] = acc3[t8][2] + b0;
            OUT[(col+1)*132 + m0 + row + 8] = acc3[t8][3] + b1;
        }
    }
    __syncthreads();
    float* zp = g_Zp + (size_t)bv*4096;
    __nv_bfloat16* zpb = g_Zpb + (size_t)bv*4096;
    for (int i = t; i < 4096; i += 256) {
        int f = i >> 7, r = i & 127;
        float val = OUT[f*132 + r];
        zp[i] = val;
        zpb[i] = __float2bfloat16(val);
    }
}

// ===== K4: HMMA VQ: distances + logits + top5 + softmax gather =====
#define VQ_ZB   0
#define VQ_CB   34816
#define VQ_Z2   69632
#define VQ_C2   70144
#define VQ_CVAL 74240
#define VQ_CIDX 84480
#define VQ_WI   94720
#define SMEM_VQ 99840

__global__ void __launch_bounds__(256) k_vq_mma(const float* __restrict__ cent,
                                                float* __restrict__ logits) {
    char* sm = dynsm;
    uint32_t base = smem_u32(sm);
    int t = threadIdx.x, w = t >> 5, l = t & 31;
    int n0 = blockIdx.x * 128;

    {   // load z tile bf16 (padded rows)
        const uint4* Zg = reinterpret_cast<const uint4*>(g_Zpb) + (size_t)n0*16;
        for (int i = t; i < 2048; i += 256) {
            int row = i >> 4, q = i & 15;
            *(uint4*)(sm + VQ_ZB + row*272 + q*16) = Zg[i];
        }
        float* c2s = (float*)(sm + VQ_C2);
        for (int i = t; i < 1024; i += 256) c2s[i] = g_c2[i];
    }
    {   // z2 exact fp32
        float* z2s = (float*)(sm + VQ_Z2);
        for (int i = 0; i < 16; i++) {
            int r = w*16 + i;
            const float* row = g_Zp + (size_t)(n0 + r)*128;
            float s = 0.f;
            #pragma unroll
            for (int j = 0; j < 4; j++) { float vv = row[l + 32*j]; s += vv*vv; }
            #pragma unroll
            for (int o = 16; o; o >>= 1) s += __shfl_xor_sync(0xffffffffu, s, o);
            if (l == 0) z2s[r] = s;
        }
    }
    __syncthreads();

    int m0 = w*16;
    int r0 = m0 + (l >> 2), r1 = r0 + 8;
    float z2a = ((float*)(sm + VQ_Z2))[r0];
    float z2b = ((float*)(sm + VQ_Z2))[r1];
    const float* c2s = (float*)(sm + VQ_C2);

    float tv0[5], tv1[5]; int ti0[5], ti1[5];
    #pragma unroll
    for (int s = 0; s < 5; s++) { tv0[s] = 3.0e38f; tv1[s] = 3.0e38f; ti0[s] = 0; ti1[s] = 0; }

    const uint4* Cg = reinterpret_cast<const uint4*>(g_Cb);
    for (int ch = 0; ch < 8; ch++) {
        __syncthreads();
        for (int i = t; i < 2048; i += 256) {
            int row = i >> 4, q = i & 15;
            *(uint4*)(sm + VQ_CB + row*272 + q*16) = Cg[ch*2048 + i];
        }
        __syncthreads();
        for (int h = 0; h < 2; h++) {
            float acc[8][4];
            #pragma unroll
            for (int i = 0; i < 8; i++)
                #pragma unroll
                for (int j = 0; j < 4; j++) acc[i][j] = 0.f;
            for (int ks = 0; ks < 8; ks++) {
                int kk = ks*16;
                uint32_t av[4];
                ldsm4(av, base + VQ_ZB + (uint32_t)(((m0 + (l&15))*136 + kk + ((l>>4)<<3))*2));
                #pragma unroll
                for (int tt = 0; tt < 4; tt++) {
                    uint32_t bvv[4];
                    ldsm4(bvv, base + VQ_CB + (uint32_t)(((h*64 + tt*16 + (l&15))*136 + kk + ((l>>4)<<3))*2));
                    mma_bf16(acc[2*tt],   av, bvv[0], bvv[2]);
                    mma_bf16(acc[2*tt+1], av, bvv[1], bvv[3]);
                }
            }
            int cb = ch*128 + h*64;
            #pragma unroll
            for (int a = 0; a < 8; a++) {
                int col = cb + (a>>1)*16 + ((a&1)<<3) + ((l&3)<<1);
                float c20 = c2s[col], c21 = c2s[col+1];
                float d00 = z2a + c20 - 2.0f*acc[a][0];
                float d01 = z2a + c21 - 2.0f*acc[a][1];
                float d10 = z2b + c20 - 2.0f*acc[a][2];
                float d11 = z2b + c21 - 2.0f*acc[a][3];
                *(float2*)(logits + (size_t)(n0+r0)*1024 + col) = make_float2(-d00, -d01);
                *(float2*)(logits + (size_t)(n0+r1)*1024 + col) = make_float2(-d10, -d11);
                top5_ins(tv0, ti0, d00, col); top5_ins(tv0, ti0, d01, col+1);
                top5_ins(tv1, ti1, d10, col); top5_ins(tv1, ti1, d11, col+1);
            }
        }
    }
    __syncthreads();

    {
        float* cval = (float*)(sm + VQ_CVAL);
        int*   cidx = (int*)(sm + VQ_CIDX);
        int own = l & 3;
        #pragma unroll
        for (int s = 0; s < 5; s++) {
            cval[r0*20 + own*5 + s] = tv0[s]; cidx[r0*20 + own*5 + s] = ti0[s];
            cval[r1*20 + own*5 + s] = tv1[s]; cidx[r1*20 + own*5 + s] = ti1[s];
        }
    }
    __syncthreads();
    if (t < 128) {
        float* cval = (float*)(sm + VQ_CVAL);
        int*   cidx = (int*)(sm + VQ_CIDX);
        float mv[5]; int mi[5];
        #pragma unroll
        for (int s = 0; s < 5; s++) { mv[s] = 3.0e38f; mi[s] = 0; }
        for (int c = 0; c < 20; c++) top5_ins(mv, mi, cval[t*20 + c], cidx[t*20 + c]);
        float m0v = mv[0];
        float wv[5]; float wsum = 0.f;
        #pragma unroll
        for (int j = 0; j < 5; j++) { wv[j] = expf(m0v - mv[j]); wsum += wv[j]; }
        float inv = 1.0f / wsum;
        float* wsm = (float*)(sm + VQ_WI);
        int*   ism = (int*)(sm + VQ_WI + 2560);
        #pragma unroll
        for (int j = 0; j < 5; j++) { wsm[t*5 + j] = wv[j]*inv; ism[t*5 + j] = mi[j]; }
    }
    __syncthreads();

    {
        float* wsm = (float*)(sm + VQ_WI);
        int*   ism = (int*)(sm + VQ_WI + 2560);
        for (int r = w; r < 128; r += 8) {
            float wg[5]; int id[5];
            #pragma unroll
            for (int j = 0; j < 5; j++) { wg[j] = wsm[r*5 + j]; id[j] = ism[r*5 + j]; }
            int dbase = l*4;
            float4 o = make_float4(0.f,0.f,0.f,0.f);
            #pragma unroll
            for (int j = 0; j < 5; j++) {
                float4 cv = *(const float4*)&cent[(size_t)id[j]*128 + dbase];
                o.x += wg[j]*cv.x; o.y += wg[j]*cv.y;
                o.z += wg[j]*cv.z; o.w += wg[j]*cv.w;
            }
            *(float4*)&g_Zcode[(size_t)(n0+r)*128 + dbase] = o;
        }
    }
}

// ===== K5: residual fusion + LN + decode + denorm =====
__global__ void __launch_bounds__(256) k_fuse(
    const float* __restrict__ fw, const float* __restrict__ fb,
    const float* __restrict__ flnw, const float* __restrict__ flnb,
    const float* __restrict__ dw, const float* __restrict__ db,
    float* __restrict__ out) {
    float* sm = (float*)dynsm;
    float* Ws  = sm;
    float* Zps = Ws + 16384;
    float* dws = Zps + 4096;
    float* Fs  = dws + 2048;
    int t = threadIdx.x;
    int bv = blockIdx.x;
    int b = bv >> 6, v = bv & 63;
    for (int i = t; i < 16384; i += 256) Ws[i] = fw[i];
    for (int i = t; i < 4096; i += 256) Zps[i] = g_Zp[(size_t)bv*4096 + i];
    for (int i = t; i < 2048; i += 256) dws[i] = dw[i];
    __syncthreads();
    int w = t >> 5, l = t & 31;
    float stdv = g_std[bv], meanv = g_mean[bv];
    for (int f = w; f < 32; f += 8) {
        float acc4[4];
        #pragma unroll
        for (int q = 0; q < 4; q++) acc4[q] = fb[l + 32*q];
        const float* zrow = &Zps[f*128];
        for (int e = 0; e < 128; e++) {
            float z = zrow[e];
            const float* wr = &Ws[e*128];
            #pragma unroll
            for (int q = 0; q < 4; q++) acc4[q] += z * wr[l + 32*q];
        }
        size_t nrow = (size_t)(bv*32 + f)*128;
        float s = 0.f, qq = 0.f;
        #pragma unroll
        for (int q = 0; q < 4; q++) {
            float val = fmaxf(acc4[q], 0.f) + g_Zcode[nrow + l + 32*q];
            acc4[q] = val;
            s += val; qq += val*val;
        }
        #pragma unroll
        for (int o = 16; o; o >>= 1) {
            s  += __shfl_xor_sync(0xffffffffu, s,  o);
            qq += __shfl_xor_sync(0xffffffffu, qq, o);
        }
        float mu = s * (1.0f/128.0f);
        float rs = rsqrtf(qq*(1.0f/128.0f) - mu*mu + 1e-5f);
        #pragma unroll
        for (int q = 0; q < 4; q++) {
            int d = l + 32*q;
            Fs[w*128 + d] = (acc4[q]-mu)*rs*flnw[d] + flnb[d];
        }
        __syncwarp();
        if (l < 16) {
            float r = db[l];
            #pragma unroll 8
            for (int d = 0; d < 128; d++) r += Fs[w*128 + d] * dws[d*16 + l];
            out[(size_t)b*512*64 + (size_t)(f*16 + l)*64 + v] = r*stdv + meanv;
        }
        __syncwarp();
    }
}

// ===== launch =====
extern "C" void kernel_launch(void* const* d_in, const int* in_sizes, int n_in,
                              void* d_out, int out_size) {
    const float* x      = (const float*)d_in[0];
    const float* cent   = (const float*)d_in[1];
    const float* enc_w  = (const float*)d_in[2];
    const float* enc_b  = (const float*)d_in[3];
    const float* ln_w   = (const float*)d_in[4];
    const float* ln_b   = (const float*)d_in[5];
    const float* fc1_w  = (const float*)d_in[6];
    const float* fc1_b  = (const float*)d_in[7];
    const float* fcm_w  = (const float*)d_in[8];
    const float* fcm_b  = (const float*)d_in[9];
    const float* fc2_w  = (const float*)d_in[10];
    const float* fc2_b  = (const float*)d_in[11];
    const float* fuse_w = (const float*)d_in[12];
    const float* fuse_b = (const float*)d_in[13];
    const float* fln_w  = (const float*)d_in[14];
    const float* fln_b  = (const float*)d_in[15];
    const float* dec_w  = (const float*)d_in[16];
    const float* dec_b  = (const float*)d_in[17];

    float* out    = (float*)d_out;
    float* logits = out + (size_t)BB*512*VV;

    int sm5 = (16384 + 4096 + 2048 + 1024) * 4;
    cudaFuncSetAttribute(k_mlp_mma, cudaFuncAttributeMaxDynamicSharedMemorySize, SMEM_MLP);
    cudaFuncSetAttribute(k_vq_mma,  cudaFuncAttributeMaxDynamicSharedMemorySize, SMEM_VQ);
    cudaFuncSetAttribute(k_fuse,    cudaFuncAttributeMaxDynamicSharedMemorySize, sm5);

    k_xT<<<dim3(16, 32), 256>>>(x);
    k_revin<<<BB, 256>>>();
    k_c2<<<KK/8, 256>>>(cent);
    k_wprep<<<640, 256>>>(fc1_w, fcm_w, fc2_w);
    k_encode<<<BB*VV, 256>>>(enc_w, enc_b, ln_w, ln_b);
    k_mlp_mma<<<BB*VV, 256, SMEM_MLP>>>(fc1_b, fcm_b, fc2_b);
    k_vq_mma<<<NVQ/128, 256, SMEM_VQ>>>(cent, logits);
    k_fuse<<<BB*VV, 256, sm5>>>(fuse_w, fuse_b, fln_w, fln_b, dec_w, dec_b, out);
}

// round 7
// speedup vs baseline: 6.8354x; 1.2676x over previous
#include <cuda_runtime.h>
#include <cuda_bf16.h>
#include <math.h>
#include <stdint.h>

#define BB   32
#define LL   1024
#define VV   64
#define PHn  64
#define PFn  32
#define DD   128
#define KK   1024
#define NVQ  (BB*VV*PFn)
#define NROW (BB*VV*DD)

__device__ float g_mean[BB*VV];
__device__ float g_std[BB*VV];
__device__ float g_xt[(size_t)BB*VV*LL];          // x transposed [b][v][l]
__device__ float g_Zp[(size_t)NVQ*DD];
__device__ float g_Zcode[(size_t)NVQ*DD];
__device__ float g_c2[KK];
__device__ __nv_bfloat16 g_Zpb[(size_t)NVQ*DD];   // bf16 z_p [n][d]
__device__ __nv_bfloat16 g_Cb[(size_t)KK*DD];     // bf16 centroids [k][d]
__device__ __nv_bfloat16 g_Ab[(size_t)NROW*64];   // [bv][d(row)][p(k)]
__device__ __nv_bfloat16 g_W1b[64*256];
__device__ __nv_bfloat16 g_W2b[256*512];
__device__ __nv_bfloat16 g_W3b[512*32];
__device__ __nv_bfloat16 g_Fwb[128*128];          // bf16 fuse_w [k][n]

extern __shared__ char dynsm[];

// ===== helpers =====
__device__ __forceinline__ uint32_t smem_u32(const void* p) {
    uint32_t a;
    asm("{ .reg .u64 t; cvta.to.shared.u64 t, %1; cvt.u32.u64 %0, t; }" : "=r"(a) : "l"(p));
    return a;
}
__device__ __forceinline__ void ldsm4(uint32_t* r, uint32_t a) {
    asm volatile("ldmatrix.sync.aligned.m8n8.x4.shared.b16 {%0,%1,%2,%3}, [%4];"
        : "=r"(r[0]), "=r"(r[1]), "=r"(r[2]), "=r"(r[3]) : "r"(a));
}
__device__ __forceinline__ void ldsm4t(uint32_t* r, uint32_t a) {
    asm volatile("ldmatrix.sync.aligned.m8n8.x4.trans.shared.b16 {%0,%1,%2,%3}, [%4];"
        : "=r"(r[0]), "=r"(r[1]), "=r"(r[2]), "=r"(r[3]) : "r"(a));
}
__device__ __forceinline__ void mma_bf16(float* c, const uint32_t* a, uint32_t b0, uint32_t b1) {
    asm volatile("mma.sync.aligned.m16n8k16.row.col.f32.bf16.bf16.f32 "
        "{%0,%1,%2,%3}, {%4,%5,%6,%7}, {%8,%9}, {%0,%1,%2,%3};"
        : "+f"(c[0]), "+f"(c[1]), "+f"(c[2]), "+f"(c[3])
        : "r"(a[0]), "r"(a[1]), "r"(a[2]), "r"(a[3]), "r"(b0), "r"(b1));
}
__device__ __forceinline__ uint32_t packrelu(float x, float y, float bx, float by) {
    __nv_bfloat162 h = __float22bfloat162_rn(make_float2(fmaxf(x+bx,0.f), fmaxf(y+by,0.f)));
    return *reinterpret_cast<uint32_t*>(&h);
}
__device__ __forceinline__ void top5_ins(float* tv, int* ti, float d, int k) {
    if (d < tv[4]) {
        tv[4] = d; ti[4] = k;
        #pragma unroll
        for (int s = 4; s > 0; s--) {
            if (tv[s] < tv[s-1]) {
                float tf = tv[s]; tv[s] = tv[s-1]; tv[s-1] = tf;
                int tk = ti[s]; ti[s] = ti[s-1]; ti[s-1] = tk;
            }
        }
    }
}
#define CP_ASYNC16(dst, src) \
    asm volatile("cp.async.cg.shared.global [%0], [%1], 16;" :: "r"(dst), "l"(src))
#define CP_COMMIT() asm volatile("cp.async.commit_group;" ::: "memory")
#define CP_WAIT1()  asm volatile("cp.async.wait_group 1;" ::: "memory")
#define CP_WAIT0()  asm volatile("cp.async.wait_group 0;" ::: "memory")

// ===== K0: transpose x -> [b][v][l] =====
__global__ void __launch_bounds__(256) k_xT(const float* __restrict__ x) {
    __shared__ float tile[64][65];
    int b = blockIdx.y, l0 = blockIdx.x*64;
    int t = threadIdx.x;
    for (int i = t; i < 4096; i += 256) {
        int li = i >> 6, v = i & 63;
        tile[li][v] = x[((size_t)b*1024 + l0 + li)*64 + v];
    }
    __syncthreads();
    for (int i = t; i < 4096; i += 256) {
        int v = i >> 6, li = i & 63;
        g_xt[((size_t)b*64 + v)*1024 + l0 + li] = tile[li][v];
    }
}

// ===== K1: RevIN stats =====
__global__ void __launch_bounds__(256) k_revin() {
    int b = blockIdx.x, t = threadIdx.x, w = t >> 5, l = t & 31;
    #pragma unroll
    for (int vi = 0; vi < 8; vi++) {
        int v = vi*8 + w;
        const float* row = g_xt + ((size_t)b*64 + v)*1024;
        float s = 0.f, q = 0.f;
        #pragma unroll 8
        for (int j = 0; j < 32; j++) { float val = row[l + 32*j]; s += val; q += val*val; }
        #pragma unroll
        for (int o = 16; o; o >>= 1) {
            s += __shfl_xor_sync(0xffffffffu, s, o);
            q += __shfl_xor_sync(0xffffffffu, q, o);
        }
        if (l == 0) {
            float mean = s * (1.0f/LL);
            g_mean[b*VV + v] = mean;
            g_std[b*VV + v]  = sqrtf(q*(1.0f/LL) - mean*mean + 1e-5f);
        }
    }
}

// ===== K1b: centroid norms + bf16 copy =====
__global__ void k_c2(const float* __restrict__ cent) {
    int w = threadIdx.x >> 5, l = threadIdx.x & 31;
    int k = blockIdx.x * 8 + w;
    const float* cp = cent + (size_t)k*DD;
    float s = 0.f;
    #pragma unroll
    for (int q = 0; q < 4; q++) {
        float c = cp[l + 32*q];
        s += c*c;
        g_Cb[(size_t)k*DD + l + 32*q] = __float2bfloat16(c);
    }
    #pragma unroll
    for (int o = 16; o; o >>= 1) s += __shfl_xor_sync(0xffffffffu, s, o);
    if (l == 0) g_c2[k] = s;
}

// ===== K1c: weight convert to bf16 =====
__global__ void k_wprep(const float* __restrict__ w1, const float* __restrict__ w2,
                        const float* __restrict__ w3, const float* __restrict__ fw) {
    int i = blockIdx.x*256 + threadIdx.x;
    if (i < 16384)        g_W1b[i] = __float2bfloat16(w1[i]);
    else if (i < 147456)  g_W2b[i - 16384] = __float2bfloat16(w2[i - 16384]);
    else if (i < 163840)  g_W3b[i - 147456] = __float2bfloat16(w3[i - 147456]);
    else if (i < 180224)  g_Fwb[i - 163840] = __float2bfloat16(fw[i - 163840]);
}

// ===== K2: encode + LN -> bf16 A [d][p] =====
__global__ void __launch_bounds__(256) k_encode(
    const float* __restrict__ ew, const float* __restrict__ eb,
    const float* __restrict__ lnw, const float* __restrict__ lnb) {
    __shared__ float xv[1024], ws[2048], zt[8192];
    int bv = blockIdx.x, t = threadIdx.x;
    float mean = g_mean[bv], rstd = 1.0f / g_std[bv];
    const float* xp = g_xt + (size_t)bv*1024;
    for (int i = t; i < 1024; i += 256) xv[i] = (xp[i] - mean) * rstd;
    for (int i = t; i < 2048; i += 256) ws[i] = ew[i];
    __syncthreads();
    for (int idx = t; idx < 8192; idx += 256) {
        int p = idx >> 7, d = idx & 127;
        float s = eb[d];
        const float* xq = &xv[p*16];
        #pragma unroll
        for (int i = 0; i < 16; i++) s += xq[i] * ws[i*128 + d];
        zt[idx] = s;
    }
    __syncthreads();
    int w = t >> 5, l = t & 31;
    __nv_bfloat16* Adst = g_Ab + (size_t)bv*8192;
    #pragma unroll
    for (int j = 0; j < 8; j++) {
        int p = w*8 + j;
        float z[4], s = 0.f, q = 0.f;
        #pragma unroll
        for (int qq = 0; qq < 4; qq++) {
            z[qq] = zt[p*128 + l + 32*qq];
            s += z[qq]; q += z[qq]*z[qq];
        }
        #pragma unroll
        for (int o = 16; o; o >>= 1) {
            s += __shfl_xor_sync(0xffffffffu, s, o);
            q += __shfl_xor_sync(0xffffffffu, q, o);
        }
        float mu = s * (1.0f/128.0f);
        float rs = rsqrtf(q*(1.0f/128.0f) - mu*mu + 1e-5f);
        #pragma unroll
        for (int qq = 0; qq < 4; qq++) {
            int d = l + 32*qq;
            Adst[d*64 + p] = __float2bfloat16((z[qq]-mu)*rs*lnw[d] + lnb[d]);
        }
    }
}

// ===== K3: HMMA bf16 fused MLP with cp.async W2 pipeline =====
// A   [128][72]b16 @ 0        (18432)  -> reused as f32 OUT[32][132]
// W   2x half-buffers [256][72]b16 @ 18432 (36864 each, 73728 total; W1 in buf0 for stage1)
// H1  [128][264]b16 @ 92160   (67584)
// H2  [128][72]b16  @ 159744  (18432)
// W3  [512][40]b16  @ 178176  (40960)  total 219136
#define MO_A   0
#define MO_W   18432
#define MO_H1  92160
#define MO_H2  159744
#define MO_W3  178176
#define SMEM_MLP 219136
#define W_HALF 36864

__device__ __forceinline__ void gemm_tile64(uint32_t Abase, int sA, int m0,
                                            uint32_t Bbase, int sB, int n0,
                                            int ksteps, int l, float acc[8][4]) {
    for (int ks = 0; ks < ksteps; ks++) {
        int kk = ks*16;
        uint32_t av[4];
        ldsm4(av, Abase + (uint32_t)(((m0 + (l&15))*sA + kk + ((l>>4)<<3))*2));
        #pragma unroll
        for (int t = 0; t < 4; t++) {
            uint32_t bvv[4];
            ldsm4t(bvv, Bbase + (uint32_t)(((kk + (l&15))*sB + n0 + t*16 + ((l>>4)<<3))*2));
            mma_bf16(acc[2*t],   av, bvv[0], bvv[1]);
            mma_bf16(acc[2*t+1], av, bvv[2], bvv[3]);
        }
    }
}

__device__ __forceinline__ void epi64(float acc[8][4], char* hdst, int sH, int m0, int n0,
                                      const float* __restrict__ bias, int boff, int l) {
    int row = l >> 2, qc = (l & 3)*2;
    #pragma unroll
    for (int t8 = 0; t8 < 8; t8++) {
        int col = n0 + t8*8 + qc;
        float b0 = __ldg(&bias[boff + col]), b1 = __ldg(&bias[boff + col + 1]);
        *(uint32_t*)(hdst + ((m0+row)*sH + col)*2)   = packrelu(acc[t8][0], acc[t8][1], b0, b1);
        *(uint32_t*)(hdst + ((m0+row+8)*sH + col)*2) = packrelu(acc[t8][2], acc[t8][3], b0, b1);
    }
}

// issue cp.async for W2 half hc into buffer hb
__device__ __forceinline__ void issue_w2_half(uint32_t base, int hc, int hb, int t) {
    const uint4* W2g = reinterpret_cast<const uint4*>(g_W2b);
    #pragma unroll
    for (int rep = 0; rep < 8; rep++) {
        int i = t + rep*256;                 // 2048 uint4 total
        int row = i >> 3, q = i & 7;
        uint32_t dst = base + MO_W + hb*W_HALF + row*144 + q*16;
        CP_ASYNC16(dst, (const void*)(W2g + row*64 + hc*8 + q));
    }
    CP_COMMIT();
}

__global__ void __launch_bounds__(256, 1) k_mlp_mma(
    const float* __restrict__ b1g, const float* __restrict__ b2g,
    const float* __restrict__ b3g) {
    char* smem = dynsm;
    uint32_t base = smem_u32(smem);
    int t = threadIdx.x, w = t >> 5, l = t & 31;
    int bv = blockIdx.x;

    {   // load A, W1 (into buf0), W3
        const uint4* Ag = reinterpret_cast<const uint4*>(g_Ab) + (size_t)bv*1024;
        for (int i = t; i < 1024; i += 256) {
            int row = i >> 3, q = i & 7;
            *(uint4*)(smem + MO_A + row*144 + q*16) = Ag[i];
        }
        const uint4* W1g = reinterpret_cast<const uint4*>(g_W1b);
        for (int i = t; i < 2048; i += 256) {
            int row = i >> 5, q = i & 31;
            *(uint4*)(smem + MO_W + row*528 + q*16) = W1g[i];
        }
        const uint4* W3g = reinterpret_cast<const uint4*>(g_W3b);
        for (int i = t; i < 2048; i += 256) {
            int row = i >> 2, q = i & 3;
            *(uint4*)(smem + MO_W3 + row*80 + q*16) = W3g[i];
        }
    }
    __syncthreads();

    // stage 1: H1[128,256] = relu(A @ W1 + b1)
    int m0 = w*16;
    for (int j = 0; j < 4; j++) {
        float acc[8][4];
        #pragma unroll
        for (int i = 0; i < 8; i++)
            #pragma unroll
            for (int jj = 0; jj < 4; jj++) acc[i][jj] = 0.f;
        gemm_tile64(base + MO_A, 72, m0, base + MO_W, 264, j*64, 4, l, acc);
        epi64(acc, smem + MO_H1, 264, m0, j*64, b1g, 0, l);
    }
    __syncthreads();

    // stages 2+3: 8 pipelined 64-col halves of W2
    float acc3[4][4];
    #pragma unroll
    for (int i = 0; i < 4; i++)
        #pragma unroll
        for (int j = 0; j < 4; j++) acc3[i][j] = 0.f;

    issue_w2_half(base, 0, 0, t);
    for (int hc = 0; hc < 8; hc++) {
        if (hc < 7) { issue_w2_half(base, hc+1, (hc+1)&1, t); CP_WAIT1(); }
        else        { CP_WAIT0(); }
        __syncthreads();
        // stage 2: H2half[128,64] = relu(H1 @ W2half + b2)
        {
            float acc[8][4];
            #pragma unroll
            for (int i = 0; i < 8; i++)
                #pragma unroll
                for (int jj = 0; jj < 4; jj++) acc[i][jj] = 0.f;
            gemm_tile64(base + MO_H1, 264, m0, base + MO_W + (hc&1)*W_HALF, 72, 0, 16, l, acc);
            epi64(acc, smem + MO_H2, 72, m0, 0, b2g, hc*64, l);
        }
        __syncwarp();
        // stage 3 partial: OUT += H2half @ W3[hc*64:hc*64+64]
        for (int ks = 0; ks < 4; ks++) {
            int kk = ks*16;
            uint32_t av[4];
            ldsm4(av, base + MO_H2 + (uint32_t)(((m0 + (l&15))*72 + kk + ((l>>4)<<3))*2));
            #pragma unroll
            for (int tt = 0; tt < 2; tt++) {
                uint32_t bvv[4];
                ldsm4t(bvv, base + MO_W3 + (uint32_t)(((hc*64 + kk + (l&15))*40 + tt*16 + ((l>>4)<<3))*2));
                mma_bf16(acc3[2*tt],   av, bvv[0], bvv[1]);
                mma_bf16(acc3[2*tt+1], av, bvv[2], bvv[3]);
            }
        }
        __syncthreads();
    }

    // final epilogue: +b3, transpose via smem, write z_p [f][d] (fp32 + bf16)
    float* OUT = (float*)(smem + MO_A);
    {
        int row = l >> 2, qc = (l & 3)*2;
        #pragma unroll
        for (int t8 = 0; t8 < 4; t8++) {
            int col = t8*8 + qc;
            float b0 = __ldg(&b3g[col]), b1 = __ldg(&b3g[col+1]);
            OUT[col*132     + m0 + row]     = acc3[t8][0] + b0;
            OUT[(col+1)*132 + m0 + row]     = acc3[t8][1] + b1;
            OUT[col*132     + m0 + row + 8] = acc3[t8][2] + b0;
            OUT[(col+1)*132 + m0 + row + 8] = acc3[t8][3] + b1;
        }
    }
    __syncthreads();
    float* zp = g_Zp + (size_t)bv*4096;
    __nv_bfloat16* zpb = g_Zpb + (size_t)bv*4096;
    for (int i = t; i < 4096; i += 256) {
        int f = i >> 7, r = i & 127;
        float val = OUT[f*132 + r];
        zp[i] = val;
        zpb[i] = __float2bfloat16(val);
    }
}

// ===== K4: HMMA VQ =====
#define VQ_ZB   0
#define VQ_CB   34816
#define VQ_Z2   69632
#define VQ_C2   70144
#define VQ_CVAL 74240
#define VQ_CIDX 84480
#define VQ_WI   94720
#define SMEM_VQ 99840

__global__ void __launch_bounds__(256) k_vq_mma(const float* __restrict__ cent,
                                                float* __restrict__ logits) {
    char* sm = dynsm;
    uint32_t base = smem_u32(sm);
    int t = threadIdx.x, w = t >> 5, l = t & 31;
    int n0 = blockIdx.x * 128;

    {
        const uint4* Zg = reinterpret_cast<const uint4*>(g_Zpb) + (size_t)n0*16;
        for (int i = t; i < 2048; i += 256) {
            int row = i >> 4, q = i & 15;
            *(uint4*)(sm + VQ_ZB + row*272 + q*16) = Zg[i];
        }
        float* c2s = (float*)(sm + VQ_C2);
        for (int i = t; i < 1024; i += 256) c2s[i] = g_c2[i];
    }
    {
        float* z2s = (float*)(sm + VQ_Z2);
        for (int i = 0; i < 16; i++) {
            int r = w*16 + i;
            const float* row = g_Zp + (size_t)(n0 + r)*128;
            float s = 0.f;
            #pragma unroll
            for (int j = 0; j < 4; j++) { float vv = row[l + 32*j]; s += vv*vv; }
            #pragma unroll
            for (int o = 16; o; o >>= 1) s += __shfl_xor_sync(0xffffffffu, s, o);
            if (l == 0) z2s[r] = s;
        }
    }
    __syncthreads();

    int m0 = w*16;
    int r0 = m0 + (l >> 2), r1 = r0 + 8;
    float z2a = ((float*)(sm + VQ_Z2))[r0];
    float z2b = ((float*)(sm + VQ_Z2))[r1];
    const float* c2s = (float*)(sm + VQ_C2);

    float tv0[5], tv1[5]; int ti0[5], ti1[5];
    #pragma unroll
    for (int s = 0; s < 5; s++) { tv0[s] = 3.0e38f; tv1[s] = 3.0e38f; ti0[s] = 0; ti1[s] = 0; }

    const uint4* Cg = reinterpret_cast<const uint4*>(g_Cb);
    for (int ch = 0; ch < 8; ch++) {
        __syncthreads();
        for (int i = t; i < 2048; i += 256) {
            int row = i >> 4, q = i & 15;
            *(uint4*)(sm + VQ_CB + row*272 + q*16) = Cg[ch*2048 + i];
        }
        __syncthreads();
        for (int h = 0; h < 2; h++) {
            float acc[8][4];
            #pragma unroll
            for (int i = 0; i < 8; i++)
                #pragma unroll
                for (int j = 0; j < 4; j++) acc[i][j] = 0.f;
            for (int ks = 0; ks < 8; ks++) {
                int kk = ks*16;
                uint32_t av[4];
                ldsm4(av, base + VQ_ZB + (uint32_t)(((m0 + (l&15))*136 + kk + ((l>>4)<<3))*2));
                #pragma unroll
                for (int tt = 0; tt < 4; tt++) {
                    uint32_t bvv[4];
                    ldsm4(bvv, base + VQ_CB + (uint32_t)(((h*64 + tt*16 + (l&15))*136 + kk + ((l>>4)<<3))*2));
                    mma_bf16(acc[2*tt],   av, bvv[0], bvv[2]);
                    mma_bf16(acc[2*tt+1], av, bvv[1], bvv[3]);
                }
            }
            int cb = ch*128 + h*64;
            #pragma unroll
            for (int a = 0; a < 8; a++) {
                int col = cb + (a>>1)*16 + ((a&1)<<3) + ((l&3)<<1);
                float c20 = c2s[col], c21 = c2s[col+1];
                float d00 = z2a + c20 - 2.0f*acc[a][0];
                float d01 = z2a + c21 - 2.0f*acc[a][1];
                float d10 = z2b + c20 - 2.0f*acc[a][2];
                float d11 = z2b + c21 - 2.0f*acc[a][3];
                *(float2*)(logits + (size_t)(n0+r0)*1024 + col) = make_float2(-d00, -d01);
                *(float2*)(logits + (size_t)(n0+r1)*1024 + col) = make_float2(-d10, -d11);
                top5_ins(tv0, ti0, d00, col); top5_ins(tv0, ti0, d01, col+1);
                top5_ins(tv1, ti1, d10, col); top5_ins(tv1, ti1, d11, col+1);
            }
        }
    }
    __syncthreads();

    {
        float* cval = (float*)(sm + VQ_CVAL);
        int*   cidx = (int*)(sm + VQ_CIDX);
        int own = l & 3;
        #pragma unroll
        for (int s = 0; s < 5; s++) {
            cval[r0*20 + own*5 + s] = tv0[s]; cidx[r0*20 + own*5 + s] = ti0[s];
            cval[r1*20 + own*5 + s] = tv1[s]; cidx[r1*20 + own*5 + s] = ti1[s];
        }
    }
    __syncthreads();
    if (t < 128) {
        float* cval = (float*)(sm + VQ_CVAL);
        int*   cidx = (int*)(sm + VQ_CIDX);
        float mv[5]; int mi[5];
        #pragma unroll
        for (int s = 0; s < 5; s++) { mv[s] = 3.0e38f; mi[s] = 0; }
        for (int c = 0; c < 20; c++) top5_ins(mv, mi, cval[t*20 + c], cidx[t*20 + c]);
        float m0v = mv[0];
        float wv[5]; float wsum = 0.f;
        #pragma unroll
        for (int j = 0; j < 5; j++) { wv[j] = expf(m0v - mv[j]); wsum += wv[j]; }
        float inv = 1.0f / wsum;
        float* wsm = (float*)(sm + VQ_WI);
        int*   ism = (int*)(sm + VQ_WI + 2560);
        #pragma unroll
        for (int j = 0; j < 5; j++) { wsm[t*5 + j] = wv[j]*inv; ism[t*5 + j] = mi[j]; }
    }
    __syncthreads();

    {
        float* wsm = (float*)(sm + VQ_WI);
        int*   ism = (int*)(sm + VQ_WI + 2560);
        for (int r = w; r < 128; r += 8) {
            float wg[5]; int id[5];
            #pragma unroll
            for (int j = 0; j < 5; j++) { wg[j] = wsm[r*5 + j]; id[j] = ism[r*5 + j]; }
            int dbase = l*4;
            float4 o = make_float4(0.f,0.f,0.f,0.f);
            #pragma unroll
            for (int j = 0; j < 5; j++) {
                float4 cv = *(const float4*)&cent[(size_t)id[j]*128 + dbase];
                o.x += wg[j]*cv.x; o.y += wg[j]*cv.y;
                o.z += wg[j]*cv.z; o.w += wg[j]*cv.w;
            }
            *(float4*)&g_Zcode[(size_t)(n0+r)*128 + dbase] = o;
        }
    }
}

// ===== K5: HMMA fuse + LN + decode + denorm =====
// Zb [32][136]b16 @0 (8704) | Fw [128][136]b16 @8704 (34816)
// F f32 [32][132] @43520 (16896) | dwT f32 [16][132] @60416 (8448)
#define FO_ZB 0
#define FO_FW 8704
#define FO_F  43520
#define FO_DW 60416
#define SMEM_FUSE 68864

__global__ void __launch_bounds__(256) k_fuse_mma(
    const float* __restrict__ fb, const float* __restrict__ flnw,
    const float* __restrict__ flnb, const float* __restrict__ dwg,
    const float* __restrict__ db, float* __restrict__ out) {
    char* sm = dynsm;
    uint32_t base = smem_u32(sm);
    int t = threadIdx.x, w = t >> 5, l = t & 31;
    int bv = blockIdx.x;
    int b = bv >> 6, v = bv & 63;

    {
        const uint4* Zg = reinterpret_cast<const uint4*>(g_Zpb) + (size_t)bv*512;
        for (int i = t; i < 512; i += 256) {
            int row = i >> 4, q = i & 15;
            *(uint4*)(sm + FO_ZB + row*272 + q*16) = Zg[i];
        }
        const uint4* Fg = reinterpret_cast<const uint4*>(g_Fwb);
        for (int i = t; i < 2048; i += 256) {
            int row = i >> 4, q = i & 15;
            *(uint4*)(sm + FO_FW + row*272 + q*16) = Fg[i];
        }
        float* dwT = (float*)(sm + FO_DW);
        for (int i = t; i < 2048; i += 256) {
            int d = i >> 4, pl = i & 15;
            dwT[pl*132 + d] = dwg[i];
        }
    }
    __syncthreads();

    // MMA: warp w covers m0=(w&1)*16 rows, nb=(w>>1)*32 cols
    int m0 = (w & 1) * 16, nb = (w >> 1) * 32;
    float acc[4][4];
    #pragma unroll
    for (int i = 0; i < 4; i++)
        #pragma unroll
        for (int j = 0; j < 4; j++) acc[i][j] = 0.f;
    for (int ks = 0; ks < 8; ks++) {
        int kk = ks*16;
        uint32_t av[4];
        ldsm4(av, base + FO_ZB + (uint32_t)(((m0 + (l&15))*136 + kk + ((l>>4)<<3))*2));
        #pragma unroll
        for (int tt = 0; tt < 2; tt++) {
            uint32_t bvv[4];
            ldsm4t(bvv, base + FO_FW + (uint32_t)(((kk + (l&15))*136 + nb + tt*16 + ((l>>4)<<3))*2));
            mma_bf16(acc[2*tt],   av, bvv[0], bvv[1]);
            mma_bf16(acc[2*tt+1], av, bvv[2], bvv[3]);
        }
    }
    // epilogue: + fuse_b, relu, + z_code -> F (pre-LN)
    {
        float* F = (float*)(sm + FO_F);
        int r0 = m0 + (l >> 2), r1 = r0 + 8;
        const float* zc0 = g_Zcode + ((size_t)bv*32 + r0)*128;
        const float* zc1 = g_Zcode + ((size_t)bv*32 + r1)*128;
        #pragma unroll
        for (int t8 = 0; t8 < 4; t8++) {
            int col = nb + t8*8 + (l&3)*2;
            float b0 = __ldg(&fb[col]), b1 = __ldg(&fb[col+1]);
            float2 z0 = *(const float2*)(zc0 + col);
            float2 z1 = *(const float2*)(zc1 + col);
            F[r0*132 + col]     = fmaxf(acc[t8][0] + b0, 0.f) + z0.x;
            F[r0*132 + col + 1] = fmaxf(acc[t8][1] + b1, 0.f) + z0.y;
            F[r1*132 + col]     = fmaxf(acc[t8][2] + b0, 0.f) + z1.x;
            F[r1*132 + col + 1] = fmaxf(acc[t8][3] + b1, 0.f) + z1.y;
        }
    }
    __syncthreads();
    // LN per row (warp w: rows w*4..w*4+3)
    {
        float* F = (float*)(sm + FO_F);
        #pragma unroll
        for (int rr = 0; rr < 4; rr++) {
            int r = w*4 + rr;
            float vals[4], s = 0.f, q = 0.f;
            #pragma unroll
            for (int j = 0; j < 4; j++) {
                vals[j] = F[r*132 + l + 32*j];
                s += vals[j]; q += vals[j]*vals[j];
            }
            #pragma unroll
            for (int o = 16; o; o >>= 1) {
                s += __shfl_xor_sync(0xffffffffu, s, o);
                q += __shfl_xor_sync(0xffffffffu, q, o);
            }
            float mu = s * (1.0f/128.0f);
            float rs = rsqrtf(q*(1.0f/128.0f) - mu*mu + 1e-5f);
            #pragma unroll
            for (int j = 0; j < 4; j++) {
                int d = l + 32*j;
                F[r*132 + d] = (vals[j]-mu)*rs*__ldg(&flnw[d]) + __ldg(&flnb[d]);
            }
        }
    }
    __syncthreads();
    // decode: thread -> (f, 2 pl outputs)
    {
        const float* F = (float*)(sm + FO_F);
        const float* dwT = (float*)(sm + FO_DW);
        int f = t >> 3, pl = (t & 7)*2;
        float r0 = __ldg(&db[pl]), r1 = __ldg(&db[pl+1]);
        const float* Fr = F + f*132;
        const float* d0 = dwT + pl*132;
        const float* d1 = dwT + (pl+1)*132;
        #pragma unroll 8
        for (int d = 0; d < 128; d++) {
            float ff = Fr[d];
            r0 += ff * d0[d];
            r1 += ff * d1[d];
        }
        float stdv = g_std[bv], meanv = g_mean[bv];
        out[(size_t)b*32768 + (size_t)(f*16 + pl)*64 + v]     = r0*stdv + meanv;
        out[(size_t)b*32768 + (size_t)(f*16 + pl + 1)*64 + v] = r1*stdv + meanv;
    }
}

// ===== launch =====
extern "C" void kernel_launch(void* const* d_in, const int* in_sizes, int n_in,
                              void* d_out, int out_size) {
    const float* x      = (const float*)d_in[0];
    const float* cent   = (const float*)d_in[1];
    const float* enc_w  = (const float*)d_in[2];
    const float* enc_b  = (const float*)d_in[3];
    const float* ln_w   = (const float*)d_in[4];
    const float* ln_b   = (const float*)d_in[5];
    const float* fc1_w  = (const float*)d_in[6];
    const float* fc1_b  = (const float*)d_in[7];
    const float* fcm_w  = (const float*)d_in[8];
    const float* fcm_b  = (const float*)d_in[9];
    const float* fc2_w  = (const float*)d_in[10];
    const float* fc2_b  = (const float*)d_in[11];
    const float* fuse_w = (const float*)d_in[12];
    const float* fuse_b = (const float*)d_in[13];
    const float* fln_w  = (const float*)d_in[14];
    const float* fln_b  = (const float*)d_in[15];
    const float* dec_w  = (const float*)d_in[16];
    const float* dec_b  = (const float*)d_in[17];

    float* out    = (float*)d_out;
    float* logits = out + (size_t)BB*512*VV;

    cudaFuncSetAttribute(k_mlp_mma,  cudaFuncAttributeMaxDynamicSharedMemorySize, SMEM_MLP);
    cudaFuncSetAttribute(k_vq_mma,   cudaFuncAttributeMaxDynamicSharedMemorySize, SMEM_VQ);
    cudaFuncSetAttribute(k_fuse_mma, cudaFuncAttributeMaxDynamicSharedMemorySize, SMEM_FUSE);

    k_xT<<<dim3(16, 32), 256>>>(x);
    k_revin<<<BB, 256>>>();
    k_c2<<<KK/8, 256>>>(cent);
    k_wprep<<<704, 256>>>(fc1_w, fcm_w, fc2_w, fuse_w);
    k_encode<<<BB*VV, 256>>>(enc_w, enc_b, ln_w, ln_b);
    k_mlp_mma<<<BB*VV, 256, SMEM_MLP>>>(fc1_b, fcm_b, fc2_b);
    k_vq_mma<<<NVQ/128, 256, SMEM_VQ>>>(cent, logits);
    k_fuse_mma<<<BB*VV, 256, SMEM_FUSE>>>(fuse_b, fln_w, fln_b, dec_w, dec_b, out);
}

// round 9
// speedup vs baseline: 7.5060x; 1.0981x over previous
#include <cuda_runtime.h>
#include <cuda_bf16.h>
#include <math.h>
#include <stdint.h>

#define BB   32
#define LL   1024
#define VV   64
#define PHn  64
#define PFn  32
#define DD   128
#define KK   1024
#define NVQ  (BB*VV*PFn)
#define NROW (BB*VV*DD)

__device__ float g_mean[BB*VV];
__device__ float g_std[BB*VV];
__device__ float g_xt[(size_t)BB*VV*LL];          // x transposed [b][v][l]
__device__ float g_z2[NVQ];                       // exact fp32 |z|^2 per row
__device__ float g_Zcode[(size_t)NVQ*DD];
__device__ float g_c2[KK];
__device__ __nv_bfloat16 g_Zpb[(size_t)NVQ*DD];   // bf16 z_p [n][d]
__device__ __nv_bfloat16 g_Cb[(size_t)KK*DD];     // bf16 centroids [k][d]
__device__ __nv_bfloat16 g_Ab[(size_t)NROW*64];   // [bv][d(row)][p(k)]
__device__ __nv_bfloat16 g_W1b[64*256];
__device__ __nv_bfloat16 g_W2b[256*512];
__device__ __nv_bfloat16 g_W3b[512*32];
__device__ __nv_bfloat16 g_Fwb[128*128];          // bf16 fuse_w [k][n]

extern __shared__ char dynsm[];

// ===== helpers =====
__device__ __forceinline__ uint32_t smem_u32(const void* p) {
    uint32_t a;
    asm("{ .reg .u64 t; cvta.to.shared.u64 t, %1; cvt.u32.u64 %0, t; }" : "=r"(a) : "l"(p));
    return a;
}
__device__ __forceinline__ void ldsm4(uint32_t* r, uint32_t a) {
    asm volatile("ldmatrix.sync.aligned.m8n8.x4.shared.b16 {%0,%1,%2,%3}, [%4];"
        : "=r"(r[0]), "=r"(r[1]), "=r"(r[2]), "=r"(r[3]) : "r"(a));
}
__device__ __forceinline__ void ldsm4t(uint32_t* r, uint32_t a) {
    asm volatile("ldmatrix.sync.aligned.m8n8.x4.trans.shared.b16 {%0,%1,%2,%3}, [%4];"
        : "=r"(r[0]), "=r"(r[1]), "=r"(r[2]), "=r"(r[3]) : "r"(a));
}
__device__ __forceinline__ void mma_bf16(float* c, const uint32_t* a, uint32_t b0, uint32_t b1) {
    asm volatile("mma.sync.aligned.m16n8k16.row.col.f32.bf16.bf16.f32 "
        "{%0,%1,%2,%3}, {%4,%5,%6,%7}, {%8,%9}, {%0,%1,%2,%3};"
        : "+f"(c[0]), "+f"(c[1]), "+f"(c[2]), "+f"(c[3])
        : "r"(a[0]), "r"(a[1]), "r"(a[2]), "r"(a[3]), "r"(b0), "r"(b1));
}
__device__ __forceinline__ uint32_t packrelu(float x, float y, float bx, float by) {
    __nv_bfloat162 h = __float22bfloat162_rn(make_float2(fmaxf(x+bx,0.f), fmaxf(y+by,0.f)));
    return *reinterpret_cast<uint32_t*>(&h);
}
__device__ __forceinline__ void top5_ins(float* tv, int* ti, float d, int k) {
    if (d < tv[4]) {
        tv[4] = d; ti[4] = k;
        #pragma unroll
        for (int s = 4; s > 0; s--) {
            if (tv[s] < tv[s-1]) {
                float tf = tv[s]; tv[s] = tv[s-1]; tv[s-1] = tf;
                int tk = ti[s]; ti[s] = ti[s-1]; ti[s-1] = tk;
            }
        }
    }
}
#define CP_ASYNC16(dst, src) \
    asm volatile("cp.async.cg.shared.global [%0], [%1], 16;" :: "r"(dst), "l"(src))
#define CP_COMMIT() asm volatile("cp.async.commit_group;" ::: "memory")
#define CP_WAIT1()  asm volatile("cp.async.wait_group 1;" ::: "memory")
#define CP_WAIT0()  asm volatile("cp.async.wait_group 0;" ::: "memory")

// ===== K0: transpose x -> [b][v][l] =====
__global__ void __launch_bounds__(256) k_xT(const float* __restrict__ x) {
    __shared__ float tile[64][65];
    int b = blockIdx.y, l0 = blockIdx.x*64;
    int t = threadIdx.x;
    for (int i = t; i < 4096; i += 256) {
        int li = i >> 6, v = i & 63;
        tile[li][v] = x[((size_t)b*1024 + l0 + li)*64 + v];
    }
    __syncthreads();
    for (int i = t; i < 4096; i += 256) {
        int v = i >> 6, li = i & 63;
        g_xt[((size_t)b*64 + v)*1024 + l0 + li] = tile[li][v];
    }
}

// ===== K1: prep — weight bf16 convert + centroid norms (merged) =====
__global__ void k_prep(const float* __restrict__ cent, const float* __restrict__ w1,
                       const float* __restrict__ w2, const float* __restrict__ w3,
                       const float* __restrict__ fw) {
    int blk = blockIdx.x;
    if (blk < 704) {
        int i = blk*256 + threadIdx.x;
        if (i < 16384)        g_W1b[i] = __float2bfloat16(w1[i]);
        else if (i < 147456)  g_W2b[i - 16384] = __float2bfloat16(w2[i - 16384]);
        else if (i < 163840)  g_W3b[i - 147456] = __float2bfloat16(w3[i - 147456]);
        else if (i < 180224)  g_Fwb[i - 163840] = __float2bfloat16(fw[i - 163840]);
    } else {
        int w = threadIdx.x >> 5, l = threadIdx.x & 31;
        int k = (blk - 704) * 8 + w;
        const float* cp = cent + (size_t)k*DD;
        float s = 0.f;
        #pragma unroll
        for (int q = 0; q < 4; q++) {
            float c = cp[l + 32*q];
            s += c*c;
            g_Cb[(size_t)k*DD + l + 32*q] = __float2bfloat16(c);
        }
        #pragma unroll
        for (int o = 16; o; o >>= 1) s += __shfl_xor_sync(0xffffffffu, s, o);
        if (l == 0) g_c2[k] = s;
    }
}

// ===== K2: encode + RevIN stats fused + LN -> bf16 A [d][p] =====
__global__ void __launch_bounds__(256) k_encode(
    const float* __restrict__ ew, const float* __restrict__ eb,
    const float* __restrict__ lnw, const float* __restrict__ lnb) {
    __shared__ float xv[1024], ws[2048], zt[8192];
    __shared__ float red[16], stat[2];
    int bv = blockIdx.x, t = threadIdx.x;
    int w = t >> 5, l = t & 31;
    const float* xp = g_xt + (size_t)bv*1024;
    for (int i = t; i < 1024; i += 256) xv[i] = xp[i];
    for (int i = t; i < 2048; i += 256) ws[i] = ew[i];
    __syncthreads();
    {
        float s = 0.f, q = 0.f;
        #pragma unroll
        for (int j = 0; j < 4; j++) { float val = xv[t + 256*j]; s += val; q += val*val; }
        #pragma unroll
        for (int o = 16; o; o >>= 1) {
            s += __shfl_xor_sync(0xffffffffu, s, o);
            q += __shfl_xor_sync(0xffffffffu, q, o);
        }
        if (l == 0) { red[w] = s; red[8 + w] = q; }
        __syncthreads();
        if (t == 0) {
            float ss = 0.f, qq = 0.f;
            #pragma unroll
            for (int j = 0; j < 8; j++) { ss += red[j]; qq += red[8 + j]; }
            float mean = ss * (1.0f/LL);
            float stdv = sqrtf(qq*(1.0f/LL) - mean*mean + 1e-5f);
            g_mean[bv] = mean; g_std[bv] = stdv;
            stat[0] = mean; stat[1] = 1.0f / stdv;
        }
        __syncthreads();
        float mean = stat[0], rstd = stat[1];
        for (int i = t; i < 1024; i += 256) xv[i] = (xv[i] - mean) * rstd;
    }
    __syncthreads();
    for (int idx = t; idx < 8192; idx += 256) {
        int p = idx >> 7, d = idx & 127;
        float s = eb[d];
        const float* xq = &xv[p*16];
        #pragma unroll
        for (int i = 0; i < 16; i++) s += xq[i] * ws[i*128 + d];
        zt[idx] = s;
    }
    __syncthreads();
    __nv_bfloat16* Adst = g_Ab + (size_t)bv*8192;
    #pragma unroll
    for (int j = 0; j < 8; j++) {
        int p = w*8 + j;
        float z[4], s = 0.f, q = 0.f;
        #pragma unroll
        for (int qq = 0; qq < 4; qq++) {
            z[qq] = zt[p*128 + l + 32*qq];
            s += z[qq]; q += z[qq]*z[qq];
        }
        #pragma unroll
        for (int o = 16; o; o >>= 1) {
            s += __shfl_xor_sync(0xffffffffu, s, o);
            q += __shfl_xor_sync(0xffffffffu, q, o);
        }
        float mu = s * (1.0f/128.0f);
        float rs = rsqrtf(q*(1.0f/128.0f) - mu*mu + 1e-5f);
        #pragma unroll
        for (int qq = 0; qq < 4; qq++) {
            int d = l + 32*qq;
            Adst[d*64 + p] = __float2bfloat16((z[qq]-mu)*rs*lnw[d] + lnb[d]);
        }
    }
}

// ===== K3: HMMA bf16 fused MLP, cp.async pipelined (race-fixed buffers) =====
// Buffer parity: W2 half h -> buffer (h+1)&1. Half 0 lands in buf1 (disjoint
// from the W1 image in buf0), so the stage-1 overlap prefetch is safe.
#define MO_A   0
#define MO_W   18432
#define MO_H1  92160
#define MO_H2  159744
#define MO_W3  178176
#define SMEM_MLP 219136
#define W_HALF 36864

__device__ __forceinline__ void gemm_tile64(uint32_t Abase, int sA, int m0,
                                            uint32_t Bbase, int sB, int n0,
                                            int ksteps, int l, float acc[8][4]) {
    for (int ks = 0; ks < ksteps; ks++) {
        int kk = ks*16;
        uint32_t av[4];
        ldsm4(av, Abase + (uint32_t)(((m0 + (l&15))*sA + kk + ((l>>4)<<3))*2));
        #pragma unroll
        for (int t = 0; t < 4; t++) {
            uint32_t bvv[4];
            ldsm4t(bvv, Bbase + (uint32_t)(((kk + (l&15))*sB + n0 + t*16 + ((l>>4)<<3))*2));
            mma_bf16(acc[2*t],   av, bvv[0], bvv[1]);
            mma_bf16(acc[2*t+1], av, bvv[2], bvv[3]);
        }
    }
}

__device__ __forceinline__ void epi64(float acc[8][4], char* hdst, int sH, int m0, int n0,
                                      const float* __restrict__ bias, int boff, int l) {
    int row = l >> 2, qc = (l & 3)*2;
    #pragma unroll
    for (int t8 = 0; t8 < 8; t8++) {
        int col = n0 + t8*8 + qc;
        float b0 = __ldg(&bias[boff + col]), b1 = __ldg(&bias[boff + col + 1]);
        *(uint32_t*)(hdst + ((m0+row)*sH + col)*2)   = packrelu(acc[t8][0], acc[t8][1], b0, b1);
        *(uint32_t*)(hdst + ((m0+row+8)*sH + col)*2) = packrelu(acc[t8][2], acc[t8][3], b0, b1);
    }
}

__device__ __forceinline__ void issue_w2_half(uint32_t base, int hc, int hb, int t) {
    const uint4* W2g = reinterpret_cast<const uint4*>(g_W2b);
    #pragma unroll
    for (int rep = 0; rep < 8; rep++) {
        int i = t + rep*256;
        int row = i >> 3, q = i & 7;
        uint32_t dst = base + MO_W + hb*W_HALF + row*144 + q*16;
        CP_ASYNC16(dst, (const void*)(W2g + row*64 + hc*8 + q));
    }
    CP_COMMIT();
}

__global__ void __launch_bounds__(256, 1) k_mlp_mma(
    const float* __restrict__ b1g, const float* __restrict__ b2g,
    const float* __restrict__ b3g) {
    char* smem = dynsm;
    uint32_t base = smem_u32(smem);
    int t = threadIdx.x, w = t >> 5, l = t & 31;
    int bv = blockIdx.x;

    // group 0: A + W1 (into buf0 region)
    {
        const uint4* Ag = reinterpret_cast<const uint4*>(g_Ab) + (size_t)bv*1024;
        #pragma unroll
        for (int rep = 0; rep < 4; rep++) {
            int i = t + rep*256;
            int row = i >> 3, q = i & 7;
            CP_ASYNC16(base + MO_A + row*144 + q*16, (const void*)(Ag + i));
        }
        const uint4* W1g = reinterpret_cast<const uint4*>(g_W1b);
        #pragma unroll
        for (int rep = 0; rep < 8; rep++) {
            int i = t + rep*256;
            int row = i >> 5, q = i & 31;
            CP_ASYNC16(base + MO_W + row*528 + q*16, (const void*)(W1g + i));
        }
        CP_COMMIT();
    }
    // group 1: W3 + W2 half 0 -> buf1 (disjoint from W1 image)
    {
        const uint4* W3g = reinterpret_cast<const uint4*>(g_W3b);
        #pragma unroll
        for (int rep = 0; rep < 8; rep++) {
            int i = t + rep*256;
            int row = i >> 2, q = i & 3;
            CP_ASYNC16(base + MO_W3 + row*80 + q*16, (const void*)(W3g + i));
        }
        issue_w2_half(base, 0, 1, t);   // commits group 1
    }
    CP_WAIT1();          // group 0 (A+W1) complete; W3/W2h0 still in flight
    __syncthreads();

    // stage 1: H1[128,256] = relu(A @ W1 + b1)  — overlaps group-1 loads
    int m0 = w*16;
    for (int j = 0; j < 4; j++) {
        float acc[8][4];
        #pragma unroll
        for (int i = 0; i < 8; i++)
            #pragma unroll
            for (int jj = 0; jj < 4; jj++) acc[i][jj] = 0.f;
        gemm_tile64(base + MO_A, 72, m0, base + MO_W, 264, j*64, 4, l, acc);
        epi64(acc, smem + MO_H1, 264, m0, j*64, b1g, 0, l);
    }
    __syncthreads();

    // stages 2+3: 8 pipelined 64-col halves of W2; half h lives in buf (h+1)&1
    float acc3[4][4];
    #pragma unroll
    for (int i = 0; i < 4; i++)
        #pragma unroll
        for (int j = 0; j < 4; j++) acc3[i][j] = 0.f;

    for (int hc = 0; hc < 8; hc++) {
        if (hc < 7) { issue_w2_half(base, hc+1, hc&1, t); CP_WAIT1(); }
        else        { CP_WAIT0(); }
        __syncthreads();
        {
            float acc[8][4];
            #pragma unroll
            for (int i = 0; i < 8; i++)
                #pragma unroll
                for (int jj = 0; jj < 4; jj++) acc[i][jj] = 0.f;
            gemm_tile64(base + MO_H1, 264, m0, base + MO_W + ((hc+1)&1)*W_HALF, 72, 0, 16, l, acc);
            epi64(acc, smem + MO_H2, 72, m0, 0, b2g, hc*64, l);
        }
        __syncwarp();
        for (int ks = 0; ks < 4; ks++) {
            int kk = ks*16;
            uint32_t av[4];
            ldsm4(av, base + MO_H2 + (uint32_t)(((m0 + (l&15))*72 + kk + ((l>>4)<<3))*2));
            #pragma unroll
            for (int tt = 0; tt < 2; tt++) {
                uint32_t bvv[4];
                ldsm4t(bvv, base + MO_W3 + (uint32_t)(((hc*64 + kk + (l&15))*40 + tt*16 + ((l>>4)<<3))*2));
                mma_bf16(acc3[2*tt],   av, bvv[0], bvv[1]);
                mma_bf16(acc3[2*tt+1], av, bvv[2], bvv[3]);
            }
        }
        __syncthreads();
    }

    // final epilogue: +b3, transpose via smem -> OUT[f][d]
    float* OUT = (float*)(smem + MO_A);
    {
        int row = l >> 2, qc = (l & 3)*2;
        #pragma unroll
        for (int t8 = 0; t8 < 4; t8++) {
            int col = t8*8 + qc;
            float b0 = __ldg(&b3g[col]), b1 = __ldg(&b3g[col+1]);
            OUT[col*132     + m0 + row]     = acc3[t8][0] + b0;
            OUT[(col+1)*132 + m0 + row]     = acc3[t8][1] + b1;
            OUT[col*132     + m0 + row + 8] = acc3[t8][2] + b0;
            OUT[(col+1)*132 + m0 + row + 8] = acc3[t8][3] + b1;
        }
    }
    __syncthreads();
    // exact fp32 z2 per row f (warp w -> rows w*4..w*4+3)
    #pragma unroll
    for (int rr = 0; rr < 4; rr++) {
        int f = w*4 + rr;
        const float* Fr = OUT + f*132;
        float s = 0.f;
        #pragma unroll
        for (int j = 0; j < 4; j++) { float vv = Fr[l + 32*j]; s += vv*vv; }
        #pragma unroll
        for (int o = 16; o; o >>= 1) s += __shfl_xor_sync(0xffffffffu, s, o);
        if (l == 0) g_z2[bv*32 + f] = s;
    }
    // bf16 z_p store
    __nv_bfloat16* zpb = g_Zpb + (size_t)bv*4096;
    for (int i = t; i < 4096; i += 256) {
        int f = i >> 7, r = i & 127;
        zpb[i] = __float2bfloat16(OUT[f*132 + r]);
    }
}

// ===== K4: HMMA VQ =====
#define VQ_ZB   0
#define VQ_CB   34816
#define VQ_Z2   69632
#define VQ_C2   70144
#define VQ_CVAL 74240
#define VQ_CIDX 84480
#define VQ_WI   94720
#define SMEM_VQ 99840

__global__ void __launch_bounds__(256) k_vq_mma(const float* __restrict__ cent,
                                                float* __restrict__ logits) {
    char* sm = dynsm;
    uint32_t base = smem_u32(sm);
    int t = threadIdx.x, w = t >> 5, l = t & 31;
    int n0 = blockIdx.x * 128;

    {
        const uint4* Zg = reinterpret_cast<const uint4*>(g_Zpb) + (size_t)n0*16;
        #pragma unroll
        for (int rep = 0; rep < 8; rep++) {
            int i = t + rep*256;
            int row = i >> 4, q = i & 15;
            CP_ASYNC16(base + VQ_ZB + row*272 + q*16, (const void*)(Zg + i));
        }
        CP_COMMIT();
        float* c2s = (float*)(sm + VQ_C2);
        for (int i = t; i < 1024; i += 256) c2s[i] = g_c2[i];
        float* z2s = (float*)(sm + VQ_Z2);
        if (t < 128) z2s[t] = g_z2[n0 + t];
    }
    CP_WAIT0();
    __syncthreads();

    int m0 = w*16;
    int r0 = m0 + (l >> 2), r1 = r0 + 8;
    float z2a = ((float*)(sm + VQ_Z2))[r0];
    float z2b = ((float*)(sm + VQ_Z2))[r1];
    const float* c2s = (float*)(sm + VQ_C2);

    float tv0[5], tv1[5]; int ti0[5], ti1[5];
    #pragma unroll
    for (int s = 0; s < 5; s++) { tv0[s] = 3.0e38f; tv1[s] = 3.0e38f; ti0[s] = 0; ti1[s] = 0; }

    const uint4* Cg = reinterpret_cast<const uint4*>(g_Cb);
    for (int ch = 0; ch < 8; ch++) {
        __syncthreads();
        #pragma unroll
        for (int rep = 0; rep < 8; rep++) {
            int i = t + rep*256;
            int row = i >> 4, q = i & 15;
            CP_ASYNC16(base + VQ_CB + row*272 + q*16, (const void*)(Cg + ch*2048 + i));
        }
        CP_COMMIT();
        CP_WAIT0();
        __syncthreads();
        for (int h = 0; h < 2; h++) {
            float acc[8][4];
            #pragma unroll
            for (int i = 0; i < 8; i++)
                #pragma unroll
                for (int j = 0; j < 4; j++) acc[i][j] = 0.f;
            for (int ks = 0; ks < 8; ks++) {
                int kk = ks*16;
                uint32_t av[4];
                ldsm4(av, base + VQ_ZB + (uint32_t)(((m0 + (l&15))*136 + kk + ((l>>4)<<3))*2));
                #pragma unroll
                for (int tt = 0; tt < 4; tt++) {
                    uint32_t bvv[4];
                    ldsm4(bvv, base + VQ_CB + (uint32_t)(((h*64 + tt*16 + (l&15))*136 + kk + ((l>>4)<<3))*2));
                    mma_bf16(acc[2*tt],   av, bvv[0], bvv[2]);
                    mma_bf16(acc[2*tt+1], av, bvv[1], bvv[3]);
                }
            }
            int cb = ch*128 + h*64;
            #pragma unroll
            for (int a = 0; a < 8; a++) {
                int col = cb + (a>>1)*16 + ((a&1)<<3) + ((l&3)<<1);
                float c20 = c2s[col], c21 = c2s[col+1];
                float d00 = z2a + c20 - 2.0f*acc[a][0];
                float d01 = z2a + c21 - 2.0f*acc[a][1];
                float d10 = z2b + c20 - 2.0f*acc[a][2];
                float d11 = z2b + c21 - 2.0f*acc[a][3];
                *(float2*)(logits + (size_t)(n0+r0)*1024 + col) = make_float2(-d00, -d01);
                *(float2*)(logits + (size_t)(n0+r1)*1024 + col) = make_float2(-d10, -d11);
                top5_ins(tv0, ti0, d00, col); top5_ins(tv0, ti0, d01, col+1);
                top5_ins(tv1, ti1, d10, col); top5_ins(tv1, ti1, d11, col+1);
            }
        }
    }
    __syncthreads();

    {
        float* cval = (float*)(sm + VQ_CVAL);
        int*   cidx = (int*)(sm + VQ_CIDX);
        int own = l & 3;
        #pragma unroll
        for (int s = 0; s < 5; s++) {
            cval[r0*20 + own*5 + s] = tv0[s]; cidx[r0*20 + own*5 + s] = ti0[s];
            cval[r1*20 + own*5 + s] = tv1[s]; cidx[r1*20 + own*5 + s] = ti1[s];
        }
    }
    __syncthreads();
    if (t < 128) {
        float* cval = (float*)(sm + VQ_CVAL);
        int*   cidx = (int*)(sm + VQ_CIDX);
        float mv[5]; int mi[5];
        #pragma unroll
        for (int s = 0; s < 5; s++) { mv[s] = 3.0e38f; mi[s] = 0; }
        for (int c = 0; c < 20; c++) top5_ins(mv, mi, cval[t*20 + c], cidx[t*20 + c]);
        float m0v = mv[0];
        float wv[5]; float wsum = 0.f;
        #pragma unroll
        for (int j = 0; j < 5; j++) { wv[j] = expf(m0v - mv[j]); wsum += wv[j]; }
        float inv = 1.0f / wsum;
        float* wsm = (float*)(sm + VQ_WI);
        int*   ism = (int*)(sm + VQ_WI + 2560);
        #pragma unroll
        for (int j = 0; j < 5; j++) { wsm[t*5 + j] = wv[j]*inv; ism[t*5 + j] = mi[j]; }
    }
    __syncthreads();

    {
        float* wsm = (float*)(sm + VQ_WI);
        int*   ism = (int*)(sm + VQ_WI + 2560);
        for (int r = w; r < 128; r += 8) {
            float wg[5]; int id[5];
            #pragma unroll
            for (int j = 0; j < 5; j++) { wg[j] = wsm[r*5 + j]; id[j] = ism[r*5 + j]; }
            int dbase = l*4;
            float4 o = make_float4(0.f,0.f,0.f,0.f);
            #pragma unroll
            for (int j = 0; j < 5; j++) {
                float4 cv = *(const float4*)&cent[(size_t)id[j]*128 + dbase];
                o.x += wg[j]*cv.x; o.y += wg[j]*cv.y;
                o.z += wg[j]*cv.z; o.w += wg[j]*cv.w;
            }
            *(float4*)&g_Zcode[(size_t)(n0+r)*128 + dbase] = o;
        }
    }
}

// ===== K5: HMMA fuse + LN + decode + denorm =====
#define FO_ZB 0
#define FO_FW 8704
#define FO_F  43520
#define FO_DW 60416
#define SMEM_FUSE 68864

__global__ void __launch_bounds__(256) k_fuse_mma(
    const float* __restrict__ fb, const float* __restrict__ flnw,
    const float* __restrict__ flnb, const float* __restrict__ dwg,
    const float* __restrict__ db, float* __restrict__ out) {
    char* sm = dynsm;
    uint32_t base = smem_u32(sm);
    int t = threadIdx.x, w = t >> 5, l = t & 31;
    int bv = blockIdx.x;
    int b = bv >> 6, v = bv & 63;

    {
        const uint4* Zg = reinterpret_cast<const uint4*>(g_Zpb) + (size_t)bv*512;
        for (int i = t; i < 512; i += 256) {
            int row = i >> 4, q = i & 15;
            *(uint4*)(sm + FO_ZB + row*272 + q*16) = Zg[i];
        }
        const uint4* Fg = reinterpret_cast<const uint4*>(g_Fwb);
        for (int i = t; i < 2048; i += 256) {
            int row = i >> 4, q = i & 15;
            *(uint4*)(sm + FO_FW + row*272 + q*16) = Fg[i];
        }
        float* dwT = (float*)(sm + FO_DW);
        for (int i = t; i < 2048; i += 256) {
            int d = i >> 4, pl = i & 15;
            dwT[pl*132 + d] = dwg[i];
        }
    }
    __syncthreads();

    int m0 = (w & 1) * 16, nb = (w >> 1) * 32;
    float acc[4][4];
    #pragma unroll
    for (int i = 0; i < 4; i++)
        #pragma unroll
        for (int j = 0; j < 4; j++) acc[i][j] = 0.f;
    for (int ks = 0; ks < 8; ks++) {
        int kk = ks*16;
        uint32_t av[4];
        ldsm4(av, base + FO_ZB + (uint32_t)(((m0 + (l&15))*136 + kk + ((l>>4)<<3))*2));
        #pragma unroll
        for (int tt = 0; tt < 2; tt++) {
            uint32_t bvv[4];
            ldsm4t(bvv, base + FO_FW + (uint32_t)(((kk + (l&15))*136 + nb + tt*16 + ((l>>4)<<3))*2));
            mma_bf16(acc[2*tt],   av, bvv[0], bvv[1]);
            mma_bf16(acc[2*tt+1], av, bvv[2], bvv[3]);
        }
    }
    {
        float* F = (float*)(sm + FO_F);
        int r0 = m0 + (l >> 2), r1 = r0 + 8;
        const float* zc0 = g_Zcode + ((size_t)bv*32 + r0)*128;
        const float* zc1 = g_Zcode + ((size_t)bv*32 + r1)*128;
        #pragma unroll
        for (int t8 = 0; t8 < 4; t8++) {
            int col = nb + t8*8 + (l&3)*2;
            float b0 = __ldg(&fb[col]), b1 = __ldg(&fb[col+1]);
            float2 z0 = *(const float2*)(zc0 + col);
            float2 z1 = *(const float2*)(zc1 + col);
            F[r0*132 + col]     = fmaxf(acc[t8][0] + b0, 0.f) + z0.x;
            F[r0*132 + col + 1] = fmaxf(acc[t8][1] + b1, 0.f) + z0.y;
            F[r1*132 + col]     = fmaxf(acc[t8][2] + b0, 0.f) + z1.x;
            F[r1*132 + col + 1] = fmaxf(acc[t8][3] + b1, 0.f) + z1.y;
        }
    }
    __syncthreads();
    {
        float* F = (float*)(sm + FO_F);
        #pragma unroll
        for (int rr = 0; rr < 4; rr++) {
            int r = w*4 + rr;
            float vals[4], s = 0.f, q = 0.f;
            #pragma unroll
            for (int j = 0; j < 4; j++) {
                vals[j] = F[r*132 + l + 32*j];
                s += vals[j]; q += vals[j]*vals[j];
            }
            #pragma unroll
            for (int o = 16; o; o >>= 1) {
                s += __shfl_xor_sync(0xffffffffu, s, o);
                q += __shfl_xor_sync(0xffffffffu, q, o);
            }
            float mu = s * (1.0f/128.0f);
            float rs = rsqrtf(q*(1.0f/128.0f) - mu*mu + 1e-5f);
            #pragma unroll
            for (int j = 0; j < 4; j++) {
                int d = l + 32*j;
                F[r*132 + d] = (vals[j]-mu)*rs*__ldg(&flnw[d]) + __ldg(&flnb[d]);
            }
        }
    }
    __syncthreads();
    {
        const float* F = (float*)(sm + FO_F);
        const float* dwT = (float*)(sm + FO_DW);
        int f = t >> 3, pl = (t & 7)*2;
        float r0 = __ldg(&db[pl]), r1 = __ldg(&db[pl+1]);
        const float* Fr = F + f*132;
        const float* d0 = dwT + pl*132;
        const float* d1 = dwT + (pl+1)*132;
        #pragma unroll 8
        for (int d = 0; d < 128; d++) {
            float ff = Fr[d];
            r0 += ff * d0[d];
            r1 += ff * d1[d];
        }
        float stdv = g_std[bv], meanv = g_mean[bv];
        out[(size_t)b*32768 + (size_t)(f*16 + pl)*64 + v]     = r0*stdv + meanv;
        out[(size_t)b*32768 + (size_t)(f*16 + pl + 1)*64 + v] = r1*stdv + meanv;
    }
}

// ===== launch =====
extern "C" void kernel_launch(void* const* d_in, const int* in_sizes, int n_in,
                              void* d_out, int out_size) {
    const float* x      = (const float*)d_in[0];
    const float* cent   = (const float*)d_in[1];
    const float* enc_w  = (const float*)d_in[2];
    const float* enc_b  = (const float*)d_in[3];
    const float* ln_w   = (const float*)d_in[4];
    const float* ln_b   = (const float*)d_in[5];
    const float* fc1_w  = (const float*)d_in[6];
    const float* fc1_b  = (const float*)d_in[7];
    const float* fcm_w  = (const float*)d_in[8];
    const float* fcm_b  = (const float*)d_in[9];
    const float* fc2_w  = (const float*)d_in[10];
    const float* fc2_b  = (const float*)d_in[11];
    const float* fuse_w = (const float*)d_in[12];
    const float* fuse_b = (const float*)d_in[13];
    const float* fln_w  = (const float*)d_in[14];
    const float* fln_b  = (const float*)d_in[15];
    const float* dec_w  = (const float*)d_in[16];
    const float* dec_b  = (const float*)d_in[17];

    float* out    = (float*)d_out;
    float* logits = out + (size_t)BB*512*VV;

    cudaFuncSetAttribute(k_mlp_mma,  cudaFuncAttributeMaxDynamicSharedMemorySize, SMEM_MLP);
    cudaFuncSetAttribute(k_vq_mma,   cudaFuncAttributeMaxDynamicSharedMemorySize, SMEM_VQ);
    cudaFuncSetAttribute(k_fuse_mma, cudaFuncAttributeMaxDynamicSharedMemorySize, SMEM_FUSE);

    k_xT<<<dim3(16, 32), 256>>>(x);
    k_prep<<<832, 256>>>(cent, fc1_w, fcm_w, fc2_w, fuse_w);
    k_encode<<<BB*VV, 256>>>(enc_w, enc_b, ln_w, ln_b);
    k_mlp_mma<<<BB*VV, 256, SMEM_MLP>>>(fc1_b, fcm_b, fc2_b);
    k_vq_mma<<<NVQ/128, 256, SMEM_VQ>>>(cent, logits);
    k_fuse_mma<<<BB*VV, 256, SMEM_FUSE>>>(fuse_b, fln_w, fln_b, dec_w, dec_b, out);
}

// round 10
// speedup vs baseline: 8.0179x; 1.0682x over previous
#include <cuda_runtime.h>
#include <cuda_bf16.h>
#include <math.h>
#include <stdint.h>

#define BB   32
#define LL   1024
#define VV   64
#define PHn  64
#define PFn  32
#define DD   128
#define KK   1024
#define NVQ  (BB*VV*PFn)
#define NROW (BB*VV*DD)

__device__ float g_mean[BB*VV];
__device__ float g_std[BB*VV];
__device__ float g_xt[(size_t)BB*VV*LL];          // x transposed [b][v][l]
__device__ float g_z2[NVQ];                       // exact fp32 |z|^2 per row
__device__ float g_Zcode[(size_t)NVQ*DD];
__device__ float g_c2[KK];
__device__ __nv_bfloat16 g_Zpb[(size_t)NVQ*DD];   // bf16 z_p [n][d]
__device__ __nv_bfloat16 g_Cb[(size_t)KK*DD];     // bf16 centroids [k][d]
__device__ __nv_bfloat16 g_Ab[(size_t)NROW*64];   // [bv][d(row)][p(k)]
__device__ __nv_bfloat16 g_W1b[64*256];
__device__ __nv_bfloat16 g_W2b[256*512];
__device__ __nv_bfloat16 g_W3b[512*32];
__device__ __nv_bfloat16 g_Fwb[128*128];          // bf16 fuse_w [k][n]

extern __shared__ char dynsm[];

// ===== helpers =====
__device__ __forceinline__ uint32_t smem_u32(const void* p) {
    uint32_t a;
    asm("{ .reg .u64 t; cvta.to.shared.u64 t, %1; cvt.u32.u64 %0, t; }" : "=r"(a) : "l"(p));
    return a;
}
__device__ __forceinline__ void ldsm4(uint32_t* r, uint32_t a) {
    asm volatile("ldmatrix.sync.aligned.m8n8.x4.shared.b16 {%0,%1,%2,%3}, [%4];"
        : "=r"(r[0]), "=r"(r[1]), "=r"(r[2]), "=r"(r[3]) : "r"(a));
}
__device__ __forceinline__ void ldsm4t(uint32_t* r, uint32_t a) {
    asm volatile("ldmatrix.sync.aligned.m8n8.x4.trans.shared.b16 {%0,%1,%2,%3}, [%4];"
        : "=r"(r[0]), "=r"(r[1]), "=r"(r[2]), "=r"(r[3]) : "r"(a));
}
__device__ __forceinline__ void mma_bf16(float* c, const uint32_t* a, uint32_t b0, uint32_t b1) {
    asm volatile("mma.sync.aligned.m16n8k16.row.col.f32.bf16.bf16.f32 "
        "{%0,%1,%2,%3}, {%4,%5,%6,%7}, {%8,%9}, {%0,%1,%2,%3};"
        : "+f"(c[0]), "+f"(c[1]), "+f"(c[2]), "+f"(c[3])
        : "r"(a[0]), "r"(a[1]), "r"(a[2]), "r"(a[3]), "r"(b0), "r"(b1));
}
__device__ __forceinline__ uint32_t packrelu(float x, float y, float bx, float by) {
    __nv_bfloat162 h = __float22bfloat162_rn(make_float2(fmaxf(x+bx,0.f), fmaxf(y+by,0.f)));
    return *reinterpret_cast<uint32_t*>(&h);
}
__device__ __forceinline__ void top5_ins(float* tv, int* ti, float d, int k) {
    if (d < tv[4]) {
        tv[4] = d; ti[4] = k;
        #pragma unroll
        for (int s = 4; s > 0; s--) {
            if (tv[s] < tv[s-1]) {
                float tf = tv[s]; tv[s] = tv[s-1]; tv[s-1] = tf;
                int tk = ti[s]; ti[s] = ti[s-1]; ti[s-1] = tk;
            }
        }
    }
}
#define CP_ASYNC16(dst, src) \
    asm volatile("cp.async.cg.shared.global [%0], [%1], 16;" :: "r"(dst), "l"(src))
#define CP_COMMIT() asm volatile("cp.async.commit_group;" ::: "memory")
#define CP_WAIT1()  asm volatile("cp.async.wait_group 1;" ::: "memory")
#define CP_WAIT0()  asm volatile("cp.async.wait_group 0;" ::: "memory")

// ===== K0: transpose x -> [b][v][l] =====
__global__ void __launch_bounds__(256) k_xT(const float* __restrict__ x) {
    __shared__ float tile[64][65];
    int b = blockIdx.y, l0 = blockIdx.x*64;
    int t = threadIdx.x;
    for (int i = t; i < 4096; i += 256) {
        int li = i >> 6, v = i & 63;
        tile[li][v] = x[((size_t)b*1024 + l0 + li)*64 + v];
    }
    __syncthreads();
    for (int i = t; i < 4096; i += 256) {
        int v = i >> 6, li = i & 63;
        g_xt[((size_t)b*64 + v)*1024 + l0 + li] = tile[li][v];
    }
}

// ===== K1: prep — weight bf16 convert + centroid norms (merged) =====
__global__ void k_prep(const float* __restrict__ cent, const float* __restrict__ w1,
                       const float* __restrict__ w2, const float* __restrict__ w3,
                       const float* __restrict__ fw) {
    int blk = blockIdx.x;
    if (blk < 704) {
        int i = blk*256 + threadIdx.x;
        if (i < 16384)        g_W1b[i] = __float2bfloat16(w1[i]);
        else if (i < 147456)  g_W2b[i - 16384] = __float2bfloat16(w2[i - 16384]);
        else if (i < 163840)  g_W3b[i - 147456] = __float2bfloat16(w3[i - 147456]);
        else if (i < 180224)  g_Fwb[i - 163840] = __float2bfloat16(fw[i - 163840]);
    } else {
        int w = threadIdx.x >> 5, l = threadIdx.x & 31;
        int k = (blk - 704) * 8 + w;
        const float* cp = cent + (size_t)k*DD;
        float s = 0.f;
        #pragma unroll
        for (int q = 0; q < 4; q++) {
            float c = cp[l + 32*q];
            s += c*c;
            g_Cb[(size_t)k*DD + l + 32*q] = __float2bfloat16(c);
        }
        #pragma unroll
        for (int o = 16; o; o >>= 1) s += __shfl_xor_sync(0xffffffffu, s, o);
        if (l == 0) g_c2[k] = s;
    }
}

// ===== K2: encode + RevIN stats fused + LN -> bf16 A [d][p] =====
__global__ void __launch_bounds__(256) k_encode(
    const float* __restrict__ ew, const float* __restrict__ eb,
    const float* __restrict__ lnw, const float* __restrict__ lnb) {
    __shared__ float xv[1024], ws[2048], zt[8192];
    __shared__ float red[16], stat[2];
    int bv = blockIdx.x, t = threadIdx.x;
    int w = t >> 5, l = t & 31;
    const float* xp = g_xt + (size_t)bv*1024;
    for (int i = t; i < 1024; i += 256) xv[i] = xp[i];
    for (int i = t; i < 2048; i += 256) ws[i] = ew[i];
    __syncthreads();
    {
        float s = 0.f, q = 0.f;
        #pragma unroll
        for (int j = 0; j < 4; j++) { float val = xv[t + 256*j]; s += val; q += val*val; }
        #pragma unroll
        for (int o = 16; o; o >>= 1) {
            s += __shfl_xor_sync(0xffffffffu, s, o);
            q += __shfl_xor_sync(0xffffffffu, q, o);
        }
        if (l == 0) { red[w] = s; red[8 + w] = q; }
        __syncthreads();
        if (t == 0) {
            float ss = 0.f, qq = 0.f;
            #pragma unroll
            for (int j = 0; j < 8; j++) { ss += red[j]; qq += red[8 + j]; }
            float mean = ss * (1.0f/LL);
            float stdv = sqrtf(qq*(1.0f/LL) - mean*mean + 1e-5f);
            g_mean[bv] = mean; g_std[bv] = stdv;
            stat[0] = mean; stat[1] = 1.0f / stdv;
        }
        __syncthreads();
        float mean = stat[0], rstd = stat[1];
        for (int i = t; i < 1024; i += 256) xv[i] = (xv[i] - mean) * rstd;
    }
    __syncthreads();
    for (int idx = t; idx < 8192; idx += 256) {
        int p = idx >> 7, d = idx & 127;
        float s = eb[d];
        const float* xq = &xv[p*16];
        #pragma unroll
        for (int i = 0; i < 16; i++) s += xq[i] * ws[i*128 + d];
        zt[idx] = s;
    }
    __syncthreads();
    __nv_bfloat16* Adst = g_Ab + (size_t)bv*8192;
    #pragma unroll
    for (int j = 0; j < 8; j++) {
        int p = w*8 + j;
        float z[4], s = 0.f, q = 0.f;
        #pragma unroll
        for (int qq = 0; qq < 4; qq++) {
            z[qq] = zt[p*128 + l + 32*qq];
            s += z[qq]; q += z[qq]*z[qq];
        }
        #pragma unroll
        for (int o = 16; o; o >>= 1) {
            s += __shfl_xor_sync(0xffffffffu, s, o);
            q += __shfl_xor_sync(0xffffffffu, q, o);
        }
        float mu = s * (1.0f/128.0f);
        float rs = rsqrtf(q*(1.0f/128.0f) - mu*mu + 1e-5f);
        #pragma unroll
        for (int qq = 0; qq < 4; qq++) {
            int d = l + 32*qq;
            Adst[d*64 + p] = __float2bfloat16((z[qq]-mu)*rs*lnw[d] + lnb[d]);
        }
    }
}

// ===== K3: HMMA bf16 fused MLP — M32xN64 warp tiles + register stage2->3 =====
// A   [128][72]b16 @ 0        (18432)  -> reused as f32 OUT[32][132]
// W   2x sub-buffers [128K][136N]b16 @ 18432 (34816 each; W1 [64][264] in buf0 for stage1)
// H1  [128][264]b16 @ 88064   (67584)
// W3  [512][40]b16  @ 155648  (40960)  total 196608
#define MO_A   0
#define MO_W   18432
#define MO_H1  88064
#define MO_W3  155648
#define SMEM_MLP 196608
#define W_SUB  34816

__device__ __forceinline__ void gemm_tile64(uint32_t Abase, int sA, int m0,
                                            uint32_t Bbase, int sB, int n0,
                                            int ksteps, int l, float acc[8][4]) {
    for (int ks = 0; ks < ksteps; ks++) {
        int kk = ks*16;
        uint32_t av[4];
        ldsm4(av, Abase + (uint32_t)(((m0 + (l&15))*sA + kk + ((l>>4)<<3))*2));
        #pragma unroll
        for (int t = 0; t < 4; t++) {
            uint32_t bvv[4];
            ldsm4t(bvv, Bbase + (uint32_t)(((kk + (l&15))*sB + n0 + t*16 + ((l>>4)<<3))*2));
            mma_bf16(acc[2*t],   av, bvv[0], bvv[1]);
            mma_bf16(acc[2*t+1], av, bvv[2], bvv[3]);
        }
    }
}

__device__ __forceinline__ void epi64(float acc[8][4], char* hdst, int sH, int m0, int n0,
                                      const float* __restrict__ bias, int boff, int l) {
    int row = l >> 2, qc = (l & 3)*2;
    #pragma unroll
    for (int t8 = 0; t8 < 8; t8++) {
        int col = n0 + t8*8 + qc;
        float b0 = __ldg(&bias[boff + col]), b1 = __ldg(&bias[boff + col + 1]);
        *(uint32_t*)(hdst + ((m0+row)*sH + col)*2)   = packrelu(acc[t8][0], acc[t8][1], b0, b1);
        *(uint32_t*)(hdst + ((m0+row+8)*sH + col)*2) = packrelu(acc[t8][2], acc[t8][3], b0, b1);
    }
}

// prefetch W2 sub-block s (nc = s>>1 N-chunk of 128, ksub = s&1 K-half of 128) into buffer hb
__device__ __forceinline__ void issue_w2_sub(uint32_t base, int s, int hb, int t) {
    int nc = s >> 1, ksub = s & 1;
    const uint4* W2g = reinterpret_cast<const uint4*>(g_W2b);
    #pragma unroll
    for (int rep = 0; rep < 8; rep++) {
        int i = t + rep*256;
        int row = i >> 4, q = i & 15;
        CP_ASYNC16(base + MO_W + hb*W_SUB + row*272 + q*16,
                   (const void*)(W2g + (ksub*128 + row)*64 + nc*16 + q));
    }
    CP_COMMIT();
}

__global__ void __launch_bounds__(256, 1) k_mlp_mma(
    const float* __restrict__ b1g, const float* __restrict__ b2g,
    const float* __restrict__ b3g) {
    char* smem = dynsm;
    uint32_t base = smem_u32(smem);
    int t = threadIdx.x, w = t >> 5, l = t & 31;
    int bv = blockIdx.x;

    // group 0: A + W1 (buf0 region)
    {
        const uint4* Ag = reinterpret_cast<const uint4*>(g_Ab) + (size_t)bv*1024;
        #pragma unroll
        for (int rep = 0; rep < 4; rep++) {
            int i = t + rep*256;
            int row = i >> 3, q = i & 7;
            CP_ASYNC16(base + MO_A + row*144 + q*16, (const void*)(Ag + i));
        }
        const uint4* W1g = reinterpret_cast<const uint4*>(g_W1b);
        #pragma unroll
        for (int rep = 0; rep < 8; rep++) {
            int i = t + rep*256;
            int row = i >> 5, q = i & 31;
            CP_ASYNC16(base + MO_W + row*528 + q*16, (const void*)(W1g + i));
        }
        CP_COMMIT();
    }
    // group 1: W3 + W2 sub 0 -> buf1 (disjoint from W1 image)
    {
        const uint4* W3g = reinterpret_cast<const uint4*>(g_W3b);
        #pragma unroll
        for (int rep = 0; rep < 8; rep++) {
            int i = t + rep*256;
            int row = i >> 2, q = i & 3;
            CP_ASYNC16(base + MO_W3 + row*80 + q*16, (const void*)(W3g + i));
        }
        issue_w2_sub(base, 0, 1, t);   // commits group 1
    }
    CP_WAIT1();          // A+W1 complete; W3/W2sub0 still in flight
    __syncthreads();

    // stage 1: H1[128,256] = relu(A @ W1 + b1)  — overlaps group-1 loads
    {
        int m0s1 = w*16;
        for (int j = 0; j < 4; j++) {
            float acc[8][4];
            #pragma unroll
            for (int i = 0; i < 8; i++)
                #pragma unroll
                for (int jj = 0; jj < 4; jj++) acc[i][jj] = 0.f;
            gemm_tile64(base + MO_A, 72, m0s1, base + MO_W, 264, j*64, 4, l, acc);
            epi64(acc, smem + MO_H1, 264, m0s1, j*64, b1g, 0, l);
        }
    }
    __syncthreads();

    // stages 2+3: warp grid 4M x 2N; N-chunks of 128, K-halves of 128
    int wm = w & 3, wn = w >> 2;
    int m0 = wm*32;
    float acc2[2][8][4];
    float acc3[2][4][4];
    #pragma unroll
    for (int mt = 0; mt < 2; mt++)
        #pragma unroll
        for (int j = 0; j < 4; j++)
            #pragma unroll
            for (int c = 0; c < 4; c++) acc3[mt][j][c] = 0.f;

    for (int s = 0; s < 8; s++) {
        int nc = s >> 1, ksub = s & 1;
        if (s < 7) { issue_w2_sub(base, s+1, s&1, t); CP_WAIT1(); }
        else       { CP_WAIT0(); }
        __syncthreads();
        if (ksub == 0) {
            #pragma unroll
            for (int mt = 0; mt < 2; mt++)
                #pragma unroll
                for (int j = 0; j < 8; j++)
                    #pragma unroll
                    for (int c = 0; c < 4; c++) acc2[mt][j][c] = 0.f;
        }
        uint32_t bufb = base + MO_W + ((s+1)&1)*W_SUB;
        for (int ks = 0; ks < 8; ks++) {
            int kk = ks*16;
            uint32_t a0[4], a1[4];
            ldsm4(a0, base + MO_H1 + (uint32_t)(((m0 + (l&15))*264 + ksub*128 + kk + ((l>>4)<<3))*2));
            ldsm4(a1, base + MO_H1 + (uint32_t)(((m0 + 16 + (l&15))*264 + ksub*128 + kk + ((l>>4)<<3))*2));
            #pragma unroll
            for (int tt = 0; tt < 4; tt++) {
                uint32_t bvv[4];
                ldsm4t(bvv, bufb + (uint32_t)(((kk + (l&15))*136 + wn*64 + tt*16 + ((l>>4)<<3))*2));
                mma_bf16(acc2[0][2*tt],   a0, bvv[0], bvv[1]);
                mma_bf16(acc2[0][2*tt+1], a0, bvv[2], bvv[3]);
                mma_bf16(acc2[1][2*tt],   a1, bvv[0], bvv[1]);
                mma_bf16(acc2[1][2*tt+1], a1, bvv[2], bvv[3]);
            }
        }
        if (ksub == 1) {
            // bias+relu pack acc2 -> A fragments; stage-3 partial (no H2 smem)
            #pragma unroll
            for (int kg = 0; kg < 4; kg++) {
                int krow = nc*128 + wn*64 + kg*16 + (l & 15);
                uint32_t bA[4], bB[4];
                ldsm4t(bA, base + MO_W3 + (uint32_t)((krow*40 + 0  + ((l>>4)<<3))*2));
                ldsm4t(bB, base + MO_W3 + (uint32_t)((krow*40 + 16 + ((l>>4)<<3))*2));
                int colb = nc*128 + wn*64 + kg*16 + (l&3)*2;
                float bb0 = __ldg(&b2g[colb]),     bb1 = __ldg(&b2g[colb+1]);
                float bb8 = __ldg(&b2g[colb+8]),   bb9 = __ldg(&b2g[colb+9]);
                #pragma unroll
                for (int mt = 0; mt < 2; mt++) {
                    uint32_t af[4];
                    af[0] = packrelu(acc2[mt][kg*2][0],   acc2[mt][kg*2][1],   bb0, bb1);
                    af[1] = packrelu(acc2[mt][kg*2][2],   acc2[mt][kg*2][3],   bb0, bb1);
                    af[2] = packrelu(acc2[mt][kg*2+1][0], acc2[mt][kg*2+1][1], bb8, bb9);
                    af[3] = packrelu(acc2[mt][kg*2+1][2], acc2[mt][kg*2+1][3], bb8, bb9);
                    mma_bf16(acc3[mt][0], af, bA[0], bA[1]);
                    mma_bf16(acc3[mt][1], af, bA[2], bA[3]);
                    mma_bf16(acc3[mt][2], af, bB[0], bB[1]);
                    mma_bf16(acc3[mt][3], af, bB[2], bB[3]);
                }
            }
        }
        __syncthreads();
    }

    // final: combine split-K partials (+b3) into OUT[f][d], then z2 + bf16 z_p
    float* OUT = (float*)(smem + MO_A);
    {
        int r = m0 + (l >> 2);
        if (wn == 0) {
            #pragma unroll
            for (int mt = 0; mt < 2; mt++)
                #pragma unroll
                for (int j = 0; j < 4; j++) {
                    int col = j*8 + (l&3)*2;
                    float b0 = __ldg(&b3g[col]), b1 = __ldg(&b3g[col+1]);
                    int rr = r + mt*16;
                    OUT[col*132 + rr]         = acc3[mt][j][0] + b0;
                    OUT[(col+1)*132 + rr]     = acc3[mt][j][1] + b1;
                    OUT[col*132 + rr + 8]     = acc3[mt][j][2] + b0;
                    OUT[(col+1)*132 + rr + 8] = acc3[mt][j][3] + b1;
                }
        }
        __syncthreads();
        if (wn == 1) {
            #pragma unroll
            for (int mt = 0; mt < 2; mt++)
                #pragma unroll
                for (int j = 0; j < 4; j++) {
                    int col = j*8 + (l&3)*2;
                    int rr = r + mt*16;
                    OUT[col*132 + rr]         += acc3[mt][j][0];
                    OUT[(col+1)*132 + rr]     += acc3[mt][j][1];
                    OUT[col*132 + rr + 8]     += acc3[mt][j][2];
                    OUT[(col+1)*132 + rr + 8] += acc3[mt][j][3];
                }
        }
        __syncthreads();
    }
    // exact fp32 z2 per row f (warp w -> rows w*4..w*4+3)
    #pragma unroll
    for (int rr = 0; rr < 4; rr++) {
        int f = w*4 + rr;
        const float* Fr = OUT + f*132;
        float s = 0.f;
        #pragma unroll
        for (int j = 0; j < 4; j++) { float vv = Fr[l + 32*j]; s += vv*vv; }
        #pragma unroll
        for (int o = 16; o; o >>= 1) s += __shfl_xor_sync(0xffffffffu, s, o);
        if (l == 0) g_z2[bv*32 + f] = s;
    }
    // bf16 z_p store
    __nv_bfloat16* zpb = g_Zpb + (size_t)bv*4096;
    for (int i = t; i < 4096; i += 256) {
        int f = i >> 7, r = i & 127;
        zpb[i] = __float2bfloat16(OUT[f*132 + r]);
    }
}

// ===== K4: HMMA VQ =====
#define VQ_ZB   0
#define VQ_CB   34816
#define VQ_Z2   69632
#define VQ_C2   70144
#define VQ_CVAL 74240
#define VQ_CIDX 84480
#define VQ_WI   94720
#define SMEM_VQ 99840

__global__ void __launch_bounds__(256) k_vq_mma(const float* __restrict__ cent,
                                                float* __restrict__ logits) {
    char* sm = dynsm;
    uint32_t base = smem_u32(sm);
    int t = threadIdx.x, w = t >> 5, l = t & 31;
    int n0 = blockIdx.x * 128;

    {
        const uint4* Zg = reinterpret_cast<const uint4*>(g_Zpb) + (size_t)n0*16;
        #pragma unroll
        for (int rep = 0; rep < 8; rep++) {
            int i = t + rep*256;
            int row = i >> 4, q = i & 15;
            CP_ASYNC16(base + VQ_ZB + row*272 + q*16, (const void*)(Zg + i));
        }
        CP_COMMIT();
        float* c2s = (float*)(sm + VQ_C2);
        for (int i = t; i < 1024; i += 256) c2s[i] = g_c2[i];
        float* z2s = (float*)(sm + VQ_Z2);
        if (t < 128) z2s[t] = g_z2[n0 + t];
    }
    CP_WAIT0();
    __syncthreads();

    int m0 = w*16;
    int r0 = m0 + (l >> 2), r1 = r0 + 8;
    float z2a = ((float*)(sm + VQ_Z2))[r0];
    float z2b = ((float*)(sm + VQ_Z2))[r1];
    const float* c2s = (float*)(sm + VQ_C2);

    float tv0[5], tv1[5]; int ti0[5], ti1[5];
    #pragma unroll
    for (int s = 0; s < 5; s++) { tv0[s] = 3.0e38f; tv1[s] = 3.0e38f; ti0[s] = 0; ti1[s] = 0; }

    const uint4* Cg = reinterpret_cast<const uint4*>(g_Cb);
    for (int ch = 0; ch < 8; ch++) {
        __syncthreads();
        #pragma unroll
        for (int rep = 0; rep < 8; rep++) {
            int i = t + rep*256;
            int row = i >> 4, q = i & 15;
            CP_ASYNC16(base + VQ_CB + row*272 + q*16, (const void*)(Cg + ch*2048 + i));
        }
        CP_COMMIT();
        CP_WAIT0();
        __syncthreads();
        for (int h = 0; h < 2; h++) {
            float acc[8][4];
            #pragma unroll
            for (int i = 0; i < 8; i++)
                #pragma unroll
                for (int j = 0; j < 4; j++) acc[i][j] = 0.f;
            for (int ks = 0; ks < 8; ks++) {
                int kk = ks*16;
                uint32_t av[4];
                ldsm4(av, base + VQ_ZB + (uint32_t)(((m0 + (l&15))*136 + kk + ((l>>4)<<3))*2));
                #pragma unroll
                for (int tt = 0; tt < 4; tt++) {
                    uint32_t bvv[4];
                    ldsm4(bvv, base + VQ_CB + (uint32_t)(((h*64 + tt*16 + (l&15))*136 + kk + ((l>>4)<<3))*2));
                    mma_bf16(acc[2*tt],   av, bvv[0], bvv[2]);
                    mma_bf16(acc[2*tt+1], av, bvv[1], bvv[3]);
                }
            }
            int cb = ch*128 + h*64;
            #pragma unroll
            for (int a = 0; a < 8; a++) {
                int col = cb + (a>>1)*16 + ((a&1)<<3) + ((l&3)<<1);
                float c20 = c2s[col], c21 = c2s[col+1];
                float d00 = z2a + c20 - 2.0f*acc[a][0];
                float d01 = z2a + c21 - 2.0f*acc[a][1];
                float d10 = z2b + c20 - 2.0f*acc[a][2];
                float d11 = z2b + c21 - 2.0f*acc[a][3];
                *(float2*)(logits + (size_t)(n0+r0)*1024 + col) = make_float2(-d00, -d01);
                *(float2*)(logits + (size_t)(n0+r1)*1024 + col) = make_float2(-d10, -d11);
                top5_ins(tv0, ti0, d00, col); top5_ins(tv0, ti0, d01, col+1);
                top5_ins(tv1, ti1, d10, col); top5_ins(tv1, ti1, d11, col+1);
            }
        }
    }
    __syncthreads();

    {
        float* cval = (float*)(sm + VQ_CVAL);
        int*   cidx = (int*)(sm + VQ_CIDX);
        int own = l & 3;
        #pragma unroll
        for (int s = 0; s < 5; s++) {
            cval[r0*20 + own*5 + s] = tv0[s]; cidx[r0*20 + own*5 + s] = ti0[s];
            cval[r1*20 + own*5 + s] = tv1[s]; cidx[r1*20 + own*5 + s] = ti1[s];
        }
    }
    __syncthreads();
    if (t < 128) {
        float* cval = (float*)(sm + VQ_CVAL);
        int*   cidx = (int*)(sm + VQ_CIDX);
        float mv[5]; int mi[5];
        #pragma unroll
        for (int s = 0; s < 5; s++) { mv[s] = 3.0e38f; mi[s] = 0; }
        for (int c = 0; c < 20; c++) top5_ins(mv, mi, cval[t*20 + c], cidx[t*20 + c]);
        float m0v = mv[0];
        float wv[5]; float wsum = 0.f;
        #pragma unroll
        for (int j = 0; j < 5; j++) { wv[j] = expf(m0v - mv[j]); wsum += wv[j]; }
        float inv = 1.0f / wsum;
        float* wsm = (float*)(sm + VQ_WI);
        int*   ism = (int*)(sm + VQ_WI + 2560);
        #pragma unroll
        for (int j = 0; j < 5; j++) { wsm[t*5 + j] = wv[j]*inv; ism[t*5 + j] = mi[j]; }
    }
    __syncthreads();

    {
        float* wsm = (float*)(sm + VQ_WI);
        int*   ism = (int*)(sm + VQ_WI + 2560);
        for (int r = w; r < 128; r += 8) {
            float wg[5]; int id[5];
            #pragma unroll
            for (int j = 0; j < 5; j++) { wg[j] = wsm[r*5 + j]; id[j] = ism[r*5 + j]; }
            int dbase = l*4;
            float4 o = make_float4(0.f,0.f,0.f,0.f);
            #pragma unroll
            for (int j = 0; j < 5; j++) {
                float4 cv = *(const float4*)&cent[(size_t)id[j]*128 + dbase];
                o.x += wg[j]*cv.x; o.y += wg[j]*cv.y;
                o.z += wg[j]*cv.z; o.w += wg[j]*cv.w;
            }
            *(float4*)&g_Zcode[(size_t)(n0+r)*128 + dbase] = o;
        }
    }
}

// ===== K5: HMMA fuse + LN + decode + denorm =====
#define FO_ZB 0
#define FO_FW 8704
#define FO_F  43520
#define FO_DW 60416
#define SMEM_FUSE 68864

__global__ void __launch_bounds__(256) k_fuse_mma(
    const float* __restrict__ fb, const float* __restrict__ flnw,
    const float* __restrict__ flnb, const float* __restrict__ dwg,
    const float* __restrict__ db, float* __restrict__ out) {
    char* sm = dynsm;
    uint32_t base = smem_u32(sm);
    int t = threadIdx.x, w = t >> 5, l = t & 31;
    int bv = blockIdx.x;
    int b = bv >> 6, v = bv & 63;

    {
        const uint4* Zg = reinterpret_cast<const uint4*>(g_Zpb) + (size_t)bv*512;
        for (int i = t; i < 512; i += 256) {
            int row = i >> 4, q = i & 15;
            *(uint4*)(sm + FO_ZB + row*272 + q*16) = Zg[i];
        }
        const uint4* Fg = reinterpret_cast<const uint4*>(g_Fwb);
        for (int i = t; i < 2048; i += 256) {
            int row = i >> 4, q = i & 15;
            *(uint4*)(sm + FO_FW + row*272 + q*16) = Fg[i];
        }
        float* dwT = (float*)(sm + FO_DW);
        for (int i = t; i < 2048; i += 256) {
            int d = i >> 4, pl = i & 15;
            dwT[pl*132 + d] = dwg[i];
        }
    }
    __syncthreads();

    int m0 = (w & 1) * 16, nb = (w >> 1) * 32;
    float acc[4][4];
    #pragma unroll
    for (int i = 0; i < 4; i++)
        #pragma unroll
        for (int j = 0; j < 4; j++) acc[i][j] = 0.f;
    for (int ks = 0; ks < 8; ks++) {
        int kk = ks*16;
        uint32_t av[4];
        ldsm4(av, base + FO_ZB + (uint32_t)(((m0 + (l&15))*136 + kk + ((l>>4)<<3))*2));
        #pragma unroll
        for (int tt = 0; tt < 2; tt++) {
            uint32_t bvv[4];
            ldsm4t(bvv, base + FO_FW + (uint32_t)(((kk + (l&15))*136 + nb + tt*16 + ((l>>4)<<3))*2));
            mma_bf16(acc[2*tt],   av, bvv[0], bvv[1]);
            mma_bf16(acc[2*tt+1], av, bvv[2], bvv[3]);
        }
    }
    {
        float* F = (float*)(sm + FO_F);
        int r0 = m0 + (l >> 2), r1 = r0 + 8;
        const float* zc0 = g_Zcode + ((size_t)bv*32 + r0)*128;
        const float* zc1 = g_Zcode + ((size_t)bv*32 + r1)*128;
        #pragma unroll
        for (int t8 = 0; t8 < 4; t8++) {
            int col = nb + t8*8 + (l&3)*2;
            float b0 = __ldg(&fb[col]), b1 = __ldg(&fb[col+1]);
            float2 z0 = *(const float2*)(zc0 + col);
            float2 z1 = *(const float2*)(zc1 + col);
            F[r0*132 + col]     = fmaxf(acc[t8][0] + b0, 0.f) + z0.x;
            F[r0*132 + col + 1] = fmaxf(acc[t8][1] + b1, 0.f) + z0.y;
            F[r1*132 + col]     = fmaxf(acc[t8][2] + b0, 0.f) + z1.x;
            F[r1*132 + col + 1] = fmaxf(acc[t8][3] + b1, 0.f) + z1.y;
        }
    }
    __syncthreads();
    {
        float* F = (float*)(sm + FO_F);
        #pragma unroll
        for (int rr = 0; rr < 4; rr++) {
            int r = w*4 + rr;
            float vals[4], s = 0.f, q = 0.f;
            #pragma unroll
            for (int j = 0; j < 4; j++) {
                vals[j] = F[r*132 + l + 32*j];
                s += vals[j]; q += vals[j]*vals[j];
            }
            #pragma unroll
            for (int o = 16; o; o >>= 1) {
                s += __shfl_xor_sync(0xffffffffu, s, o);
                q += __shfl_xor_sync(0xffffffffu, q, o);
            }
            float mu = s * (1.0f/128.0f);
            float rs = rsqrtf(q*(1.0f/128.0f) - mu*mu + 1e-5f);
            #pragma unroll
            for (int j = 0; j < 4; j++) {
                int d = l + 32*j;
                F[r*132 + d] = (vals[j]-mu)*rs*__ldg(&flnw[d]) + __ldg(&flnb[d]);
            }
        }
    }
    __syncthreads();
    {
        const float* F = (float*)(sm + FO_F);
        const float* dwT = (float*)(sm + FO_DW);
        int f = t >> 3, pl = (t & 7)*2;
        float r0 = __ldg(&db[pl]), r1 = __ldg(&db[pl+1]);
        const float* Fr = F + f*132;
        const float* d0 = dwT + pl*132;
        const float* d1 = dwT + (pl+1)*132;
        #pragma unroll 8
        for (int d = 0; d < 128; d++) {
            float ff = Fr[d];
            r0 += ff * d0[d];
            r1 += ff * d1[d];
        }
        float stdv = g_std[bv], meanv = g_mean[bv];
        out[(size_t)b*32768 + (size_t)(f*16 + pl)*64 + v]     = r0*stdv + meanv;
        out[(size_t)b*32768 + (size_t)(f*16 + pl + 1)*64 + v] = r1*stdv + meanv;
    }
}

// ===== launch =====
extern "C" void kernel_launch(void* const* d_in, const int* in_sizes, int n_in,
                              void* d_out, int out_size) {
    const float* x      = (const float*)d_in[0];
    const float* cent   = (const float*)d_in[1];
    const float* enc_w  = (const float*)d_in[2];
    const float* enc_b  = (const float*)d_in[3];
    const float* ln_w   = (const float*)d_in[4];
    const float* ln_b   = (const float*)d_in[5];
    const float* fc1_w  = (const float*)d_in[6];
    const float* fc1_b  = (const float*)d_in[7];
    const float* fcm_w  = (const float*)d_in[8];
    const float* fcm_b  = (const float*)d_in[9];
    const float* fc2_w  = (const float*)d_in[10];
    const float* fc2_b  = (const float*)d_in[11];
    const float* fuse_w = (const float*)d_in[12];
    const float* fuse_b = (const float*)d_in[13];
    const float* fln_w  = (const float*)d_in[14];
    const float* fln_b  = (const float*)d_in[15];
    const float* dec_w  = (const float*)d_in[16];
    const float* dec_b  = (const float*)d_in[17];

    float* out    = (float*)d_out;
    float* logits = out + (size_t)BB*512*VV;

    cudaFuncSetAttribute(k_mlp_mma,  cudaFuncAttributeMaxDynamicSharedMemorySize, SMEM_MLP);
    cudaFuncSetAttribute(k_vq_mma,   cudaFuncAttributeMaxDynamicSharedMemorySize, SMEM_VQ);
    cudaFuncSetAttribute(k_fuse_mma, cudaFuncAttributeMaxDynamicSharedMemorySize, SMEM_FUSE);

    k_xT<<<dim3(16, 32), 256>>>(x);
    k_prep<<<832, 256>>>(cent, fc1_w, fcm_w, fc2_w, fuse_w);
    k_encode<<<BB*VV, 256>>>(enc_w, enc_b, ln_w, ln_b);
    k_mlp_mma<<<BB*VV, 256, SMEM_MLP>>>(fc1_b, fcm_b, fc2_b);
    k_vq_mma<<<NVQ/128, 256, SMEM_VQ>>>(cent, logits);
    k_fuse_mma<<<BB*VV, 256, SMEM_FUSE>>>(fuse_b, fln_w, fln_b, dec_w, dec_b, out);
}

// round 11
// speedup vs baseline: 9.3668x; 1.1682x over previous
#include <cuda_runtime.h>
#include <cuda_bf16.h>
#include <math.h>
#include <stdint.h>

#define BB   32
#define LL   1024
#define VV   64
#define PHn  64
#define PFn  32
#define DD   128
#define KK   1024
#define NVQ  (BB*VV*PFn)
#define NROW (BB*VV*DD)

__device__ float g_mean[BB*VV];
__device__ float g_std[BB*VV];
__device__ float g_xt[(size_t)BB*VV*LL];          // x transposed [b][v][l]
__device__ float g_z2[NVQ];                       // exact fp32 |z|^2 per row
__device__ float g_c2[KK];
__device__ __nv_bfloat16 g_Zpb[(size_t)NVQ*DD];   // bf16 z_p [n][d]
__device__ __nv_bfloat16 g_Cb[(size_t)KK*DD];     // bf16 centroids [k][d]
__device__ __nv_bfloat16 g_W1b[64*256];
__device__ __nv_bfloat16 g_W2b[256*512];
__device__ __nv_bfloat16 g_W3b[512*32];
__device__ __nv_bfloat16 g_Fwb[128*128];          // bf16 fuse_w [k][n]

extern __shared__ char dynsm[];

// ===== helpers =====
__device__ __forceinline__ uint32_t smem_u32(const void* p) {
    uint32_t a;
    asm("{ .reg .u64 t; cvta.to.shared.u64 t, %1; cvt.u32.u64 %0, t; }" : "=r"(a) : "l"(p));
    return a;
}
__device__ __forceinline__ void ldsm4(uint32_t* r, uint32_t a) {
    asm volatile("ldmatrix.sync.aligned.m8n8.x4.shared.b16 {%0,%1,%2,%3}, [%4];"
        : "=r"(r[0]), "=r"(r[1]), "=r"(r[2]), "=r"(r[3]) : "r"(a));
}
__device__ __forceinline__ void ldsm4t(uint32_t* r, uint32_t a) {
    asm volatile("ldmatrix.sync.aligned.m8n8.x4.trans.shared.b16 {%0,%1,%2,%3}, [%4];"
        : "=r"(r[0]), "=r"(r[1]), "=r"(r[2]), "=r"(r[3]) : "r"(a));
}
__device__ __forceinline__ void mma_bf16(float* c, const uint32_t* a, uint32_t b0, uint32_t b1) {
    asm volatile("mma.sync.aligned.m16n8k16.row.col.f32.bf16.bf16.f32 "
        "{%0,%1,%2,%3}, {%4,%5,%6,%7}, {%8,%9}, {%0,%1,%2,%3};"
        : "+f"(c[0]), "+f"(c[1]), "+f"(c[2]), "+f"(c[3])
        : "r"(a[0]), "r"(a[1]), "r"(a[2]), "r"(a[3]), "r"(b0), "r"(b1));
}
__device__ __forceinline__ uint32_t packrelu(float x, float y, float bx, float by) {
    __nv_bfloat162 h = __float22bfloat162_rn(make_float2(fmaxf(x+bx,0.f), fmaxf(y+by,0.f)));
    return *reinterpret_cast<uint32_t*>(&h);
}
__device__ __forceinline__ void top5_ins(float* tv, int* ti, float d, int k) {
    if (d < tv[4]) {
        tv[4] = d; ti[4] = k;
        #pragma unroll
        for (int s = 4; s > 0; s--) {
            if (tv[s] < tv[s-1]) {
                float tf = tv[s]; tv[s] = tv[s-1]; tv[s-1] = tf;
                int tk = ti[s]; ti[s] = ti[s-1]; ti[s-1] = tk;
            }
        }
    }
}
#define CP_ASYNC16(dst, src) \
    asm volatile("cp.async.cg.shared.global [%0], [%1], 16;" :: "r"(dst), "l"(src))
#define CP_COMMIT() asm volatile("cp.async.commit_group;" ::: "memory")
#define CP_WAIT1()  asm volatile("cp.async.wait_group 1;" ::: "memory")
#define CP_WAIT0()  asm volatile("cp.async.wait_group 0;" ::: "memory")

// ===== K0: transpose x -> [b][v][l] =====
__global__ void __launch_bounds__(256) k_xT(const float* __restrict__ x) {
    __shared__ float tile[64][65];
    int b = blockIdx.y, l0 = blockIdx.x*64;
    int t = threadIdx.x;
    for (int i = t; i < 4096; i += 256) {
        int li = i >> 6, v = i & 63;
        tile[li][v] = x[((size_t)b*1024 + l0 + li)*64 + v];
    }
    __syncthreads();
    for (int i = t; i < 4096; i += 256) {
        int v = i >> 6, li = i & 63;
        g_xt[((size_t)b*64 + v)*1024 + l0 + li] = tile[li][v];
    }
}

// ===== K1: prep — weight bf16 convert + centroid norms =====
__global__ void k_prep(const float* __restrict__ cent, const float* __restrict__ w1,
                       const float* __restrict__ w2, const float* __restrict__ w3,
                       const float* __restrict__ fw) {
    int blk = blockIdx.x;
    if (blk < 704) {
        int i = blk*256 + threadIdx.x;
        if (i < 16384)        g_W1b[i] = __float2bfloat16(w1[i]);
        else if (i < 147456)  g_W2b[i - 16384] = __float2bfloat16(w2[i - 16384]);
        else if (i < 163840)  g_W3b[i - 147456] = __float2bfloat16(w3[i - 147456]);
        else if (i < 180224)  g_Fwb[i - 163840] = __float2bfloat16(fw[i - 163840]);
    } else {
        int w = threadIdx.x >> 5, l = threadIdx.x & 31;
        int k = (blk - 704) * 8 + w;
        const float* cp = cent + (size_t)k*DD;
        float s = 0.f;
        #pragma unroll
        for (int q = 0; q < 4; q++) {
            float c = cp[l + 32*q];
            s += c*c;
            g_Cb[(size_t)k*DD + l + 32*q] = __float2bfloat16(c);
        }
        #pragma unroll
        for (int o = 16; o; o >>= 1) s += __shfl_xor_sync(0xffffffffu, s, o);
        if (l == 0) g_c2[k] = s;
    }
}

// ===== K3: fused encode + 3-layer HMMA MLP =====
// A   [128][72]b16 @ 0        (18432)  -> reused as f32 OUT[32][132]
// W   2x sub-buffers @ 18432 (34816 each; W1 [64][264] in buf0 for stage1)
// H1  [128][264]b16 @ 88064   (67584; encode zt scratch first)
// W3  [512][40]b16  @ 155648  (40960; encode xv/ws scratch first)
#define MO_A   0
#define MO_W   18432
#define MO_H1  88064
#define MO_W3  155648
#define SC_XV  155648
#define SC_WS  159744
#define SMEM_MLP 196608
#define W_SUB  34816

__device__ __forceinline__ void gemm_tile64(uint32_t Abase, int sA, int m0,
                                            uint32_t Bbase, int sB, int n0,
                                            int ksteps, int l, float acc[8][4]) {
    for (int ks = 0; ks < ksteps; ks++) {
        int kk = ks*16;
        uint32_t av[4];
        ldsm4(av, Abase + (uint32_t)(((m0 + (l&15))*sA + kk + ((l>>4)<<3))*2));
        #pragma unroll
        for (int t = 0; t < 4; t++) {
            uint32_t bvv[4];
            ldsm4t(bvv, Bbase + (uint32_t)(((kk + (l&15))*sB + n0 + t*16 + ((l>>4)<<3))*2));
            mma_bf16(acc[2*t],   av, bvv[0], bvv[1]);
            mma_bf16(acc[2*t+1], av, bvv[2], bvv[3]);
        }
    }
}

__device__ __forceinline__ void epi64(float acc[8][4], char* hdst, int sH, int m0, int n0,
                                      const float* __restrict__ bias, int boff, int l) {
    int row = l >> 2, qc = (l & 3)*2;
    #pragma unroll
    for (int t8 = 0; t8 < 8; t8++) {
        int col = n0 + t8*8 + qc;
        float b0 = __ldg(&bias[boff + col]), b1 = __ldg(&bias[boff + col + 1]);
        *(uint32_t*)(hdst + ((m0+row)*sH + col)*2)   = packrelu(acc[t8][0], acc[t8][1], b0, b1);
        *(uint32_t*)(hdst + ((m0+row+8)*sH + col)*2) = packrelu(acc[t8][2], acc[t8][3], b0, b1);
    }
}

__device__ __forceinline__ void issue_w2_sub(uint32_t base, int s, int hb, int t) {
    int nc = s >> 1, ksub = s & 1;
    const uint4* W2g = reinterpret_cast<const uint4*>(g_W2b);
    #pragma unroll
    for (int rep = 0; rep < 8; rep++) {
        int i = t + rep*256;
        int row = i >> 4, q = i & 15;
        CP_ASYNC16(base + MO_W + hb*W_SUB + row*272 + q*16,
                   (const void*)(W2g + (ksub*128 + row)*64 + nc*16 + q));
    }
    CP_COMMIT();
}

__global__ void __launch_bounds__(256, 1) k_mlp_mma(
    const float* __restrict__ ew, const float* __restrict__ eb,
    const float* __restrict__ lnw, const float* __restrict__ lnb,
    const float* __restrict__ b1g, const float* __restrict__ b2g,
    const float* __restrict__ b3g) {
    char* smem = dynsm;
    uint32_t base = smem_u32(smem);
    __shared__ float red[16], stat[2];
    int t = threadIdx.x, w = t >> 5, l = t & 31;
    int bv = blockIdx.x;

    // group 0: x tile + enc_w + W1
    {
        const uint4* Xg = reinterpret_cast<const uint4*>(g_xt + (size_t)bv*1024);
        CP_ASYNC16(base + SC_XV + t*16, (const void*)(Xg + t));
        const uint4* Eg = reinterpret_cast<const uint4*>(ew);
        CP_ASYNC16(base + SC_WS + t*16, (const void*)(Eg + t));
        CP_ASYNC16(base + SC_WS + (t+256)*16, (const void*)(Eg + t + 256));
        const uint4* W1g = reinterpret_cast<const uint4*>(g_W1b);
        #pragma unroll
        for (int rep = 0; rep < 8; rep++) {
            int i = t + rep*256;
            int row = i >> 5, q = i & 31;
            CP_ASYNC16(base + MO_W + row*528 + q*16, (const void*)(W1g + i));
        }
        CP_COMMIT();
    }
    CP_WAIT0();
    __syncthreads();

    // ---- fused encode: RevIN stats + patch-encode + LN -> A bf16 image ----
    {
        float* xv = (float*)(smem + SC_XV);
        float* ws = (float*)(smem + SC_WS);
        float s = 0.f, q = 0.f;
        #pragma unroll
        for (int j = 0; j < 4; j++) { float val = xv[t + 256*j]; s += val; q += val*val; }
        #pragma unroll
        for (int o = 16; o; o >>= 1) {
            s += __shfl_xor_sync(0xffffffffu, s, o);
            q += __shfl_xor_sync(0xffffffffu, q, o);
        }
        if (l == 0) { red[w] = s; red[8 + w] = q; }
        __syncthreads();
        if (t == 0) {
            float ss = 0.f, qq = 0.f;
            #pragma unroll
            for (int j = 0; j < 8; j++) { ss += red[j]; qq += red[8 + j]; }
            float mean = ss * (1.0f/LL);
            float stdv = sqrtf(qq*(1.0f/LL) - mean*mean + 1e-5f);
            g_mean[bv] = mean; g_std[bv] = stdv;
            stat[0] = mean; stat[1] = 1.0f / stdv;
        }
        __syncthreads();
        float mean = stat[0], rstd = stat[1];
        for (int i = t; i < 1024; i += 256) xv[i] = (xv[i] - mean) * rstd;
        __syncthreads();
        float* zt = (float*)(smem + MO_H1);
        for (int idx = t; idx < 8192; idx += 256) {
            int p = idx >> 7, d = idx & 127;
            float sv = __ldg(&eb[d]);
            const float* xq = &xv[p*16];
            #pragma unroll
            for (int i = 0; i < 16; i++) sv += xq[i] * ws[i*128 + d];
            zt[idx] = sv;
        }
        __syncthreads();
        __nv_bfloat16* Aimg = (__nv_bfloat16*)(smem + MO_A);
        #pragma unroll
        for (int j = 0; j < 8; j++) {
            int p = w*8 + j;
            float z[4], sv = 0.f, qv = 0.f;
            #pragma unroll
            for (int qq2 = 0; qq2 < 4; qq2++) {
                z[qq2] = zt[p*128 + l + 32*qq2];
                sv += z[qq2]; qv += z[qq2]*z[qq2];
            }
            #pragma unroll
            for (int o = 16; o; o >>= 1) {
                sv += __shfl_xor_sync(0xffffffffu, sv, o);
                qv += __shfl_xor_sync(0xffffffffu, qv, o);
            }
            float mu = sv * (1.0f/128.0f);
            float rs = rsqrtf(qv*(1.0f/128.0f) - mu*mu + 1e-5f);
            #pragma unroll
            for (int qq2 = 0; qq2 < 4; qq2++) {
                int d = l + 32*qq2;
                Aimg[d*72 + p] = __float2bfloat16((z[qq2]-mu)*rs*__ldg(&lnw[d]) + __ldg(&lnb[d]));
            }
        }
    }
    __syncthreads();

    // prefetch W3 (overwrites encode scratch) + W2 sub 0 -> buf1
    {
        const uint4* W3g = reinterpret_cast<const uint4*>(g_W3b);
        #pragma unroll
        for (int rep = 0; rep < 8; rep++) {
            int i = t + rep*256;
            int row = i >> 2, q = i & 3;
            CP_ASYNC16(base + MO_W3 + row*80 + q*16, (const void*)(W3g + i));
        }
        issue_w2_sub(base, 0, 1, t);   // one commit covers W3 + sub0
    }

    // stage 1: H1[128,256] = relu(A @ W1 + b1)  — overlaps prefetch
    {
        int m0s1 = w*16;
        for (int j = 0; j < 4; j++) {
            float acc[8][4];
            #pragma unroll
            for (int i = 0; i < 8; i++)
                #pragma unroll
                for (int jj = 0; jj < 4; jj++) acc[i][jj] = 0.f;
            gemm_tile64(base + MO_A, 72, m0s1, base + MO_W, 264, j*64, 4, l, acc);
            epi64(acc, smem + MO_H1, 264, m0s1, j*64, b1g, 0, l);
        }
    }
    __syncthreads();

    // stages 2+3: warp grid 4M x 2N; sub-blocks: nc (N128) x ksub (K128)
    int wm = w & 3, wn = w >> 2;
    int m0 = wm*32;
    float acc2[2][8][4];
    float acc3[2][4][4];
    #pragma unroll
    for (int mt = 0; mt < 2; mt++)
        #pragma unroll
        for (int j = 0; j < 4; j++)
            #pragma unroll
            for (int c = 0; c < 4; c++) acc3[mt][j][c] = 0.f;

    for (int s = 0; s < 8; s++) {
        int nc = s >> 1, ksub = s & 1;
        if (s < 7) { issue_w2_sub(base, s+1, s&1, t); CP_WAIT1(); }
        else       { CP_WAIT0(); }
        __syncthreads();
        if (ksub == 0) {
            #pragma unroll
            for (int mt = 0; mt < 2; mt++)
                #pragma unroll
                for (int j = 0; j < 8; j++)
                    #pragma unroll
                    for (int c = 0; c < 4; c++) acc2[mt][j][c] = 0.f;
        }
        uint32_t bufb = base + MO_W + ((s+1)&1)*W_SUB;
        for (int ks = 0; ks < 8; ks++) {
            int kk = ks*16;
            uint32_t a0[4], a1[4];
            ldsm4(a0, base + MO_H1 + (uint32_t)(((m0 + (l&15))*264 + ksub*128 + kk + ((l>>4)<<3))*2));
            ldsm4(a1, base + MO_H1 + (uint32_t)(((m0 + 16 + (l&15))*264 + ksub*128 + kk + ((l>>4)<<3))*2));
            #pragma unroll
            for (int tt = 0; tt < 4; tt++) {
                uint32_t bvv[4];
                ldsm4t(bvv, bufb + (uint32_t)(((kk + (l&15))*136 + wn*64 + tt*16 + ((l>>4)<<3))*2));
                mma_bf16(acc2[0][2*tt],   a0, bvv[0], bvv[1]);
                mma_bf16(acc2[0][2*tt+1], a0, bvv[2], bvv[3]);
                mma_bf16(acc2[1][2*tt],   a1, bvv[0], bvv[1]);
                mma_bf16(acc2[1][2*tt+1], a1, bvv[2], bvv[3]);
            }
        }
        if (ksub == 1) {
            #pragma unroll
            for (int kg = 0; kg < 4; kg++) {
                int krow = nc*128 + wn*64 + kg*16 + (l & 15);
                uint32_t bA[4], bB[4];
                ldsm4t(bA, base + MO_W3 + (uint32_t)((krow*40 + 0  + ((l>>4)<<3))*2));
                ldsm4t(bB, base + MO_W3 + (uint32_t)((krow*40 + 16 + ((l>>4)<<3))*2));
                int colb = nc*128 + wn*64 + kg*16 + (l&3)*2;
                float bb0 = __ldg(&b2g[colb]),     bb1 = __ldg(&b2g[colb+1]);
                float bb8 = __ldg(&b2g[colb+8]),   bb9 = __ldg(&b2g[colb+9]);
                #pragma unroll
                for (int mt = 0; mt < 2; mt++) {
                    uint32_t af[4];
                    af[0] = packrelu(acc2[mt][kg*2][0],   acc2[mt][kg*2][1],   bb0, bb1);
                    af[1] = packrelu(acc2[mt][kg*2][2],   acc2[mt][kg*2][3],   bb0, bb1);
                    af[2] = packrelu(acc2[mt][kg*2+1][0], acc2[mt][kg*2+1][1], bb8, bb9);
                    af[3] = packrelu(acc2[mt][kg*2+1][2], acc2[mt][kg*2+1][3], bb8, bb9);
                    mma_bf16(acc3[mt][0], af, bA[0], bA[1]);
                    mma_bf16(acc3[mt][1], af, bA[2], bA[3]);
                    mma_bf16(acc3[mt][2], af, bB[0], bB[1]);
                    mma_bf16(acc3[mt][3], af, bB[2], bB[3]);
                }
            }
        }
        __syncthreads();
    }

    // final: combine split-K partials (+b3) into OUT[f][d], then z2 + bf16 z_p
    float* OUT = (float*)(smem + MO_A);
    {
        int r = m0 + (l >> 2);
        if (wn == 0) {
            #pragma unroll
            for (int mt = 0; mt < 2; mt++)
                #pragma unroll
                for (int j = 0; j < 4; j++) {
                    int col = j*8 + (l&3)*2;
                    float b0 = __ldg(&b3g[col]), b1 = __ldg(&b3g[col+1]);
                    int rr = r + mt*16;
                    OUT[col*132 + rr]         = acc3[mt][j][0] + b0;
                    OUT[(col+1)*132 + rr]     = acc3[mt][j][1] + b1;
                    OUT[col*132 + rr + 8]     = acc3[mt][j][2] + b0;
                    OUT[(col+1)*132 + rr + 8] = acc3[mt][j][3] + b1;
                }
        }
        __syncthreads();
        if (wn == 1) {
            #pragma unroll
            for (int mt = 0; mt < 2; mt++)
                #pragma unroll
                for (int j = 0; j < 4; j++) {
                    int col = j*8 + (l&3)*2;
                    int rr = r + mt*16;
                    OUT[col*132 + rr]         += acc3[mt][j][0];
                    OUT[(col+1)*132 + rr]     += acc3[mt][j][1];
                    OUT[col*132 + rr + 8]     += acc3[mt][j][2];
                    OUT[(col+1)*132 + rr + 8] += acc3[mt][j][3];
                }
        }
        __syncthreads();
    }
    #pragma unroll
    for (int rr = 0; rr < 4; rr++) {
        int f = w*4 + rr;
        const float* Fr = OUT + f*132;
        float s = 0.f;
        #pragma unroll
        for (int j = 0; j < 4; j++) { float vv = Fr[l + 32*j]; s += vv*vv; }
        #pragma unroll
        for (int o = 16; o; o >>= 1) s += __shfl_xor_sync(0xffffffffu, s, o);
        if (l == 0) g_z2[bv*32 + f] = s;
    }
    __nv_bfloat16* zpb = g_Zpb + (size_t)bv*4096;
    for (int i = t; i < 4096; i += 256) {
        int f = i >> 7, r = i & 127;
        zpb[i] = __float2bfloat16(OUT[f*132 + r]);
    }
}

// ===== K4: HMMA VQ + fused ResidualFusion/LN/decode/denorm =====
#define VQ_ZB   0
#define VQ_CB   34816       // centroid chunks; later fuse_w image
#define VQ_Z2   69632
#define VQ_C2   70144
#define VQ_CVAL 74240       // candidates; later F tile [32][132] f32 (spans CVAL+CIDX)
#define VQ_CIDX 84480
#define VQ_WI   94720
#define VQ_DW   99840       // dwT f32 [16][132]
#define SMEM_VQ 108288

__global__ void __launch_bounds__(256) k_vq_mma(
    const float* __restrict__ cent, float* __restrict__ logits,
    const float* __restrict__ fb, const float* __restrict__ flnw,
    const float* __restrict__ flnb, const float* __restrict__ dwg,
    const float* __restrict__ db, float* __restrict__ out) {
    char* sm = dynsm;
    uint32_t base = smem_u32(sm);
    int t = threadIdx.x, w = t >> 5, l = t & 31;
    int n0 = blockIdx.x * 128;

    {
        const uint4* Zg = reinterpret_cast<const uint4*>(g_Zpb) + (size_t)n0*16;
        #pragma unroll
        for (int rep = 0; rep < 8; rep++) {
            int i = t + rep*256;
            int row = i >> 4, q = i & 15;
            CP_ASYNC16(base + VQ_ZB + row*272 + q*16, (const void*)(Zg + i));
        }
        CP_COMMIT();
        float* c2s = (float*)(sm + VQ_C2);
        for (int i = t; i < 1024; i += 256) c2s[i] = g_c2[i];
        float* z2s = (float*)(sm + VQ_Z2);
        if (t < 128) z2s[t] = g_z2[n0 + t];
    }
    CP_WAIT0();
    __syncthreads();

    int m0 = w*16;
    int r0 = m0 + (l >> 2), r1 = r0 + 8;
    float z2a = ((float*)(sm + VQ_Z2))[r0];
    float z2b = ((float*)(sm + VQ_Z2))[r1];
    const float* c2s = (float*)(sm + VQ_C2);

    float tv0[5], tv1[5]; int ti0[5], ti1[5];
    #pragma unroll
    for (int s = 0; s < 5; s++) { tv0[s] = 3.0e38f; tv1[s] = 3.0e38f; ti0[s] = 0; ti1[s] = 0; }

    const uint4* Cg = reinterpret_cast<const uint4*>(g_Cb);
    for (int ch = 0; ch < 8; ch++) {
        __syncthreads();
        #pragma unroll
        for (int rep = 0; rep < 8; rep++) {
            int i = t + rep*256;
            int row = i >> 4, q = i & 15;
            CP_ASYNC16(base + VQ_CB + row*272 + q*16, (const void*)(Cg + ch*2048 + i));
        }
        CP_COMMIT();
        CP_WAIT0();
        __syncthreads();
        for (int h = 0; h < 2; h++) {
            float acc[8][4];
            #pragma unroll
            for (int i = 0; i < 8; i++)
                #pragma unroll
                for (int j = 0; j < 4; j++) acc[i][j] = 0.f;
            for (int ks = 0; ks < 8; ks++) {
                int kk = ks*16;
                uint32_t av[4];
                ldsm4(av, base + VQ_ZB + (uint32_t)(((m0 + (l&15))*136 + kk + ((l>>4)<<3))*2));
                #pragma unroll
                for (int tt = 0; tt < 4; tt++) {
                    uint32_t bvv[4];
                    ldsm4(bvv, base + VQ_CB + (uint32_t)(((h*64 + tt*16 + (l&15))*136 + kk + ((l>>4)<<3))*2));
                    mma_bf16(acc[2*tt],   av, bvv[0], bvv[2]);
                    mma_bf16(acc[2*tt+1], av, bvv[1], bvv[3]);
                }
            }
            int cb = ch*128 + h*64;
            #pragma unroll
            for (int a = 0; a < 8; a++) {
                int col = cb + (a>>1)*16 + ((a&1)<<3) + ((l&3)<<1);
                float c20 = c2s[col], c21 = c2s[col+1];
                float d00 = z2a + c20 - 2.0f*acc[a][0];
                float d01 = z2a + c21 - 2.0f*acc[a][1];
                float d10 = z2b + c20 - 2.0f*acc[a][2];
                float d11 = z2b + c21 - 2.0f*acc[a][3];
                *(float2*)(logits + (size_t)(n0+r0)*1024 + col) = make_float2(-d00, -d01);
                *(float2*)(logits + (size_t)(n0+r1)*1024 + col) = make_float2(-d10, -d11);
                top5_ins(tv0, ti0, d00, col); top5_ins(tv0, ti0, d01, col+1);
                top5_ins(tv1, ti1, d10, col); top5_ins(tv1, ti1, d11, col+1);
            }
        }
    }
    __syncthreads();

    // candidate dump
    {
        float* cval = (float*)(sm + VQ_CVAL);
        int*   cidx = (int*)(sm + VQ_CIDX);
        int own = l & 3;
        #pragma unroll
        for (int s = 0; s < 5; s++) {
            cval[r0*20 + own*5 + s] = tv0[s]; cidx[r0*20 + own*5 + s] = ti0[s];
            cval[r1*20 + own*5 + s] = tv1[s]; cidx[r1*20 + own*5 + s] = ti1[s];
        }
    }
    __syncthreads();
    // load fuse_w into CB region + dwT (all threads), then per-row merge (t<128)
    {
        const uint4* Fg = reinterpret_cast<const uint4*>(g_Fwb);
        for (int i = t; i < 2048; i += 256) {
            int row = i >> 4, q = i & 15;
            *(uint4*)(sm + VQ_CB + row*272 + q*16) = Fg[i];
        }
        float* dwT = (float*)(sm + VQ_DW);
        for (int i = t; i < 2048; i += 256) {
            int d = i >> 4, pl = i & 15;
            dwT[pl*132 + d] = dwg[i];
        }
    }
    if (t < 128) {
        float* cval = (float*)(sm + VQ_CVAL);
        int*   cidx = (int*)(sm + VQ_CIDX);
        float mv[5]; int mi[5];
        #pragma unroll
        for (int s = 0; s < 5; s++) { mv[s] = 3.0e38f; mi[s] = 0; }
        for (int c = 0; c < 20; c++) top5_ins(mv, mi, cval[t*20 + c], cidx[t*20 + c]);
        float m0v = mv[0];
        float wv[5]; float wsum = 0.f;
        #pragma unroll
        for (int j = 0; j < 5; j++) { wv[j] = expf(m0v - mv[j]); wsum += wv[j]; }
        float inv = 1.0f / wsum;
        float* wsm = (float*)(sm + VQ_WI);
        int*   ism = (int*)(sm + VQ_WI + 2560);
        #pragma unroll
        for (int j = 0; j < 5; j++) { wsm[t*5 + j] = wv[j]*inv; ism[t*5 + j] = mi[j]; }
    }
    __syncthreads();

    // fused ResidualFusion + LN + decode + denorm, per bv (4 per CTA)
    float* F = (float*)(sm + VQ_CVAL);           // [32][132] f32
    float* wsm = (float*)(sm + VQ_WI);
    int*   ism = (int*)(sm + VQ_WI + 2560);
    const float* dwT = (float*)(sm + VQ_DW);
    for (int i4 = 0; i4 < 4; i4++) {
        int bvg = blockIdx.x*4 + i4;
        // gather z_code -> F
        for (int r = w; r < 32; r += 8) {
            int gr = i4*32 + r;
            float wg[5]; int id[5];
            #pragma unroll
            for (int j = 0; j < 5; j++) { wg[j] = wsm[gr*5 + j]; id[j] = ism[gr*5 + j]; }
            int dbase = l*4;
            float4 o = make_float4(0.f,0.f,0.f,0.f);
            #pragma unroll
            for (int j = 0; j < 5; j++) {
                float4 cv = *(const float4*)&cent[(size_t)id[j]*128 + dbase];
                o.x += wg[j]*cv.x; o.y += wg[j]*cv.y;
                o.z += wg[j]*cv.z; o.w += wg[j]*cv.w;
            }
            *(float4*)&F[r*132 + dbase] = o;
        }
        __syncthreads();
        // fuse MMA: z_p[32,128] @ fuse_w
        {
            int m0f = (w & 1) * 16, nb = (w >> 1) * 32;
            float facc[4][4];
            #pragma unroll
            for (int i = 0; i < 4; i++)
                #pragma unroll
                for (int j = 0; j < 4; j++) facc[i][j] = 0.f;
            for (int ks = 0; ks < 8; ks++) {
                int kk = ks*16;
                uint32_t av[4];
                ldsm4(av, base + VQ_ZB + (uint32_t)(((i4*32 + m0f + (l&15))*136 + kk + ((l>>4)<<3))*2));
                #pragma unroll
                for (int tt = 0; tt < 2; tt++) {
                    uint32_t bvv[4];
                    ldsm4t(bvv, base + VQ_CB + (uint32_t)(((kk + (l&15))*136 + nb + tt*16 + ((l>>4)<<3))*2));
                    mma_bf16(facc[2*tt],   av, bvv[0], bvv[1]);
                    mma_bf16(facc[2*tt+1], av, bvv[2], bvv[3]);
                }
            }
            int fr0 = m0f + (l >> 2), fr1 = fr0 + 8;
            #pragma unroll
            for (int t8 = 0; t8 < 4; t8++) {
                int col = nb + t8*8 + (l&3)*2;
                float b0 = __ldg(&fb[col]), b1 = __ldg(&fb[col+1]);
                F[fr0*132 + col]     = fmaxf(facc[t8][0] + b0, 0.f) + F[fr0*132 + col];
                F[fr0*132 + col + 1] = fmaxf(facc[t8][1] + b1, 0.f) + F[fr0*132 + col + 1];
                F[fr1*132 + col]     = fmaxf(facc[t8][2] + b0, 0.f) + F[fr1*132 + col];
                F[fr1*132 + col + 1] = fmaxf(facc[t8][3] + b1, 0.f) + F[fr1*132 + col + 1];
            }
        }
        __syncthreads();
        // LN per row (warp w: rows w*4..w*4+3)
        #pragma unroll
        for (int rr = 0; rr < 4; rr++) {
            int r = w*4 + rr;
            float vals[4], s = 0.f, q = 0.f;
            #pragma unroll
            for (int j = 0; j < 4; j++) {
                vals[j] = F[r*132 + l + 32*j];
                s += vals[j]; q += vals[j]*vals[j];
            }
            #pragma unroll
            for (int o = 16; o; o >>= 1) {
                s += __shfl_xor_sync(0xffffffffu, s, o);
                q += __shfl_xor_sync(0xffffffffu, q, o);
            }
            float mu = s * (1.0f/128.0f);
            float rs = rsqrtf(q*(1.0f/128.0f) - mu*mu + 1e-5f);
            #pragma unroll
            for (int j = 0; j < 4; j++) {
                int d = l + 32*j;
                F[r*132 + d] = (vals[j]-mu)*rs*__ldg(&flnw[d]) + __ldg(&flnb[d]);
            }
        }
        __syncthreads();
        // decode + denorm
        {
            int f = t >> 3, pl = (t & 7)*2;
            float rr0 = __ldg(&db[pl]), rr1 = __ldg(&db[pl+1]);
            const float* Fr = F + f*132;
            const float* d0 = dwT + pl*132;
            const float* d1 = dwT + (pl+1)*132;
            #pragma unroll 8
            for (int d = 0; d < 128; d++) {
                float ff = Fr[d];
                rr0 += ff * d0[d];
                rr1 += ff * d1[d];
            }
            int b = bvg >> 6, v = bvg & 63;
            float stdv = g_std[bvg], meanv = g_mean[bvg];
            out[(size_t)b*32768 + (size_t)(f*16 + pl)*64 + v]     = rr0*stdv + meanv;
            out[(size_t)b*32768 + (size_t)(f*16 + pl + 1)*64 + v] = rr1*stdv + meanv;
        }
        __syncthreads();
    }
}

// ===== launch =====
extern "C" void kernel_launch(void* const* d_in, const int* in_sizes, int n_in,
                              void* d_out, int out_size) {
    const float* x      = (const float*)d_in[0];
    const float* cent   = (const float*)d_in[1];
    const float* enc_w  = (const float*)d_in[2];
    const float* enc_b  = (const float*)d_in[3];
    const float* ln_w   = (const float*)d_in[4];
    const float* ln_b   = (const float*)d_in[5];
    const float* fc1_w  = (const float*)d_in[6];
    const float* fc1_b  = (const float*)d_in[7];
    const float* fcm_w  = (const float*)d_in[8];
    const float* fcm_b  = (const float*)d_in[9];
    const float* fc2_w  = (const float*)d_in[10];
    const float* fc2_b  = (const float*)d_in[11];
    const float* fuse_w = (const float*)d_in[12];
    const float* fuse_b = (const float*)d_in[13];
    const float* fln_w  = (const float*)d_in[14];
    const float* fln_b  = (const float*)d_in[15];
    const float* dec_w  = (const float*)d_in[16];
    const float* dec_b  = (const float*)d_in[17];

    float* out    = (float*)d_out;
    float* logits = out + (size_t)BB*512*VV;

    cudaFuncSetAttribute(k_mlp_mma, cudaFuncAttributeMaxDynamicSharedMemorySize, SMEM_MLP);
    cudaFuncSetAttribute(k_vq_mma,  cudaFuncAttributeMaxDynamicSharedMemorySize, SMEM_VQ);

    k_xT<<<dim3(16, 32), 256>>>(x);
    k_prep<<<832, 256>>>(cent, fc1_w, fcm_w, fc2_w, fuse_w);
    k_mlp_mma<<<BB*VV, 256, SMEM_MLP>>>(enc_w, enc_b, ln_w, ln_b, fc1_b, fcm_b, fc2_b);
    k_vq_mma<<<NVQ/128, 256, SMEM_VQ>>>(cent, logits, fuse_b, fln_w, fln_b, dec_w, dec_b, out);
}

// round 12
// speedup vs baseline: 9.5574x; 1.0204x over previous
#include <cuda_runtime.h>
#include <cuda_bf16.h>
#include <math.h>
#include <stdint.h>

#define BB   32
#define LL   1024
#define VV   64
#define PHn  64
#define PFn  32
#define DD   128
#define KK   1024
#define NVQ  (BB*VV*PFn)
#define NROW (BB*VV*DD)

__device__ float g_mean[BB*VV];
__device__ float g_std[BB*VV];
__device__ float g_xt[(size_t)BB*VV*LL];          // x transposed [b][v][l]
__device__ float g_z2[NVQ];                       // exact fp32 |z|^2 per row
__device__ float g_c2[KK];
__device__ __nv_bfloat16 g_Zpb[(size_t)NVQ*DD];   // bf16 z_p [n][d]
__device__ __nv_bfloat16 g_Cb[(size_t)KK*DD];     // bf16 centroids [k][d]
__device__ __nv_bfloat16 g_W1b[64*256];
__device__ __nv_bfloat16 g_W2b[256*512];
__device__ __nv_bfloat16 g_W3b[512*32];
__device__ __nv_bfloat16 g_Fwb[128*128];          // bf16 fuse_w [k][n]

extern __shared__ char dynsm[];

// ===== helpers =====
__device__ __forceinline__ uint32_t smem_u32(const void* p) {
    uint32_t a;
    asm("{ .reg .u64 t; cvta.to.shared.u64 t, %1; cvt.u32.u64 %0, t; }" : "=r"(a) : "l"(p));
    return a;
}
__device__ __forceinline__ void ldsm4(uint32_t* r, uint32_t a) {
    asm volatile("ldmatrix.sync.aligned.m8n8.x4.shared.b16 {%0,%1,%2,%3}, [%4];"
        : "=r"(r[0]), "=r"(r[1]), "=r"(r[2]), "=r"(r[3]) : "r"(a));
}
__device__ __forceinline__ void ldsm4t(uint32_t* r, uint32_t a) {
    asm volatile("ldmatrix.sync.aligned.m8n8.x4.trans.shared.b16 {%0,%1,%2,%3}, [%4];"
        : "=r"(r[0]), "=r"(r[1]), "=r"(r[2]), "=r"(r[3]) : "r"(a));
}
__device__ __forceinline__ void mma_bf16(float* c, const uint32_t* a, uint32_t b0, uint32_t b1) {
    asm volatile("mma.sync.aligned.m16n8k16.row.col.f32.bf16.bf16.f32 "
        "{%0,%1,%2,%3}, {%4,%5,%6,%7}, {%8,%9}, {%0,%1,%2,%3};"
        : "+f"(c[0]), "+f"(c[1]), "+f"(c[2]), "+f"(c[3])
        : "r"(a[0]), "r"(a[1]), "r"(a[2]), "r"(a[3]), "r"(b0), "r"(b1));
}
__device__ __forceinline__ uint32_t packrelu(float x, float y, float bx, float by) {
    __nv_bfloat162 h = __float22bfloat162_rn(make_float2(fmaxf(x+bx,0.f), fmaxf(y+by,0.f)));
    return *reinterpret_cast<uint32_t*>(&h);
}
__device__ __forceinline__ void top5_ins(float* tv, int* ti, float d, int k) {
    if (d < tv[4]) {
        tv[4] = d; ti[4] = k;
        #pragma unroll
        for (int s = 4; s > 0; s--) {
            if (tv[s] < tv[s-1]) {
                float tf = tv[s]; tv[s] = tv[s-1]; tv[s-1] = tf;
                int tk = ti[s]; ti[s] = ti[s-1]; ti[s-1] = tk;
            }
        }
    }
}
#define CP_ASYNC16(dst, src) \
    asm volatile("cp.async.cg.shared.global [%0], [%1], 16;" :: "r"(dst), "l"(src))
#define CP_COMMIT() asm volatile("cp.async.commit_group;" ::: "memory")
#define CP_WAIT1()  asm volatile("cp.async.wait_group 1;" ::: "memory")
#define CP_WAIT0()  asm volatile("cp.async.wait_group 0;" ::: "memory")

// ===== K0: transpose x -> [b][v][l] =====
__global__ void __launch_bounds__(256) k_xT(const float* __restrict__ x) {
    __shared__ float tile[64][65];
    int b = blockIdx.y, l0 = blockIdx.x*64;
    int t = threadIdx.x;
    for (int i = t; i < 4096; i += 256) {
        int li = i >> 6, v = i & 63;
        tile[li][v] = x[((size_t)b*1024 + l0 + li)*64 + v];
    }
    __syncthreads();
    for (int i = t; i < 4096; i += 256) {
        int v = i >> 6, li = i & 63;
        g_xt[((size_t)b*64 + v)*1024 + l0 + li] = tile[li][v];
    }
}

// ===== K1: prep — weight bf16 convert + centroid norms =====
__global__ void k_prep(const float* __restrict__ cent, const float* __restrict__ w1,
                       const float* __restrict__ w2, const float* __restrict__ w3,
                       const float* __restrict__ fw) {
    int blk = blockIdx.x;
    if (blk < 704) {
        int i = blk*256 + threadIdx.x;
        if (i < 16384)        g_W1b[i] = __float2bfloat16(w1[i]);
        else if (i < 147456)  g_W2b[i - 16384] = __float2bfloat16(w2[i - 16384]);
        else if (i < 163840)  g_W3b[i - 147456] = __float2bfloat16(w3[i - 147456]);
        else if (i < 180224)  g_Fwb[i - 163840] = __float2bfloat16(fw[i - 163840]);
    } else {
        int w = threadIdx.x >> 5, l = threadIdx.x & 31;
        int k = (blk - 704) * 8 + w;
        const float* cp = cent + (size_t)k*DD;
        float s = 0.f;
        #pragma unroll
        for (int q = 0; q < 4; q++) {
            float c = cp[l + 32*q];
            s += c*c;
            g_Cb[(size_t)k*DD + l + 32*q] = __float2bfloat16(c);
        }
        #pragma unroll
        for (int o = 16; o; o >>= 1) s += __shfl_xor_sync(0xffffffffu, s, o);
        if (l == 0) g_c2[k] = s;
    }
}

// ===== K3: fused encode + 3-layer HMMA MLP =====
#define MO_A   0
#define MO_W   18432
#define MO_H1  88064
#define MO_W3  155648
#define SC_XV  155648
#define SC_WS  159744
#define SMEM_MLP 196608
#define W_SUB  34816

__device__ __forceinline__ void gemm_tile64(uint32_t Abase, int sA, int m0,
                                            uint32_t Bbase, int sB, int n0,
                                            int ksteps, int l, float acc[8][4]) {
    for (int ks = 0; ks < ksteps; ks++) {
        int kk = ks*16;
        uint32_t av[4];
        ldsm4(av, Abase + (uint32_t)(((m0 + (l&15))*sA + kk + ((l>>4)<<3))*2));
        #pragma unroll
        for (int t = 0; t < 4; t++) {
            uint32_t bvv[4];
            ldsm4t(bvv, Bbase + (uint32_t)(((kk + (l&15))*sB + n0 + t*16 + ((l>>4)<<3))*2));
            mma_bf16(acc[2*t],   av, bvv[0], bvv[1]);
            mma_bf16(acc[2*t+1], av, bvv[2], bvv[3]);
        }
    }
}

__device__ __forceinline__ void epi64(float acc[8][4], char* hdst, int sH, int m0, int n0,
                                      const float* __restrict__ bias, int boff, int l) {
    int row = l >> 2, qc = (l & 3)*2;
    #pragma unroll
    for (int t8 = 0; t8 < 8; t8++) {
        int col = n0 + t8*8 + qc;
        float b0 = __ldg(&bias[boff + col]), b1 = __ldg(&bias[boff + col + 1]);
        *(uint32_t*)(hdst + ((m0+row)*sH + col)*2)   = packrelu(acc[t8][0], acc[t8][1], b0, b1);
        *(uint32_t*)(hdst + ((m0+row+8)*sH + col)*2) = packrelu(acc[t8][2], acc[t8][3], b0, b1);
    }
}

__device__ __forceinline__ void issue_w2_sub(uint32_t base, int s, int hb, int t) {
    int nc = s >> 1, ksub = s & 1;
    const uint4* W2g = reinterpret_cast<const uint4*>(g_W2b);
    #pragma unroll
    for (int rep = 0; rep < 8; rep++) {
        int i = t + rep*256;
        int row = i >> 4, q = i & 15;
        CP_ASYNC16(base + MO_W + hb*W_SUB + row*272 + q*16,
                   (const void*)(W2g + (ksub*128 + row)*64 + nc*16 + q));
    }
    CP_COMMIT();
}

__global__ void __launch_bounds__(256, 1) k_mlp_mma(
    const float* __restrict__ ew, const float* __restrict__ eb,
    const float* __restrict__ lnw, const float* __restrict__ lnb,
    const float* __restrict__ b1g, const float* __restrict__ b2g,
    const float* __restrict__ b3g) {
    char* smem = dynsm;
    uint32_t base = smem_u32(smem);
    __shared__ float red[16], stat[2];
    int t = threadIdx.x, w = t >> 5, l = t & 31;
    int bv = blockIdx.x;

    // group 0: x tile + enc_w + W1
    {
        const uint4* Xg = reinterpret_cast<const uint4*>(g_xt + (size_t)bv*1024);
        CP_ASYNC16(base + SC_XV + t*16, (const void*)(Xg + t));
        const uint4* Eg = reinterpret_cast<const uint4*>(ew);
        CP_ASYNC16(base + SC_WS + t*16, (const void*)(Eg + t));
        CP_ASYNC16(base + SC_WS + (t+256)*16, (const void*)(Eg + t + 256));
        const uint4* W1g = reinterpret_cast<const uint4*>(g_W1b);
        #pragma unroll
        for (int rep = 0; rep < 8; rep++) {
            int i = t + rep*256;
            int row = i >> 5, q = i & 31;
            CP_ASYNC16(base + MO_W + row*528 + q*16, (const void*)(W1g + i));
        }
        CP_COMMIT();
    }
    CP_WAIT0();
    __syncthreads();

    // ---- fused encode ----
    {
        float* xv = (float*)(smem + SC_XV);
        float* ws = (float*)(smem + SC_WS);
        float s = 0.f, q = 0.f;
        #pragma unroll
        for (int j = 0; j < 4; j++) { float val = xv[t + 256*j]; s += val; q += val*val; }
        #pragma unroll
        for (int o = 16; o; o >>= 1) {
            s += __shfl_xor_sync(0xffffffffu, s, o);
            q += __shfl_xor_sync(0xffffffffu, q, o);
        }
        if (l == 0) { red[w] = s; red[8 + w] = q; }
        __syncthreads();
        if (t == 0) {
            float ss = 0.f, qq = 0.f;
            #pragma unroll
            for (int j = 0; j < 8; j++) { ss += red[j]; qq += red[8 + j]; }
            float mean = ss * (1.0f/LL);
            float stdv = sqrtf(qq*(1.0f/LL) - mean*mean + 1e-5f);
            g_mean[bv] = mean; g_std[bv] = stdv;
            stat[0] = mean; stat[1] = 1.0f / stdv;
        }
        __syncthreads();
        float mean = stat[0], rstd = stat[1];
        for (int i = t; i < 1024; i += 256) xv[i] = (xv[i] - mean) * rstd;
        __syncthreads();
        float* zt = (float*)(smem + MO_H1);
        for (int idx = t; idx < 8192; idx += 256) {
            int p = idx >> 7, d = idx & 127;
            float sv = __ldg(&eb[d]);
            const float* xq = &xv[p*16];
            #pragma unroll
            for (int i = 0; i < 16; i++) sv += xq[i] * ws[i*128 + d];
            zt[idx] = sv;
        }
        __syncthreads();
        __nv_bfloat16* Aimg = (__nv_bfloat16*)(smem + MO_A);
        #pragma unroll
        for (int j = 0; j < 8; j++) {
            int p = w*8 + j;
            float z[4], sv = 0.f, qv = 0.f;
            #pragma unroll
            for (int qq2 = 0; qq2 < 4; qq2++) {
                z[qq2] = zt[p*128 + l + 32*qq2];
                sv += z[qq2]; qv += z[qq2]*z[qq2];
            }
            #pragma unroll
            for (int o = 16; o; o >>= 1) {
                sv += __shfl_xor_sync(0xffffffffu, sv, o);
                qv += __shfl_xor_sync(0xffffffffu, qv, o);
            }
            float mu = sv * (1.0f/128.0f);
            float rs = rsqrtf(qv*(1.0f/128.0f) - mu*mu + 1e-5f);
            #pragma unroll
            for (int qq2 = 0; qq2 < 4; qq2++) {
                int d = l + 32*qq2;
                Aimg[d*72 + p] = __float2bfloat16((z[qq2]-mu)*rs*__ldg(&lnw[d]) + __ldg(&lnb[d]));
            }
        }
    }
    __syncthreads();

    {
        const uint4* W3g = reinterpret_cast<const uint4*>(g_W3b);
        #pragma unroll
        for (int rep = 0; rep < 8; rep++) {
            int i = t + rep*256;
            int row = i >> 2, q = i & 3;
            CP_ASYNC16(base + MO_W3 + row*80 + q*16, (const void*)(W3g + i));
        }
        issue_w2_sub(base, 0, 1, t);
    }

    // stage 1
    {
        int m0s1 = w*16;
        for (int j = 0; j < 4; j++) {
            float acc[8][4];
            #pragma unroll
            for (int i = 0; i < 8; i++)
                #pragma unroll
                for (int jj = 0; jj < 4; jj++) acc[i][jj] = 0.f;
            gemm_tile64(base + MO_A, 72, m0s1, base + MO_W, 264, j*64, 4, l, acc);
            epi64(acc, smem + MO_H1, 264, m0s1, j*64, b1g, 0, l);
        }
    }
    __syncthreads();

    int wm = w & 3, wn = w >> 2;
    int m0 = wm*32;
    float acc2[2][8][4];
    float acc3[2][4][4];
    #pragma unroll
    for (int mt = 0; mt < 2; mt++)
        #pragma unroll
        for (int j = 0; j < 4; j++)
            #pragma unroll
            for (int c = 0; c < 4; c++) acc3[mt][j][c] = 0.f;

    for (int s = 0; s < 8; s++) {
        int nc = s >> 1, ksub = s & 1;
        if (s < 7) { issue_w2_sub(base, s+1, s&1, t); CP_WAIT1(); }
        else       { CP_WAIT0(); }
        __syncthreads();
        if (ksub == 0) {
            #pragma unroll
            for (int mt = 0; mt < 2; mt++)
                #pragma unroll
                for (int j = 0; j < 8; j++)
                    #pragma unroll
                    for (int c = 0; c < 4; c++) acc2[mt][j][c] = 0.f;
        }
        uint32_t bufb = base + MO_W + ((s+1)&1)*W_SUB;
        for (int ks = 0; ks < 8; ks++) {
            int kk = ks*16;
            uint32_t a0[4], a1[4];
            ldsm4(a0, base + MO_H1 + (uint32_t)(((m0 + (l&15))*264 + ksub*128 + kk + ((l>>4)<<3))*2));
            ldsm4(a1, base + MO_H1 + (uint32_t)(((m0 + 16 + (l&15))*264 + ksub*128 + kk + ((l>>4)<<3))*2));
            #pragma unroll
            for (int tt = 0; tt < 4; tt++) {
                uint32_t bvv[4];
                ldsm4t(bvv, bufb + (uint32_t)(((kk + (l&15))*136 + wn*64 + tt*16 + ((l>>4)<<3))*2));
                mma_bf16(acc2[0][2*tt],   a0, bvv[0], bvv[1]);
                mma_bf16(acc2[0][2*tt+1], a0, bvv[2], bvv[3]);
                mma_bf16(acc2[1][2*tt],   a1, bvv[0], bvv[1]);
                mma_bf16(acc2[1][2*tt+1], a1, bvv[2], bvv[3]);
            }
        }
        if (ksub == 1) {
            #pragma unroll
            for (int kg = 0; kg < 4; kg++) {
                int krow = nc*128 + wn*64 + kg*16 + (l & 15);
                uint32_t bA[4], bB[4];
                ldsm4t(bA, base + MO_W3 + (uint32_t)((krow*40 + 0  + ((l>>4)<<3))*2));
                ldsm4t(bB, base + MO_W3 + (uint32_t)((krow*40 + 16 + ((l>>4)<<3))*2));
                int colb = nc*128 + wn*64 + kg*16 + (l&3)*2;
                float bb0 = __ldg(&b2g[colb]),     bb1 = __ldg(&b2g[colb+1]);
                float bb8 = __ldg(&b2g[colb+8]),   bb9 = __ldg(&b2g[colb+9]);
                #pragma unroll
                for (int mt = 0; mt < 2; mt++) {
                    uint32_t af[4];
                    af[0] = packrelu(acc2[mt][kg*2][0],   acc2[mt][kg*2][1],   bb0, bb1);
                    af[1] = packrelu(acc2[mt][kg*2][2],   acc2[mt][kg*2][3],   bb0, bb1);
                    af[2] = packrelu(acc2[mt][kg*2+1][0], acc2[mt][kg*2+1][1], bb8, bb9);
                    af[3] = packrelu(acc2[mt][kg*2+1][2], acc2[mt][kg*2+1][3], bb8, bb9);
                    mma_bf16(acc3[mt][0], af, bA[0], bA[1]);
                    mma_bf16(acc3[mt][1], af, bA[2], bA[3]);
                    mma_bf16(acc3[mt][2], af, bB[0], bB[1]);
                    mma_bf16(acc3[mt][3], af, bB[2], bB[3]);
                }
            }
        }
        __syncthreads();
    }

    float* OUT = (float*)(smem + MO_A);
    {
        int r = m0 + (l >> 2);
        if (wn == 0) {
            #pragma unroll
            for (int mt = 0; mt < 2; mt++)
                #pragma unroll
                for (int j = 0; j < 4; j++) {
                    int col = j*8 + (l&3)*2;
                    float b0 = __ldg(&b3g[col]), b1 = __ldg(&b3g[col+1]);
                    int rr = r + mt*16;
                    OUT[col*132 + rr]         = acc3[mt][j][0] + b0;
                    OUT[(col+1)*132 + rr]     = acc3[mt][j][1] + b1;
                    OUT[col*132 + rr + 8]     = acc3[mt][j][2] + b0;
                    OUT[(col+1)*132 + rr + 8] = acc3[mt][j][3] + b1;
                }
        }
        __syncthreads();
        if (wn == 1) {
            #pragma unroll
            for (int mt = 0; mt < 2; mt++)
                #pragma unroll
                for (int j = 0; j < 4; j++) {
                    int col = j*8 + (l&3)*2;
                    int rr = r + mt*16;
                    OUT[col*132 + rr]         += acc3[mt][j][0];
                    OUT[(col+1)*132 + rr]     += acc3[mt][j][1];
                    OUT[col*132 + rr + 8]     += acc3[mt][j][2];
                    OUT[(col+1)*132 + rr + 8] += acc3[mt][j][3];
                }
        }
        __syncthreads();
    }
    #pragma unroll
    for (int rr = 0; rr < 4; rr++) {
        int f = w*4 + rr;
        const float* Fr = OUT + f*132;
        float s = 0.f;
        #pragma unroll
        for (int j = 0; j < 4; j++) { float vv = Fr[l + 32*j]; s += vv*vv; }
        #pragma unroll
        for (int o = 16; o; o >>= 1) s += __shfl_xor_sync(0xffffffffu, s, o);
        if (l == 0) g_z2[bv*32 + f] = s;
    }
    __nv_bfloat16* zpb = g_Zpb + (size_t)bv*4096;
    for (int i = t; i < 4096; i += 256) {
        int f = i >> 7, r = i & 127;
        zpb[i] = __float2bfloat16(OUT[f*132 + r]);
    }
}

// ===== K4: HMMA VQ (double-buffered chunks) + fused fuse/LN/decode =====
#define VQ_ZB   0           // z_p tile [128][136]b16
#define VQ_CB0  34816       // centroid chunk buf0; post: cands/WI/F/dwT
#define VQ_CB1  69632       // centroid chunk buf1; post: fuse_w image
#define VQ_Z2   104448
#define VQ_C2   104960
#define SMEM_VQ 109056
// post-loop offsets inside CB0:
#define PQ_CVAL (VQ_CB0)            // 10240
#define PQ_CIDX (VQ_CB0 + 10240)    // 10240
#define PQ_WI   (VQ_CB0 + 20480)    // 5120
#define PQ_F    (VQ_CB0)            // 16896 (overlays dead candidates)
#define PQ_DW   (VQ_CB0 + 25600)    // 8448

__global__ void __launch_bounds__(256) k_vq_mma(
    const float* __restrict__ cent, float* __restrict__ logits,
    const float* __restrict__ fb, const float* __restrict__ flnw,
    const float* __restrict__ flnb, const float* __restrict__ dwg,
    const float* __restrict__ db, float* __restrict__ out) {
    char* sm = dynsm;
    uint32_t base = smem_u32(sm);
    int t = threadIdx.x, w = t >> 5, l = t & 31;
    int n0 = blockIdx.x * 128;
    const uint4* Cg = reinterpret_cast<const uint4*>(g_Cb);

    // group: Z tile
    {
        const uint4* Zg = reinterpret_cast<const uint4*>(g_Zpb) + (size_t)n0*16;
        #pragma unroll
        for (int rep = 0; rep < 8; rep++) {
            int i = t + rep*256;
            int row = i >> 4, q = i & 15;
            CP_ASYNC16(base + VQ_ZB + row*272 + q*16, (const void*)(Zg + i));
        }
        CP_COMMIT();
    }
    // group: chunk 0 -> CB0
    {
        #pragma unroll
        for (int rep = 0; rep < 8; rep++) {
            int i = t + rep*256;
            int row = i >> 4, q = i & 15;
            CP_ASYNC16(base + VQ_CB0 + row*272 + q*16, (const void*)(Cg + i));
        }
        CP_COMMIT();
    }
    {
        float* c2s = (float*)(sm + VQ_C2);
        for (int i = t; i < 1024; i += 256) c2s[i] = g_c2[i];
        float* z2s = (float*)(sm + VQ_Z2);
        if (t < 128) z2s[t] = g_z2[n0 + t];
    }

    int m0 = w*16;
    int r0 = m0 + (l >> 2), r1 = r0 + 8;
    const float* c2s = (float*)(sm + VQ_C2);
    const float* z2s = (float*)(sm + VQ_Z2);

    float tv0[5], tv1[5]; int ti0[5], ti1[5];
    #pragma unroll
    for (int s = 0; s < 5; s++) { tv0[s] = 3.0e38f; tv1[s] = 3.0e38f; ti0[s] = 0; ti1[s] = 0; }

    for (int ch = 0; ch < 8; ch++) {
        if (ch < 7) {
            uint32_t dstb = base + ((ch+1)&1 ? VQ_CB1 : VQ_CB0);
            #pragma unroll
            for (int rep = 0; rep < 8; rep++) {
                int i = t + rep*256;
                int row = i >> 4, q = i & 15;
                CP_ASYNC16(dstb + row*272 + q*16, (const void*)(Cg + (ch+1)*2048 + i));
            }
            CP_COMMIT();
            CP_WAIT1();      // Z + chunk ch complete; ch+1 in flight
        } else {
            CP_WAIT0();
        }
        __syncthreads();
        uint32_t cb = base + (ch&1 ? VQ_CB1 : VQ_CB0);
        float z2a = z2s[r0], z2b = z2s[r1];
        for (int h = 0; h < 2; h++) {
            float acc[8][4];
            #pragma unroll
            for (int i = 0; i < 8; i++)
                #pragma unroll
                for (int j = 0; j < 4; j++) acc[i][j] = 0.f;
            for (int ks = 0; ks < 8; ks++) {
                int kk = ks*16;
                uint32_t av[4];
                ldsm4(av, base + VQ_ZB + (uint32_t)(((m0 + (l&15))*136 + kk + ((l>>4)<<3))*2));
                #pragma unroll
                for (int tt = 0; tt < 4; tt++) {
                    uint32_t bvv[4];
                    ldsm4(bvv, cb + (uint32_t)(((h*64 + tt*16 + (l&15))*136 + kk + ((l>>4)<<3))*2));
                    mma_bf16(acc[2*tt],   av, bvv[0], bvv[2]);
                    mma_bf16(acc[2*tt+1], av, bvv[1], bvv[3]);
                }
            }
            int cbase = ch*128 + h*64;
            #pragma unroll
            for (int a = 0; a < 8; a++) {
                int col = cbase + (a>>1)*16 + ((a&1)<<3) + ((l&3)<<1);
                float c20 = c2s[col], c21 = c2s[col+1];
                float d00 = z2a + c20 - 2.0f*acc[a][0];
                float d01 = z2a + c21 - 2.0f*acc[a][1];
                float d10 = z2b + c20 - 2.0f*acc[a][2];
                float d11 = z2b + c21 - 2.0f*acc[a][3];
                __stcs((float2*)(logits + (size_t)(n0+r0)*1024 + col), make_float2(-d00, -d01));
                __stcs((float2*)(logits + (size_t)(n0+r1)*1024 + col), make_float2(-d10, -d11));
                top5_ins(tv0, ti0, d00, col); top5_ins(tv0, ti0, d01, col+1);
                top5_ins(tv1, ti1, d10, col); top5_ins(tv1, ti1, d11, col+1);
            }
        }
        __syncthreads();
    }

    // candidate dump into CB0 region (chunk data dead)
    {
        float* cval = (float*)(sm + PQ_CVAL);
        int*   cidx = (int*)(sm + PQ_CIDX);
        int own = l & 3;
        #pragma unroll
        for (int s = 0; s < 5; s++) {
            cval[r0*20 + own*5 + s] = tv0[s]; cidx[r0*20 + own*5 + s] = ti0[s];
            cval[r1*20 + own*5 + s] = tv1[s]; cidx[r1*20 + own*5 + s] = ti1[s];
        }
    }
    __syncthreads();
    // fuse_w -> CB1, dwT -> CB0 tail (parallel with merge below)
    {
        const uint4* Fg = reinterpret_cast<const uint4*>(g_Fwb);
        for (int i = t; i < 2048; i += 256) {
            int row = i >> 4, q = i & 15;
            *(uint4*)(sm + VQ_CB1 + row*272 + q*16) = Fg[i];
        }
        float* dwT = (float*)(sm + PQ_DW);
        for (int i = t; i < 2048; i += 256) {
            int d = i >> 4, pl = i & 15;
            dwT[pl*132 + d] = dwg[i];
        }
    }
    if (t < 128) {
        float* cval = (float*)(sm + PQ_CVAL);
        int*   cidx = (int*)(sm + PQ_CIDX);
        float mv[5]; int mi[5];
        #pragma unroll
        for (int s = 0; s < 5; s++) { mv[s] = 3.0e38f; mi[s] = 0; }
        for (int c = 0; c < 20; c++) top5_ins(mv, mi, cval[t*20 + c], cidx[t*20 + c]);
        float m0v = mv[0];
        float wv[5]; float wsum = 0.f;
        #pragma unroll
        for (int j = 0; j < 5; j++) { wv[j] = expf(m0v - mv[j]); wsum += wv[j]; }
        float inv = 1.0f / wsum;
        float* wsm = (float*)(sm + PQ_WI);
        int*   ism = (int*)(sm + PQ_WI + 2560);
        #pragma unroll
        for (int j = 0; j < 5; j++) { wsm[t*5 + j] = wv[j]*inv; ism[t*5 + j] = mi[j]; }
    }
    __syncthreads();

    // fused ResidualFusion + LN + decode + denorm per bv (4 per CTA)
    float* F = (float*)(sm + PQ_F);
    float* wsm = (float*)(sm + PQ_WI);
    int*   ism = (int*)(sm + PQ_WI + 2560);
    const float* dwT = (float*)(sm + PQ_DW);
    for (int i4 = 0; i4 < 4; i4++) {
        int bvg = blockIdx.x*4 + i4;
        for (int r = w; r < 32; r += 8) {
            int gr = i4*32 + r;
            float wg[5]; int id[5];
            #pragma unroll
            for (int j = 0; j < 5; j++) { wg[j] = wsm[gr*5 + j]; id[j] = ism[gr*5 + j]; }
            int dbase = l*4;
            float4 o = make_float4(0.f,0.f,0.f,0.f);
            #pragma unroll
            for (int j = 0; j < 5; j++) {
                float4 cv = *(const float4*)&cent[(size_t)id[j]*128 + dbase];
                o.x += wg[j]*cv.x; o.y += wg[j]*cv.y;
                o.z += wg[j]*cv.z; o.w += wg[j]*cv.w;
            }
            *(float4*)&F[r*132 + dbase] = o;
        }
        __syncthreads();
        {
            int m0f = (w & 1) * 16, nb = (w >> 1) * 32;
            float facc[4][4];
            #pragma unroll
            for (int i = 0; i < 4; i++)
                #pragma unroll
                for (int j = 0; j < 4; j++) facc[i][j] = 0.f;
            for (int ks = 0; ks < 8; ks++) {
                int kk = ks*16;
                uint32_t av[4];
                ldsm4(av, base + VQ_ZB + (uint32_t)(((i4*32 + m0f + (l&15))*136 + kk + ((l>>4)<<3))*2));
                #pragma unroll
                for (int tt = 0; tt < 2; tt++) {
                    uint32_t bvv[4];
                    ldsm4t(bvv, base + VQ_CB1 + (uint32_t)(((kk + (l&15))*136 + nb + tt*16 + ((l>>4)<<3))*2));
                    mma_bf16(facc[2*tt],   av, bvv[0], bvv[1]);
                    mma_bf16(facc[2*tt+1], av, bvv[2], bvv[3]);
                }
            }
            int fr0 = m0f + (l >> 2), fr1 = fr0 + 8;
            #pragma unroll
            for (int t8 = 0; t8 < 4; t8++) {
                int col = nb + t8*8 + (l&3)*2;
                float b0 = __ldg(&fb[col]), b1 = __ldg(&fb[col+1]);
                F[fr0*132 + col]     = fmaxf(facc[t8][0] + b0, 0.f) + F[fr0*132 + col];
                F[fr0*132 + col + 1] = fmaxf(facc[t8][1] + b1, 0.f) + F[fr0*132 + col + 1];
                F[fr1*132 + col]     = fmaxf(facc[t8][2] + b0, 0.f) + F[fr1*132 + col];
                F[fr1*132 + col + 1] = fmaxf(facc[t8][3] + b1, 0.f) + F[fr1*132 + col + 1];
            }
        }
        __syncthreads();
        #pragma unroll
        for (int rr = 0; rr < 4; rr++) {
            int r = w*4 + rr;
            float vals[4], s = 0.f, q = 0.f;
            #pragma unroll
            for (int j = 0; j < 4; j++) {
                vals[j] = F[r*132 + l + 32*j];
                s += vals[j]; q += vals[j]*vals[j];
            }
            #pragma unroll
            for (int o = 16; o; o >>= 1) {
                s += __shfl_xor_sync(0xffffffffu, s, o);
                q += __shfl_xor_sync(0xffffffffu, q, o);
            }
            float mu = s * (1.0f/128.0f);
            float rs = rsqrtf(q*(1.0f/128.0f) - mu*mu + 1e-5f);
            #pragma unroll
            for (int j = 0; j < 4; j++) {
                int d = l + 32*j;
                F[r*132 + d] = (vals[j]-mu)*rs*__ldg(&flnw[d]) + __ldg(&flnb[d]);
            }
        }
        __syncthreads();
        {
            int f = t >> 3, pl = (t & 7)*2;
            float rr0 = __ldg(&db[pl]), rr1 = __ldg(&db[pl+1]);
            const float* Fr = F + f*132;
            const float* d0 = dwT + pl*132;
            const float* d1 = dwT + (pl+1)*132;
            #pragma unroll 8
            for (int d = 0; d < 128; d++) {
                float ff = Fr[d];
                rr0 += ff * d0[d];
                rr1 += ff * d1[d];
            }
            int b = bvg >> 6, v = bvg & 63;
            float stdv = g_std[bvg], meanv = g_mean[bvg];
            out[(size_t)b*32768 + (size_t)(f*16 + pl)*64 + v]     = rr0*stdv + meanv;
            out[(size_t)b*32768 + (size_t)(f*16 + pl + 1)*64 + v] = rr1*stdv + meanv;
        }
        __syncthreads();
    }
}

// ===== launch =====
extern "C" void kernel_launch(void* const* d_in, const int* in_sizes, int n_in,
                              void* d_out, int out_size) {
    const float* x      = (const float*)d_in[0];
    const float* cent   = (const float*)d_in[1];
    const float* enc_w  = (const float*)d_in[2];
    const float* enc_b  = (const float*)d_in[3];
    const float* ln_w   = (const float*)d_in[4];
    const float* ln_b   = (const float*)d_in[5];
    const float* fc1_w  = (const float*)d_in[6];
    const float* fc1_b  = (const float*)d_in[7];
    const float* fcm_w  = (const float*)d_in[8];
    const float* fcm_b  = (const float*)d_in[9];
    const float* fc2_w  = (const float*)d_in[10];
    const float* fc2_b  = (const float*)d_in[11];
    const float* fuse_w = (const float*)d_in[12];
    const float* fuse_b = (const float*)d_in[13];
    const float* fln_w  = (const float*)d_in[14];
    const float* fln_b  = (const float*)d_in[15];
    const float* dec_w  = (const float*)d_in[16];
    const float* dec_b  = (const float*)d_in[17];

    float* out    = (float*)d_out;
    float* logits = out + (size_t)BB*512*VV;

    cudaFuncSetAttribute(k_mlp_mma, cudaFuncAttributeMaxDynamicSharedMemorySize, SMEM_MLP);
    cudaFuncSetAttribute(k_vq_mma,  cudaFuncAttributeMaxDynamicSharedMemorySize, SMEM_VQ);

    k_xT<<<dim3(16, 32), 256>>>(x);
    k_prep<<<832, 256>>>(cent, fc1_w, fcm_w, fc2_w, fuse_w);
    k_mlp_mma<<<BB*VV, 256, SMEM_MLP>>>(enc_w, enc_b, ln_w, ln_b, fc1_b, fcm_b, fc2_b);
    k_vq_mma<<<NVQ/128, 256, SMEM_VQ>>>(cent, logits, fuse_b, fln_w, fln_b, dec_w, dec_b, out);
}